// round 2
// baseline (speedup 1.0000x reference)
#include <cuda_runtime.h>
#include <float.h>

#define Bv 4
#define Hv 8
#define BH 32
#define Nv 4096
#define Dv 64
#define Mv 64
#define NSPLIT 16
#define CHUNK 256
#define P65 65
#define KVP 65

#define NEG_INF __int_as_float(0xff800000)

// ---------------- scratch (device globals; no allocation allowed) ----------------
__device__ float g_kernel1[(size_t)BH * Nv * Mv];          // 33.5 MB
__device__ int   g_cidx[BH * Mv];
__device__ int   g_ridx[BH * Mv];
__device__ float g_u[BH * Mv * Mv];
__device__ float g_Yp[(size_t)BH * NSPLIT * Mv * Dv];      // 8.4 MB
__device__ float g_mx[BH * NSPLIT * Mv];
__device__ float g_sm[BH * NSPLIT * Mv];
__device__ float g_Y[BH * Mv * Dv];
__device__ float g_Z[BH * Mv * Dv];
__device__ unsigned int g_gmax;

// ---------------- init ----------------
__global__ void init_kernel() { g_gmax = 0u; }

// ---------------- top-k selection (sum over D, exclude token 0 & masked) --------
__global__ __launch_bounds__(256) void select_kernel(const float* __restrict__ Kp,
                                                     const float* __restrict__ Qp,
                                                     const int* __restrict__ mask) {
    int bh = blockIdx.x;
    int b = bh / Hv;
    const float* T = (blockIdx.y == 0) ? Kp : Qp;
    int* outIdx = (blockIdx.y == 0) ? g_cidx : g_ridx;

    __shared__ float s[Nv];            // 16 KB
    __shared__ float rv[256];
    __shared__ int   ri[256];
    __shared__ int   picked[Mv];

    int warp = threadIdx.x >> 5, lane = threadIdx.x & 31;
    const float* Tb = T + (size_t)bh * Nv * Dv;

    // row sums: one warp per row
    for (int n = warp; n < Nv; n += 8) {
        float v = Tb[(size_t)n * Dv + lane] + Tb[(size_t)n * Dv + lane + 32];
        #pragma unroll
        for (int o = 16; o; o >>= 1) v += __shfl_xor_sync(0xffffffffu, v, o);
        if (lane == 0) {
            bool bad = (n == 0) || (mask[b * Nv + n] != 0);
            s[n] = bad ? -FLT_MAX : v;
        }
    }
    __syncthreads();

    // 63 iterations of block argmax (tie -> lowest index, matching top_k)
    for (int it = 0; it < Mv - 1; ++it) {
        float bv = NEG_INF; int bi = Nv;
        for (int n = threadIdx.x; n < Nv; n += 256) {
            float v = s[n];
            if (v > bv) { bv = v; bi = n; }
        }
        rv[threadIdx.x] = bv; ri[threadIdx.x] = bi;
        __syncthreads();
        for (int st = 128; st; st >>= 1) {
            if (threadIdx.x < st) {
                float ov = rv[threadIdx.x + st]; int oi = ri[threadIdx.x + st];
                if (ov > rv[threadIdx.x] ||
                    (ov == rv[threadIdx.x] && oi < ri[threadIdx.x])) {
                    rv[threadIdx.x] = ov; ri[threadIdx.x] = oi;
                }
            }
            __syncthreads();
        }
        if (threadIdx.x == 0) { picked[it] = ri[0]; s[ri[0]] = NEG_INF; }
        __syncthreads();
    }
    if (threadIdx.x == 0) {
        picked[Mv - 1] = 0;
        for (int i = 1; i < Mv; i++) {          // insertion sort ascending
            int key = picked[i]; int j = i - 1;
            while (j >= 0 && picked[j] > key) { picked[j + 1] = picked[j]; j--; }
            picked[j + 1] = key;
        }
        for (int i = 0; i < Mv; i++) outIdx[bh * Mv + i] = picked[i];
    }
}

// ---------------- kernel_1 = softmax(Qs @ nc^T) over M, store to global --------
__global__ __launch_bounds__(256) void k1_kernel(const float* __restrict__ Q,
                                                 const float* __restrict__ K) {
    int bh = blockIdx.y; int n0 = blockIdx.x * 64;
    __shared__ float ncs[64 * P65];   // nc[m][d], K-major -> odd pitch for NT b-operand
    __shared__ float qs[64 * P65];    // q[n][d]; reused for scores S after matmul

    const float* Kb = K + (size_t)bh * Nv * Dv;
    const float* Qb = Q + (size_t)bh * Nv * Dv;
    const int* ci = g_cidx + bh * Mv;

    for (int i = threadIdx.x; i < 64 * 64; i += 256) {
        int r = i >> 6, c = i & 63;
        ncs[r * P65 + c] = Kb[(size_t)ci[r] * Dv + c];
        qs[r * P65 + c]  = Qb[(size_t)(n0 + r) * Dv + c] * 0.125f;
    }
    __syncthreads();

    int tx = threadIdx.x & 15, ty = threadIdx.x >> 4;
    float acc[4][4];
    #pragma unroll
    for (int i = 0; i < 4; i++)
        #pragma unroll
        for (int j = 0; j < 4; j++) acc[i][j] = 0.f;

    for (int k = 0; k < 64; k++) {
        float a[4], bb[4];
        #pragma unroll
        for (int i = 0; i < 4; i++) a[i] = qs[(ty * 4 + i) * P65 + k];
        #pragma unroll
        for (int j = 0; j < 4; j++) bb[j] = ncs[(tx * 4 + j) * P65 + k];
        #pragma unroll
        for (int i = 0; i < 4; i++)
            #pragma unroll
            for (int j = 0; j < 4; j++) acc[i][j] += a[i] * bb[j];
    }
    __syncthreads();
    #pragma unroll
    for (int i = 0; i < 4; i++)
        #pragma unroll
        for (int j = 0; j < 4; j++)
            qs[(ty * 4 + i) * P65 + tx * 4 + j] = acc[i][j];
    __syncthreads();

    // softmax rows (8 warps x 8 rows, 2 elems/lane)
    int warp = threadIdx.x >> 5, lane = threadIdx.x & 31;
    float* out = g_kernel1 + ((size_t)bh * Nv + n0) * Mv;
    for (int r = warp; r < 64; r += 8) {
        float v0 = qs[r * P65 + lane], v1 = qs[r * P65 + lane + 32];
        float mx = fmaxf(v0, v1);
        #pragma unroll
        for (int o = 16; o; o >>= 1) mx = fmaxf(mx, __shfl_xor_sync(0xffffffffu, mx, o));
        float e0 = __expf(v0 - mx), e1 = __expf(v1 - mx);
        float sm = e0 + e1;
        #pragma unroll
        for (int o = 16; o; o >>= 1) sm += __shfl_xor_sync(0xffffffffu, sm, o);
        float inv = 1.f / sm;
        out[(size_t)r * Mv + lane]      = e0 * inv;
        out[(size_t)r * Mv + lane + 32] = e1 * inv;
    }
}

// ---------------- gather u rows + global colsum-max ----------------
__global__ __launch_bounds__(256) void ugather_kernel() {
    int bh = blockIdx.x;
    __shared__ float us[64 * P65];
    __shared__ float colsum[64];
    const int* ri = g_ridx + bh * Mv;
    for (int i = threadIdx.x; i < 4096; i += 256) {
        int r = i >> 6, c = i & 63;
        float v = g_kernel1[((size_t)bh * Nv + ri[r]) * Mv + c];
        us[r * P65 + c] = v;
        g_u[(bh * 64 + r) * 64 + c] = v;
    }
    __syncthreads();
    if (threadIdx.x < 64) {
        int j = threadIdx.x;
        float s = 0.f;
        for (int i = 0; i < 64; i++) s += us[i * P65 + j];
        colsum[j] = s;
    }
    __syncthreads();
    if (threadIdx.x == 0) {
        float mx = colsum[0];
        for (int j = 1; j < 64; j++) mx = fmaxf(mx, colsum[j]);
        atomicMax(&g_gmax, __float_as_uint(mx));   // colsums > 0: bit-monotonic
    }
}

// ---------------- flash pass: Y_partial = softmax_n(nr@K^T, mask) @ V ----------
__global__ __launch_bounds__(256) void flash_kernel(const float* __restrict__ Q,
                                                    const float* __restrict__ K,
                                                    const float* __restrict__ V,
                                                    const int* __restrict__ mask) {
    __shared__ float nr[64 * 64];       // nr[m][d]
    __shared__ float Ssh[64 * 33];      // scores/P [m][n], n-tile 32, odd pitch
    __shared__ float KV[32 * KVP];      // K/V tile [n][d], pitch 65 (FIX: was 33)
    __shared__ float rowmax[64], rowsum[64], alpha_s[64];
    __shared__ int   msk[32];

    int bh = blockIdx.y, sp = blockIdx.x;
    int b = bh / Hv;
    const float* Qb = Q + (size_t)bh * Nv * Dv;
    const float* Kb = K + (size_t)bh * Nv * Dv;
    const float* Vb = V + (size_t)bh * Nv * Dv;
    const int* ri = g_ridx + bh * Mv;

    int tid = threadIdx.x, tx = tid & 15, ty = tid >> 4;
    int wp = tid >> 5, lane = tid & 31;

    for (int i = tid; i < 4096; i += 256) {
        int r = i >> 6, c = i & 63;
        nr[r * 64 + c] = Qb[(size_t)ri[r] * Dv + c] * 0.125f;
    }
    if (tid < 64) { rowmax[tid] = NEG_INF; rowsum[tid] = 0.f; }

    float acc[4][4];
    #pragma unroll
    for (int i = 0; i < 4; i++)
        #pragma unroll
        for (int j = 0; j < 4; j++) acc[i][j] = 0.f;

    int base0 = sp * CHUNK;
    for (int t = 0; t < CHUNK / 32; t++) {
        int base = base0 + t * 32;
        __syncthreads();                 // protect KV/Ssh reuse (and nr on t=0)
        for (int i = tid; i < 32 * 64; i += 256) {
            int r = i >> 6, c = i & 63;
            KV[r * KVP + c] = Kb[(size_t)(base + r) * Dv + c];
        }
        if (tid < 32) msk[tid] = mask[b * Nv + base + tid];
        __syncthreads();

        // scores: 64m x 32n, thread tile 4m x 2n
        float sc[4][2];
        #pragma unroll
        for (int i = 0; i < 4; i++) { sc[i][0] = 0.f; sc[i][1] = 0.f; }
        for (int k = 0; k < 64; k++) {
            float a[4], bb[2];
            #pragma unroll
            for (int i = 0; i < 4; i++) a[i] = nr[(ty * 4 + i) * 64 + k];
            #pragma unroll
            for (int j = 0; j < 2; j++) bb[j] = KV[(tx * 2 + j) * KVP + k];
            #pragma unroll
            for (int i = 0; i < 4; i++) {
                sc[i][0] += a[i] * bb[0];
                sc[i][1] += a[i] * bb[1];
            }
        }
        #pragma unroll
        for (int j = 0; j < 2; j++) {
            int n = tx * 2 + j;
            bool ok = (msk[n] != 0);     // reference keeps where mask==1
            #pragma unroll
            for (int i = 0; i < 4; i++)
                Ssh[(ty * 4 + i) * 33 + n] = ok ? sc[i][j] : NEG_INF;
        }
        __syncthreads();

        // online softmax update: warp per row, lane per column (32 cols)
        for (int r = wp; r < 64; r += 8) {
            float v = Ssh[r * 33 + lane];
            float tmx = v;
            #pragma unroll
            for (int o = 16; o; o >>= 1) tmx = fmaxf(tmx, __shfl_xor_sync(0xffffffffu, tmx, o));
            float om = rowmax[r];
            float nm = fmaxf(om, tmx);
            float mc = fmaxf(nm, -1e30f);        // guard all-masked tiles
            float p = __expf(v - mc);
            float ts = p;
            #pragma unroll
            for (int o = 16; o; o >>= 1) ts += __shfl_xor_sync(0xffffffffu, ts, o);
            if (lane == 0) {
                float al = __expf(om - mc);      // om=-inf -> 0
                alpha_s[r] = al;
                rowsum[r] = rowsum[r] * al + ts;
                rowmax[r] = nm;
            }
            Ssh[r * 33 + lane] = p;
        }
        __syncthreads();

        // load V tile over KV
        for (int i = tid; i < 32 * 64; i += 256) {
            int r = i >> 6, c = i & 63;
            KV[r * KVP + c] = Vb[(size_t)(base + r) * Dv + c];
        }
        __syncthreads();

        // rescale + accumulate P @ V  (thread tile 4m x 4d)
        #pragma unroll
        for (int i = 0; i < 4; i++) {
            float al = alpha_s[ty * 4 + i];
            #pragma unroll
            for (int j = 0; j < 4; j++) acc[i][j] *= al;
        }
        for (int k = 0; k < 32; k++) {
            float p[4], vv[4];
            #pragma unroll
            for (int i = 0; i < 4; i++) p[i] = Ssh[(ty * 4 + i) * 33 + k];
            #pragma unroll
            for (int j = 0; j < 4; j++) vv[j] = KV[k * KVP + tx * 4 + j];
            #pragma unroll
            for (int i = 0; i < 4; i++)
                #pragma unroll
                for (int j = 0; j < 4; j++) acc[i][j] += p[i] * vv[j];
        }
    }

    int idxbase = (bh * NSPLIT + sp) * 64;
    if (tid < 64) { g_mx[idxbase + tid] = rowmax[tid]; g_sm[idxbase + tid] = rowsum[tid]; }
    #pragma unroll
    for (int i = 0; i < 4; i++)
        #pragma unroll
        for (int j = 0; j < 4; j++)
            g_Yp[((size_t)idxbase + ty * 4 + i) * 64 + tx * 4 + j] = acc[i][j];
}

// ---------------- combine split partials into Y ----------------
__global__ __launch_bounds__(256) void combine_kernel() {
    int bh = blockIdx.x, tid = threadIdx.x;
    __shared__ float smx[64], ssum[64];
    if (tid < 64) {
        float mx = NEG_INF;
        for (int s = 0; s < NSPLIT; s++)
            mx = fmaxf(mx, g_mx[(bh * NSPLIT + s) * 64 + tid]);
        float mc = fmaxf(mx, -1e30f);
        float tot = 0.f;
        for (int s = 0; s < NSPLIT; s++)
            tot += __expf(g_mx[(bh * NSPLIT + s) * 64 + tid] - mc) *
                   g_sm[(bh * NSPLIT + s) * 64 + tid];
        smx[tid] = mc; ssum[tid] = tot;
    }
    __syncthreads();
    int m = tid >> 2, db = (tid & 3) * 16;
    float inv = 1.f / ssum[m];
    float acc[16];
    #pragma unroll
    for (int d = 0; d < 16; d++) acc[d] = 0.f;
    for (int s = 0; s < NSPLIT; s++) {
        float w = __expf(g_mx[(bh * NSPLIT + s) * 64 + m] - smx[m]);
        const float* yp = g_Yp + (((size_t)(bh * NSPLIT + s) * 64) + m) * 64 + db;
        #pragma unroll
        for (int d = 0; d < 16; d++) acc[d] += w * yp[d];
    }
    float* y = g_Y + ((size_t)bh * 64 + m) * 64 + db;
    #pragma unroll
    for (int d = 0; d < 16; d++) y[d] = acc[d] * inv;
}

// shared NN 64x64 matmul helper, pitch 64 (b-operand row-contiguous)
__device__ __forceinline__ void mm64s(const float* __restrict__ A,
                                      const float* __restrict__ Bm,
                                      float acc[4][4], int tx, int ty) {
    #pragma unroll
    for (int i = 0; i < 4; i++)
        #pragma unroll
        for (int j = 0; j < 4; j++) acc[i][j] = 0.f;
    for (int k = 0; k < 64; k++) {
        float a[4], b[4];
        #pragma unroll
        for (int i = 0; i < 4; i++) a[i] = A[(ty * 4 + i) * 64 + k];
        #pragma unroll
        for (int j = 0; j < 4; j++) b[j] = Bm[k * 64 + tx * 4 + j];
        #pragma unroll
        for (int i = 0; i < 4; i++)
            #pragma unroll
            for (int j = 0; j < 4; j++) acc[i][j] += a[i] * b[j];
    }
}

// ---------------- Newton-Schulz inverse + Z = V^-1 @ Y ----------------
__global__ __launch_bounds__(256) void inv_kernel() {
    __shared__ float Vv[4096];   // 16 KB each, 48 KB total (static limit exactly)
    __shared__ float A[4096];
    __shared__ float T[4096];

    int bh = blockIdx.x, tid = threadIdx.x;
    int tx = tid & 15, ty = tid >> 4;
    const float* Ug = g_u + (size_t)bh * 4096;
    float ginv = 1.f / __uint_as_float(g_gmax);

    // V0 = U^T / gmax
    for (int i = tid; i < 4096; i += 256) {
        int r = i >> 6, c = i & 63;
        Vv[r * 64 + c] = Ug[c * 64 + r] * ginv;
    }
    __syncthreads();

    float acc[4][4], t1[4][4];
    for (int it = 0; it < 6; ++it) {
        // A = U @ V   (U streamed from global through L1)
        #pragma unroll
        for (int i = 0; i < 4; i++)
            #pragma unroll
            for (int j = 0; j < 4; j++) acc[i][j] = 0.f;
        for (int k = 0; k < 64; k++) {
            float a[4], b[4];
            #pragma unroll
            for (int i = 0; i < 4; i++) a[i] = Ug[(ty * 4 + i) * 64 + k];
            #pragma unroll
            for (int j = 0; j < 4; j++) b[j] = Vv[k * 64 + tx * 4 + j];
            #pragma unroll
            for (int i = 0; i < 4; i++)
                #pragma unroll
                for (int j = 0; j < 4; j++) acc[i][j] += a[i] * b[j];
        }
        __syncthreads();
        #pragma unroll
        for (int i = 0; i < 4; i++)
            #pragma unroll
            for (int j = 0; j < 4; j++) A[(ty * 4 + i) * 64 + tx * 4 + j] = acc[i][j];
        __syncthreads();

        // T = 7A - A@A
        mm64s(A, A, acc, tx, ty);
        #pragma unroll
        for (int i = 0; i < 4; i++)
            #pragma unroll
            for (int j = 0; j < 4; j++)
                t1[i][j] = 7.f * A[(ty * 4 + i) * 64 + tx * 4 + j] - acc[i][j];
        #pragma unroll
        for (int i = 0; i < 4; i++)
            #pragma unroll
            for (int j = 0; j < 4; j++) T[(ty * 4 + i) * 64 + tx * 4 + j] = t1[i][j];
        __syncthreads();

        // T = 15A - A@T
        mm64s(A, T, acc, tx, ty);
        #pragma unroll
        for (int i = 0; i < 4; i++)
            #pragma unroll
            for (int j = 0; j < 4; j++)
                t1[i][j] = 15.f * A[(ty * 4 + i) * 64 + tx * 4 + j] - acc[i][j];
        __syncthreads();
        #pragma unroll
        for (int i = 0; i < 4; i++)
            #pragma unroll
            for (int j = 0; j < 4; j++) T[(ty * 4 + i) * 64 + tx * 4 + j] = t1[i][j];
        __syncthreads();

        // V = 0.25 * (13V - V@T)
        mm64s(Vv, T, acc, tx, ty);
        #pragma unroll
        for (int i = 0; i < 4; i++)
            #pragma unroll
            for (int j = 0; j < 4; j++)
                t1[i][j] = 0.25f * (13.f * Vv[(ty * 4 + i) * 64 + tx * 4 + j] - acc[i][j]);
        __syncthreads();
        #pragma unroll
        for (int i = 0; i < 4; i++)
            #pragma unroll
            for (int j = 0; j < 4; j++) Vv[(ty * 4 + i) * 64 + tx * 4 + j] = t1[i][j];
        __syncthreads();
    }

    // Z = Vinv @ Y
    for (int i = tid; i < 4096; i += 256) {
        int r = i >> 6, c = i & 63;
        T[r * 64 + c] = g_Y[(size_t)(bh * 64 + r) * 64 + c];
    }
    __syncthreads();
    mm64s(Vv, T, acc, tx, ty);
    #pragma unroll
    for (int i = 0; i < 4; i++)
        #pragma unroll
        for (int j = 0; j < 4; j++)
            g_Z[((size_t)bh * 64 + ty * 4 + i) * 64 + tx * 4 + j] = acc[i][j];
}

// ---------------- X = kernel_1 @ Z ----------------
__global__ __launch_bounds__(256) void x_kernel(float* __restrict__ out) {
    int bh = blockIdx.y, n0 = blockIdx.x * 64;
    __shared__ float Zs[4096];
    __shared__ float Ps[4096];
    int tid = threadIdx.x, tx = tid & 15, ty = tid >> 4;
    for (int i = tid; i < 4096; i += 256) {
        int r = i >> 6, c = i & 63;
        Zs[r * 64 + c] = g_Z[((size_t)bh * 64 + r) * 64 + c];
        Ps[r * 64 + c] = g_kernel1[((size_t)bh * Nv + n0 + r) * Mv + c];
    }
    __syncthreads();
    float acc[4][4];
    mm64s(Ps, Zs, acc, tx, ty);
    #pragma unroll
    for (int i = 0; i < 4; i++)
        #pragma unroll
        for (int j = 0; j < 4; j++)
            out[((size_t)bh * Nv + n0 + ty * 4 + i) * Dv + tx * 4 + j] = acc[i][j];
}

// ---------------- launch ----------------
extern "C" void kernel_launch(void* const* d_in, const int* in_sizes, int n_in,
                              void* d_out, int out_size) {
    (void)in_sizes; (void)n_in; (void)out_size;
    const float* Q    = (const float*)d_in[0];
    const float* K    = (const float*)d_in[1];
    const float* V    = (const float*)d_in[2];
    const int*   mask = (const int*)d_in[3];
    float* out = (float*)d_out;

    init_kernel<<<1, 1>>>();
    select_kernel<<<dim3(BH, 2), 256>>>(K, Q, mask);
    k1_kernel<<<dim3(Nv / 64, BH), 256>>>(Q, K);
    ugather_kernel<<<BH, 256>>>();
    flash_kernel<<<dim3(NSPLIT, BH), 256>>>(Q, K, V, mask);
    combine_kernel<<<BH, 256>>>();
    inv_kernel<<<BH, 256>>>();
    x_kernel<<<dim3(Nv / 64, BH), 256>>>(out);
}

// round 3
// speedup vs baseline: 1.2385x; 1.2385x over previous
#include <cuda_runtime.h>
#include <float.h>

#define Bv 4
#define Hv 8
#define BH 32
#define Nv 4096
#define Dv 64
#define Mv 64
#define NSPLIT 16
#define CHUNK 256
#define PW 68              // padded pitch (words) for [token][d] tiles, 16B-aligned, conflict-free
#define PP 36              // pitch for P tile [m][32]

#define NEG_INF __int_as_float(0xff800000)

// ---------------- scratch (device globals; no allocation allowed) ----------------
__device__ float g_kernel1[(size_t)BH * Nv * Mv];          // 33.5 MB
__device__ int   g_cidx[BH * Mv];
__device__ int   g_ridx[BH * Mv];
__device__ float g_u[BH * Mv * Mv];
__device__ float g_Yp[(size_t)BH * NSPLIT * Mv * Dv];      // 8.4 MB
__device__ float g_mx[BH * NSPLIT * Mv];
__device__ float g_sm[BH * NSPLIT * Mv];
__device__ float g_Y[BH * Mv * Dv];
__device__ float g_Z[BH * Mv * Dv];
__device__ unsigned int g_gmax;

__global__ void init_kernel() { g_gmax = 0u; }

// ---------------- top-k selection: incremental chunk-argmax ----------------
__global__ __launch_bounds__(256) void select_kernel(const float* __restrict__ Kp,
                                                     const float* __restrict__ Qp,
                                                     const int* __restrict__ mask) {
    int bh = blockIdx.x;
    int b = bh / Hv;
    const float* T = (blockIdx.y == 0) ? Kp : Qp;
    int* outIdx = (blockIdx.y == 0) ? g_cidx : g_ridx;

    __shared__ float s[Nv];            // 16 KB
    __shared__ float cmax[16];
    __shared__ int   cidx[16];
    __shared__ int   picked[Mv];

    int tid = threadIdx.x;
    int warp = tid >> 5, lane = tid & 31;
    const float* Tb = T + (size_t)bh * Nv * Dv;

    // row sums: one warp per row
    for (int n = warp; n < Nv; n += 8) {
        float v = Tb[(size_t)n * Dv + lane] + Tb[(size_t)n * Dv + lane + 32];
        #pragma unroll
        for (int o = 16; o; o >>= 1) v += __shfl_xor_sync(0xffffffffu, v, o);
        if (lane == 0) {
            bool bad = (n == 0) || (mask[b * Nv + n] != 0);
            s[n] = bad ? -FLT_MAX : v;
        }
    }
    __syncthreads();

    // initial 16 chunk argmaxes (chunk = 256): warp w handles chunks 2w, 2w+1
    for (int c = warp; c < 16; c += 8) {
        float bv = -FLT_MAX; int bi = Nv;
        #pragma unroll
        for (int t = 0; t < 8; t++) {
            int idx = c * 256 + lane + 32 * t;
            float v = s[idx];
            if (v > bv || (v == bv && idx < bi)) { bv = v; bi = idx; }
        }
        #pragma unroll
        for (int o = 16; o; o >>= 1) {
            float ov = __shfl_xor_sync(0xffffffffu, bv, o);
            int   oi = __shfl_xor_sync(0xffffffffu, bi, o);
            if (ov > bv || (ov == bv && oi < bi)) { bv = ov; bi = oi; }
        }
        if (lane == 0) { cmax[c] = bv; cidx[c] = bi; }
    }
    __syncthreads();

    // warp 0: 63 incremental argmax iterations (no block syncs)
    if (warp == 0) {
        for (int it = 0; it < Mv - 1; ++it) {
            float bv = (lane < 16) ? cmax[lane] : -FLT_MAX;
            int   bi = (lane < 16) ? cidx[lane] : Nv;
            #pragma unroll
            for (int o = 16; o; o >>= 1) {
                float ov = __shfl_xor_sync(0xffffffffu, bv, o);
                int   oi = __shfl_xor_sync(0xffffffffu, bi, o);
                if (ov > bv || (ov == bv && oi < bi)) { bv = ov; bi = oi; }
            }
            int gidx = __shfl_sync(0xffffffffu, bi, 0);
            if (lane == 0) { picked[it] = gidx; s[gidx] = -FLT_MAX; }
            __syncwarp();
            // recompute the dirty chunk
            int c = gidx >> 8;
            float nv = -FLT_MAX; int ni = Nv;
            #pragma unroll
            for (int t = 0; t < 8; t++) {
                int idx = c * 256 + lane + 32 * t;
                float v = s[idx];
                if (v > nv || (v == nv && idx < ni)) { nv = v; ni = idx; }
            }
            #pragma unroll
            for (int o = 16; o; o >>= 1) {
                float ov = __shfl_xor_sync(0xffffffffu, nv, o);
                int   oi = __shfl_xor_sync(0xffffffffu, ni, o);
                if (ov > nv || (ov == nv && oi < ni)) { nv = ov; ni = oi; }
            }
            if (lane == 0) { cmax[c] = nv; cidx[c] = ni; }
            __syncwarp();
        }
        if (lane == 0) picked[Mv - 1] = 0;
    }
    __syncthreads();

    // parallel rank-sort (indices distinct)
    if (tid < Mv) {
        int key = picked[tid];
        int rank = 0;
        #pragma unroll 16
        for (int j = 0; j < Mv; j++) rank += (picked[j] < key);
        outIdx[bh * Mv + rank] = key;
    }
}

// ---------------- kernel_1 = softmax(Qs @ nc^T) over M ----------------
__global__ __launch_bounds__(256) void k1_kernel(const float* __restrict__ Q,
                                                 const float* __restrict__ K) {
    int bh = blockIdx.y; int n0 = blockIdx.x * 64;
    __shared__ float ncs[64 * PW];   // nc[m'][d]
    __shared__ float qs[64 * PW];    // q[n][d]; reused for scores after matmul
    __shared__ int   ci_s[64];

    const float* Kb = K + (size_t)bh * Nv * Dv;
    const float* Qb = Q + (size_t)bh * Nv * Dv;
    int tid = threadIdx.x;
    if (tid < 64) ci_s[tid] = g_cidx[bh * Mv + tid];
    __syncthreads();

    // coalesced float4 loads into pitch-PW tiles
    for (int idx = tid; idx < 64 * 16; idx += 256) {
        int r = idx >> 4, c4 = (idx & 15) * 4;
        float4 q4 = *(const float4*)(Qb + (size_t)(n0 + r) * Dv + c4);
        q4.x *= 0.125f; q4.y *= 0.125f; q4.z *= 0.125f; q4.w *= 0.125f;
        *(float4*)&qs[r * PW + c4] = q4;
        *(float4*)&ncs[r * PW + c4] = *(const float4*)(Kb + (size_t)ci_s[r] * Dv + c4);
    }
    __syncthreads();

    int tx = tid & 15, ty = tid >> 4;
    float acc[4][4];
    #pragma unroll
    for (int i = 0; i < 4; i++)
        #pragma unroll
        for (int j = 0; j < 4; j++) acc[i][j] = 0.f;

    #pragma unroll 4
    for (int k4 = 0; k4 < 16; k4++) {
        float4 a[4], bb[4];
        #pragma unroll
        for (int i = 0; i < 4; i++) a[i] = *(const float4*)&qs[(ty * 4 + i) * PW + k4 * 4];
        #pragma unroll
        for (int j = 0; j < 4; j++) bb[j] = *(const float4*)&ncs[(tx + 16 * j) * PW + k4 * 4];
        #pragma unroll
        for (int i = 0; i < 4; i++)
            #pragma unroll
            for (int j = 0; j < 4; j++) {
                acc[i][j] = fmaf(a[i].x, bb[j].x, acc[i][j]);
                acc[i][j] = fmaf(a[i].y, bb[j].y, acc[i][j]);
                acc[i][j] = fmaf(a[i].z, bb[j].z, acc[i][j]);
                acc[i][j] = fmaf(a[i].w, bb[j].w, acc[i][j]);
            }
    }
    __syncthreads();
    #pragma unroll
    for (int i = 0; i < 4; i++)
        #pragma unroll
        for (int j = 0; j < 4; j++)
            qs[(ty * 4 + i) * PW + tx + 16 * j] = acc[i][j];   // column m' = tx+16j
    __syncthreads();

    // softmax rows
    int warp = tid >> 5, lane = tid & 31;
    float* out = g_kernel1 + ((size_t)bh * Nv + n0) * Mv;
    for (int r = warp; r < 64; r += 8) {
        float v0 = qs[r * PW + lane], v1 = qs[r * PW + lane + 32];
        float mx = fmaxf(v0, v1);
        #pragma unroll
        for (int o = 16; o; o >>= 1) mx = fmaxf(mx, __shfl_xor_sync(0xffffffffu, mx, o));
        float e0 = __expf(v0 - mx), e1 = __expf(v1 - mx);
        float sm = e0 + e1;
        #pragma unroll
        for (int o = 16; o; o >>= 1) sm += __shfl_xor_sync(0xffffffffu, sm, o);
        float inv = 1.f / sm;
        out[(size_t)r * Mv + lane]      = e0 * inv;
        out[(size_t)r * Mv + lane + 32] = e1 * inv;
    }
}

// ---------------- gather u rows + global colsum-max ----------------
__global__ __launch_bounds__(256) void ugather_kernel() {
    int bh = blockIdx.x;
    __shared__ float us[64 * 65];
    __shared__ float colsum[64];
    __shared__ int ri_s[64];
    if (threadIdx.x < 64) ri_s[threadIdx.x] = g_ridx[bh * Mv + threadIdx.x];
    __syncthreads();
    for (int i = threadIdx.x; i < 4096; i += 256) {
        int r = i >> 6, c = i & 63;
        float v = g_kernel1[((size_t)bh * Nv + ri_s[r]) * Mv + c];
        us[r * 65 + c] = v;
        g_u[(bh * 64 + r) * 64 + c] = v;
    }
    __syncthreads();
    if (threadIdx.x < 64) {
        int j = threadIdx.x;
        float s = 0.f;
        #pragma unroll 8
        for (int i = 0; i < 64; i++) s += us[i * 65 + j];
        colsum[j] = s;
    }
    __syncthreads();
    if (threadIdx.x == 0) {
        float mx = colsum[0];
        for (int j = 1; j < 64; j++) mx = fmaxf(mx, colsum[j]);
        atomicMax(&g_gmax, __float_as_uint(mx));   // colsums > 0: bit-monotonic
    }
}

// ---------------- flash pass: Y_partial = softmax_n(nr@K^T, mask) @ V ----------
__global__ __launch_bounds__(256) void flash_kernel(const float* __restrict__ Q,
                                                    const float* __restrict__ K,
                                                    const float* __restrict__ V,
                                                    const int* __restrict__ mask) {
    __shared__ float nr[64 * PW];       // 17.4 KB  [m][d]
    __shared__ float KV[32 * PW];       // 8.7 KB   K tile, then V tile [n][d]
    __shared__ float P[64 * PP];        // 9.2 KB   [m][n(32)]
    __shared__ float rowmax[64], rowsum[64], alpha_s[64];
    __shared__ int   msk[32];
    __shared__ int   ri_s[64];

    int bh = blockIdx.y, sp = blockIdx.x;
    int b = bh / Hv;
    const float* Qb = Q + (size_t)bh * Nv * Dv;
    const float* Kb = K + (size_t)bh * Nv * Dv;
    const float* Vb = V + (size_t)bh * Nv * Dv;

    int tid = threadIdx.x, tx = tid & 15, ty = tid >> 4;
    int wp = tid >> 5, lane = tid & 31;

    if (tid < 64) ri_s[tid] = g_ridx[bh * Mv + tid];
    if (tid < 64) { rowmax[tid] = NEG_INF; rowsum[tid] = 0.f; }
    __syncthreads();
    for (int idx = tid; idx < 64 * 16; idx += 256) {
        int r = idx >> 4, c4 = (idx & 15) * 4;
        float4 q4 = *(const float4*)(Qb + (size_t)ri_s[r] * Dv + c4);
        q4.x *= 0.125f; q4.y *= 0.125f; q4.z *= 0.125f; q4.w *= 0.125f;
        *(float4*)&nr[r * PW + c4] = q4;
    }

    float acc[4][4];
    #pragma unroll
    for (int i = 0; i < 4; i++)
        #pragma unroll
        for (int j = 0; j < 4; j++) acc[i][j] = 0.f;

    int base0 = sp * CHUNK;
    for (int t = 0; t < CHUNK / 32; t++) {
        int base = base0 + t * 32;
        __syncthreads();                 // protect KV/P reuse (and nr on t=0)
        for (int idx = tid; idx < 32 * 16; idx += 256) {
            int r = idx >> 4, c4 = (idx & 15) * 4;
            *(float4*)&KV[r * PW + c4] = *(const float4*)(Kb + (size_t)(base + r) * Dv + c4);
        }
        if (tid < 32) msk[tid] = mask[b * Nv + base + tid];
        __syncthreads();

        // scores: 64m x 32n, thread tile 4m x 2n (n = tx+16j)
        float sc[4][2];
        #pragma unroll
        for (int i = 0; i < 4; i++) { sc[i][0] = 0.f; sc[i][1] = 0.f; }
        #pragma unroll 4
        for (int k4 = 0; k4 < 16; k4++) {
            float4 a[4], bb[2];
            #pragma unroll
            for (int i = 0; i < 4; i++) a[i] = *(const float4*)&nr[(ty * 4 + i) * PW + k4 * 4];
            #pragma unroll
            for (int j = 0; j < 2; j++) bb[j] = *(const float4*)&KV[(tx + 16 * j) * PW + k4 * 4];
            #pragma unroll
            for (int i = 0; i < 4; i++)
                #pragma unroll
                for (int j = 0; j < 2; j++) {
                    sc[i][j] = fmaf(a[i].x, bb[j].x, sc[i][j]);
                    sc[i][j] = fmaf(a[i].y, bb[j].y, sc[i][j]);
                    sc[i][j] = fmaf(a[i].z, bb[j].z, sc[i][j]);
                    sc[i][j] = fmaf(a[i].w, bb[j].w, sc[i][j]);
                }
        }
        #pragma unroll
        for (int j = 0; j < 2; j++) {
            int n = tx + 16 * j;
            bool ok = (msk[n] != 0);     // reference keeps where mask==1
            #pragma unroll
            for (int i = 0; i < 4; i++)
                P[(ty * 4 + i) * PP + n] = ok ? sc[i][j] : NEG_INF;
        }
        __syncthreads();

        // softmax update (warps) + V-tile load (all threads) — independent
        for (int idx = tid; idx < 32 * 16; idx += 256) {
            int r = idx >> 4, c4 = (idx & 15) * 4;
            *(float4*)&KV[r * PW + c4] = *(const float4*)(Vb + (size_t)(base + r) * Dv + c4);
        }
        for (int r = wp; r < 64; r += 8) {
            float v = P[r * PP + lane];
            float tmx = v;
            #pragma unroll
            for (int o = 16; o; o >>= 1) tmx = fmaxf(tmx, __shfl_xor_sync(0xffffffffu, tmx, o));
            float om = rowmax[r];
            float nm = fmaxf(om, tmx);
            float mc = fmaxf(nm, -1e30f);        // guard all-masked tiles
            float p = __expf(v - mc);
            float ts = p;
            #pragma unroll
            for (int o = 16; o; o >>= 1) ts += __shfl_xor_sync(0xffffffffu, ts, o);
            if (lane == 0) {
                float al = __expf(om - mc);      // om=-inf -> 0
                alpha_s[r] = al;
                rowsum[r] = rowsum[r] * al + ts;
                rowmax[r] = nm;
            }
            P[r * PP + lane] = p;
        }
        __syncthreads();

        // rescale + accumulate P @ V  (thread tile 4m x 4d, d = tx*4+j)
        #pragma unroll
        for (int i = 0; i < 4; i++) {
            float al = alpha_s[ty * 4 + i];
            #pragma unroll
            for (int j = 0; j < 4; j++) acc[i][j] *= al;
        }
        #pragma unroll 2
        for (int k4 = 0; k4 < 8; k4++) {
            float4 a[4];
            #pragma unroll
            for (int i = 0; i < 4; i++) a[i] = *(const float4*)&P[(ty * 4 + i) * PP + k4 * 4];
            #pragma unroll
            for (int kk = 0; kk < 4; kk++) {
                float4 bv = *(const float4*)&KV[(k4 * 4 + kk) * PW + tx * 4];
                float av[4];
                av[0] = (kk == 0) ? a[0].x : (kk == 1) ? a[0].y : (kk == 2) ? a[0].z : a[0].w;
                av[1] = (kk == 0) ? a[1].x : (kk == 1) ? a[1].y : (kk == 2) ? a[1].z : a[1].w;
                av[2] = (kk == 0) ? a[2].x : (kk == 1) ? a[2].y : (kk == 2) ? a[2].z : a[2].w;
                av[3] = (kk == 0) ? a[3].x : (kk == 1) ? a[3].y : (kk == 2) ? a[3].z : a[3].w;
                #pragma unroll
                for (int i = 0; i < 4; i++) {
                    acc[i][0] = fmaf(av[i], bv.x, acc[i][0]);
                    acc[i][1] = fmaf(av[i], bv.y, acc[i][1]);
                    acc[i][2] = fmaf(av[i], bv.z, acc[i][2]);
                    acc[i][3] = fmaf(av[i], bv.w, acc[i][3]);
                }
            }
        }
    }

    int idxbase = (bh * NSPLIT + sp) * 64;
    if (tid < 64) { g_mx[idxbase + tid] = rowmax[tid]; g_sm[idxbase + tid] = rowsum[tid]; }
    #pragma unroll
    for (int i = 0; i < 4; i++) {
        float4 w = make_float4(acc[i][0], acc[i][1], acc[i][2], acc[i][3]);
        *(float4*)&g_Yp[((size_t)idxbase + ty * 4 + i) * 64 + tx * 4] = w;
    }
}

// ---------------- combine split partials into Y ----------------
__global__ __launch_bounds__(256) void combine_kernel() {
    int bh = blockIdx.x, tid = threadIdx.x;
    __shared__ float smx[64], ssum[64];
    if (tid < 64) {
        float mx = NEG_INF;
        for (int s = 0; s < NSPLIT; s++)
            mx = fmaxf(mx, g_mx[(bh * NSPLIT + s) * 64 + tid]);
        float mc = fmaxf(mx, -1e30f);
        float tot = 0.f;
        for (int s = 0; s < NSPLIT; s++)
            tot += __expf(g_mx[(bh * NSPLIT + s) * 64 + tid] - mc) *
                   g_sm[(bh * NSPLIT + s) * 64 + tid];
        smx[tid] = mc; ssum[tid] = tot;
    }
    __syncthreads();
    int m = tid >> 2, db = (tid & 3) * 16;
    float inv = 1.f / ssum[m];
    float acc[16];
    #pragma unroll
    for (int d = 0; d < 16; d++) acc[d] = 0.f;
    for (int s = 0; s < NSPLIT; s++) {
        float w = __expf(g_mx[(bh * NSPLIT + s) * 64 + m] - smx[m]);
        const float* yp = g_Yp + (((size_t)(bh * NSPLIT + s) * 64) + m) * 64 + db;
        #pragma unroll
        for (int d = 0; d < 16; d++) acc[d] += w * yp[d];
    }
    float* y = g_Y + ((size_t)bh * 64 + m) * 64 + db;
    #pragma unroll
    for (int d = 0; d < 16; d++) y[d] = acc[d] * inv;
}

// shared NN 64x64 matmul helper, pitch 64 (b-operand row-contiguous)
__device__ __forceinline__ void mm64s(const float* __restrict__ A,
                                      const float* __restrict__ Bm,
                                      float acc[4][4], int tx, int ty) {
    #pragma unroll
    for (int i = 0; i < 4; i++)
        #pragma unroll
        for (int j = 0; j < 4; j++) acc[i][j] = 0.f;
    for (int k = 0; k < 64; k++) {
        float a[4], b[4];
        #pragma unroll
        for (int i = 0; i < 4; i++) a[i] = A[(ty * 4 + i) * 64 + k];
        #pragma unroll
        for (int j = 0; j < 4; j++) b[j] = Bm[k * 64 + tx * 4 + j];
        #pragma unroll
        for (int i = 0; i < 4; i++)
            #pragma unroll
            for (int j = 0; j < 4; j++) acc[i][j] += a[i] * b[j];
    }
}

// ---------------- Newton-Schulz inverse + Z = V^-1 @ Y ----------------
__global__ __launch_bounds__(256) void inv_kernel() {
    __shared__ float Vv[4096];
    __shared__ float A[4096];
    __shared__ float T[4096];

    int bh = blockIdx.x, tid = threadIdx.x;
    int tx = tid & 15, ty = tid >> 4;
    const float* Ug = g_u + (size_t)bh * 4096;
    float ginv = 1.f / __uint_as_float(g_gmax);

    for (int i = tid; i < 4096; i += 256) {
        int r = i >> 6, c = i & 63;
        Vv[r * 64 + c] = Ug[c * 64 + r] * ginv;
    }
    __syncthreads();

    float acc[4][4], t1[4][4];
    for (int it = 0; it < 6; ++it) {
        #pragma unroll
        for (int i = 0; i < 4; i++)
            #pragma unroll
            for (int j = 0; j < 4; j++) acc[i][j] = 0.f;
        for (int k = 0; k < 64; k++) {
            float a[4], b[4];
            #pragma unroll
            for (int i = 0; i < 4; i++) a[i] = Ug[(ty * 4 + i) * 64 + k];
            #pragma unroll
            for (int j = 0; j < 4; j++) b[j] = Vv[k * 64 + tx * 4 + j];
            #pragma unroll
            for (int i = 0; i < 4; i++)
                #pragma unroll
                for (int j = 0; j < 4; j++) acc[i][j] += a[i] * b[j];
        }
        __syncthreads();
        #pragma unroll
        for (int i = 0; i < 4; i++)
            #pragma unroll
            for (int j = 0; j < 4; j++) A[(ty * 4 + i) * 64 + tx * 4 + j] = acc[i][j];
        __syncthreads();

        mm64s(A, A, acc, tx, ty);
        #pragma unroll
        for (int i = 0; i < 4; i++)
            #pragma unroll
            for (int j = 0; j < 4; j++)
                t1[i][j] = 7.f * A[(ty * 4 + i) * 64 + tx * 4 + j] - acc[i][j];
        #pragma unroll
        for (int i = 0; i < 4; i++)
            #pragma unroll
            for (int j = 0; j < 4; j++) T[(ty * 4 + i) * 64 + tx * 4 + j] = t1[i][j];
        __syncthreads();

        mm64s(A, T, acc, tx, ty);
        #pragma unroll
        for (int i = 0; i < 4; i++)
            #pragma unroll
            for (int j = 0; j < 4; j++)
                t1[i][j] = 15.f * A[(ty * 4 + i) * 64 + tx * 4 + j] - acc[i][j];
        __syncthreads();
        #pragma unroll
        for (int i = 0; i < 4; i++)
            #pragma unroll
            for (int j = 0; j < 4; j++) T[(ty * 4 + i) * 64 + tx * 4 + j] = t1[i][j];
        __syncthreads();

        mm64s(Vv, T, acc, tx, ty);
        #pragma unroll
        for (int i = 0; i < 4; i++)
            #pragma unroll
            for (int j = 0; j < 4; j++)
                t1[i][j] = 0.25f * (13.f * Vv[(ty * 4 + i) * 64 + tx * 4 + j] - acc[i][j]);
        __syncthreads();
        #pragma unroll
        for (int i = 0; i < 4; i++)
            #pragma unroll
            for (int j = 0; j < 4; j++) Vv[(ty * 4 + i) * 64 + tx * 4 + j] = t1[i][j];
        __syncthreads();
    }

    for (int i = tid; i < 4096; i += 256) {
        int r = i >> 6, c = i & 63;
        T[r * 64 + c] = g_Y[(size_t)(bh * 64 + r) * 64 + c];
    }
    __syncthreads();
    mm64s(Vv, T, acc, tx, ty);
    #pragma unroll
    for (int i = 0; i < 4; i++)
        #pragma unroll
        for (int j = 0; j < 4; j++)
            g_Z[((size_t)bh * 64 + ty * 4 + i) * 64 + tx * 4 + j] = acc[i][j];
}

// ---------------- X = kernel_1 @ Z ----------------
__global__ __launch_bounds__(256) void x_kernel(float* __restrict__ out) {
    int bh = blockIdx.y, n0 = blockIdx.x * 64;
    __shared__ float Ps[64 * PW];
    __shared__ float Zs[64 * PW];
    int tid = threadIdx.x, tx = tid & 15, ty = tid >> 4;
    for (int idx = tid; idx < 64 * 16; idx += 256) {
        int r = idx >> 4, c4 = (idx & 15) * 4;
        *(float4*)&Ps[r * PW + c4] =
            *(const float4*)(g_kernel1 + ((size_t)bh * Nv + n0 + r) * Mv + c4);
        *(float4*)&Zs[r * PW + c4] =
            *(const float4*)(g_Z + ((size_t)bh * 64 + r) * 64 + c4);
    }
    __syncthreads();

    float acc[4][4];
    #pragma unroll
    for (int i = 0; i < 4; i++)
        #pragma unroll
        for (int j = 0; j < 4; j++) acc[i][j] = 0.f;

    #pragma unroll 2
    for (int k4 = 0; k4 < 16; k4++) {
        float4 a[4];
        #pragma unroll
        for (int i = 0; i < 4; i++) a[i] = *(const float4*)&Ps[(ty * 4 + i) * PW + k4 * 4];
        #pragma unroll
        for (int kk = 0; kk < 4; kk++) {
            float4 bv = *(const float4*)&Zs[(k4 * 4 + kk) * PW + tx * 4];
            float av[4];
            av[0] = (kk == 0) ? a[0].x : (kk == 1) ? a[0].y : (kk == 2) ? a[0].z : a[0].w;
            av[1] = (kk == 0) ? a[1].x : (kk == 1) ? a[1].y : (kk == 2) ? a[1].z : a[1].w;
            av[2] = (kk == 0) ? a[2].x : (kk == 1) ? a[2].y : (kk == 2) ? a[2].z : a[2].w;
            av[3] = (kk == 0) ? a[3].x : (kk == 1) ? a[3].y : (kk == 2) ? a[3].z : a[3].w;
            #pragma unroll
            for (int i = 0; i < 4; i++) {
                acc[i][0] = fmaf(av[i], bv.x, acc[i][0]);
                acc[i][1] = fmaf(av[i], bv.y, acc[i][1]);
                acc[i][2] = fmaf(av[i], bv.z, acc[i][2]);
                acc[i][3] = fmaf(av[i], bv.w, acc[i][3]);
            }
        }
    }
    #pragma unroll
    for (int i = 0; i < 4; i++) {
        float4 w = make_float4(acc[i][0], acc[i][1], acc[i][2], acc[i][3]);
        *(float4*)(out + ((size_t)bh * Nv + n0 + ty * 4 + i) * Dv + tx * 4) = w;
    }
}

// ---------------- launch ----------------
extern "C" void kernel_launch(void* const* d_in, const int* in_sizes, int n_in,
                              void* d_out, int out_size) {
    (void)in_sizes; (void)n_in; (void)out_size;
    const float* Q    = (const float*)d_in[0];
    const float* K    = (const float*)d_in[1];
    const float* V    = (const float*)d_in[2];
    const int*   mask = (const int*)d_in[3];
    float* out = (float*)d_out;

    init_kernel<<<1, 1>>>();
    select_kernel<<<dim3(BH, 2), 256>>>(K, Q, mask);
    k1_kernel<<<dim3(Nv / 64, BH), 256>>>(Q, K);
    ugather_kernel<<<BH, 256>>>();
    flash_kernel<<<dim3(NSPLIT, BH), 256>>>(Q, K, V, mask);
    combine_kernel<<<BH, 256>>>();
    inv_kernel<<<BH, 256>>>();
    x_kernel<<<dim3(Nv / 64, BH), 256>>>(out);
}

// round 4
// speedup vs baseline: 1.3045x; 1.0533x over previous
#include <cuda_runtime.h>
#include <float.h>

#define Bv 4
#define Hv 8
#define BH 32
#define Nv 4096
#define Dv 64
#define Mv 64
#define NSPLIT 16
#define CHUNK 256
#define PW 68              // padded pitch (words) for k-contig (TN) smem tiles

#define NEG_INF __int_as_float(0xff800000)

// ---------------- scratch (device globals; no allocation allowed) ----------------
__device__ int   g_cidx[BH * Mv];
__device__ int   g_ridx[BH * Mv];
__device__ float g_u[BH * Mv * Mv];
__device__ float g_Vinv[BH * Mv * Mv];
__device__ float g_Yp[(size_t)BH * NSPLIT * Mv * Dv];
__device__ float g_mx[BH * NSPLIT * Mv];
__device__ float g_sm[BH * NSPLIT * Mv];
__device__ float g_Y[BH * Mv * Dv];
__device__ float g_Z[BH * Mv * Dv];
__device__ unsigned int g_gmax;

__global__ void init_kernel() { g_gmax = 0u; }

// ---------------- top-k selection: incremental chunk-argmax ----------------
__global__ __launch_bounds__(256) void select_kernel(const float* __restrict__ Kp,
                                                     const float* __restrict__ Qp,
                                                     const int* __restrict__ mask) {
    int bh = blockIdx.x;
    int b = bh / Hv;
    const float* T = (blockIdx.y == 0) ? Kp : Qp;
    int* outIdx = (blockIdx.y == 0) ? g_cidx : g_ridx;

    __shared__ float s[Nv];
    __shared__ float cmax[16];
    __shared__ int   cidx[16];
    __shared__ int   picked[Mv];

    int tid = threadIdx.x;
    int warp = tid >> 5, lane = tid & 31;
    const float* Tb = T + (size_t)bh * Nv * Dv;

    for (int n = warp; n < Nv; n += 8) {
        float v = Tb[(size_t)n * Dv + lane] + Tb[(size_t)n * Dv + lane + 32];
        #pragma unroll
        for (int o = 16; o; o >>= 1) v += __shfl_xor_sync(0xffffffffu, v, o);
        if (lane == 0) {
            bool bad = (n == 0) || (mask[b * Nv + n] != 0);
            s[n] = bad ? -FLT_MAX : v;
        }
    }
    __syncthreads();

    for (int c = warp; c < 16; c += 8) {
        float bv = -FLT_MAX; int bi = Nv;
        #pragma unroll
        for (int t = 0; t < 8; t++) {
            int idx = c * 256 + lane + 32 * t;
            float v = s[idx];
            if (v > bv || (v == bv && idx < bi)) { bv = v; bi = idx; }
        }
        #pragma unroll
        for (int o = 16; o; o >>= 1) {
            float ov = __shfl_xor_sync(0xffffffffu, bv, o);
            int   oi = __shfl_xor_sync(0xffffffffu, bi, o);
            if (ov > bv || (ov == bv && oi < bi)) { bv = ov; bi = oi; }
        }
        if (lane == 0) { cmax[c] = bv; cidx[c] = bi; }
    }
    __syncthreads();

    if (warp == 0) {
        for (int it = 0; it < Mv - 1; ++it) {
            float bv = (lane < 16) ? cmax[lane] : -FLT_MAX;
            int   bi = (lane < 16) ? cidx[lane] : Nv;
            #pragma unroll
            for (int o = 16; o; o >>= 1) {
                float ov = __shfl_xor_sync(0xffffffffu, bv, o);
                int   oi = __shfl_xor_sync(0xffffffffu, bi, o);
                if (ov > bv || (ov == bv && oi < bi)) { bv = ov; bi = oi; }
            }
            int gidx = __shfl_sync(0xffffffffu, bi, 0);
            if (lane == 0) { picked[it] = gidx; s[gidx] = -FLT_MAX; }
            __syncwarp();
            int c = gidx >> 8;
            float nv = -FLT_MAX; int ni = Nv;
            #pragma unroll
            for (int t = 0; t < 8; t++) {
                int idx = c * 256 + lane + 32 * t;
                float v = s[idx];
                if (v > nv || (v == nv && idx < ni)) { nv = v; ni = idx; }
            }
            #pragma unroll
            for (int o = 16; o; o >>= 1) {
                float ov = __shfl_xor_sync(0xffffffffu, nv, o);
                int   oi = __shfl_xor_sync(0xffffffffu, ni, o);
                if (ov > nv || (ov == nv && oi < ni)) { nv = ov; ni = oi; }
            }
            if (lane == 0) { cmax[c] = nv; cidx[c] = ni; }
            __syncwarp();
        }
        if (lane == 0) picked[Mv - 1] = 0;
    }
    __syncthreads();

    if (tid < Mv) {
        int key = picked[tid];
        int rank = 0;
        #pragma unroll 16
        for (int j = 0; j < Mv; j++) rank += (picked[j] < key);
        outIdx[bh * Mv + rank] = key;
    }
}

// ---------------- u = softmax(Qs[ridx] @ nc^T) rows + global colsum-max ----------
__global__ __launch_bounds__(256) void u_kernel(const float* __restrict__ Q,
                                                const float* __restrict__ K) {
    int bh = blockIdx.x;
    __shared__ float Kc[64 * PW];
    __shared__ float Qr[64 * PW];   // reused for u after matmul
    __shared__ float colsum[64];
    __shared__ int ci_s[64], ri_s[64];

    const float* Kb = K + (size_t)bh * Nv * Dv;
    const float* Qb = Q + (size_t)bh * Nv * Dv;
    int tid = threadIdx.x;
    if (tid < 64) { ci_s[tid] = g_cidx[bh * Mv + tid]; ri_s[tid] = g_ridx[bh * Mv + tid]; }
    __syncthreads();

    for (int idx = tid; idx < 64 * 16; idx += 256) {
        int r = idx >> 4, c4 = (idx & 15) * 4;
        float4 q4 = *(const float4*)(Qb + (size_t)ri_s[r] * Dv + c4);
        q4.x *= 0.125f; q4.y *= 0.125f; q4.z *= 0.125f; q4.w *= 0.125f;
        *(float4*)&Qr[r * PW + c4] = q4;
        *(float4*)&Kc[r * PW + c4] = *(const float4*)(Kb + (size_t)ci_s[r] * Dv + c4);
    }
    __syncthreads();

    int tx = tid & 15, ty = tid >> 4;
    float acc[4][4];
    #pragma unroll
    for (int i = 0; i < 4; i++)
        #pragma unroll
        for (int j = 0; j < 4; j++) acc[i][j] = 0.f;
    #pragma unroll 4
    for (int k4 = 0; k4 < 16; k4++) {
        float4 a[4], bb[4];
        #pragma unroll
        for (int i = 0; i < 4; i++) a[i] = *(const float4*)&Qr[(ty * 4 + i) * PW + k4 * 4];
        #pragma unroll
        for (int j = 0; j < 4; j++) bb[j] = *(const float4*)&Kc[(tx + 16 * j) * PW + k4 * 4];
        #pragma unroll
        for (int i = 0; i < 4; i++)
            #pragma unroll
            for (int j = 0; j < 4; j++) {
                acc[i][j] = fmaf(a[i].x, bb[j].x, acc[i][j]);
                acc[i][j] = fmaf(a[i].y, bb[j].y, acc[i][j]);
                acc[i][j] = fmaf(a[i].z, bb[j].z, acc[i][j]);
                acc[i][j] = fmaf(a[i].w, bb[j].w, acc[i][j]);
            }
    }
    __syncthreads();   // matmul done; Qr reusable

    // row softmax within 16-lane tx-groups (row = ty*4+i, cols tx+16j)
    #pragma unroll
    for (int i = 0; i < 4; i++) {
        float mx = fmaxf(fmaxf(acc[i][0], acc[i][1]), fmaxf(acc[i][2], acc[i][3]));
        #pragma unroll
        for (int o = 8; o; o >>= 1) mx = fmaxf(mx, __shfl_xor_sync(0xffffffffu, mx, o));
        float e[4], sm = 0.f;
        #pragma unroll
        for (int j = 0; j < 4; j++) { e[j] = __expf(acc[i][j] - mx); sm += e[j]; }
        #pragma unroll
        for (int o = 8; o; o >>= 1) sm += __shfl_xor_sync(0xffffffffu, sm, o);
        float inv = 1.f / sm;
        int row = ty * 4 + i;
        #pragma unroll
        for (int j = 0; j < 4; j++) {
            float p = e[j] * inv;
            Qr[row * PW + tx + 16 * j] = p;
            g_u[(bh * 64 + row) * 64 + tx + 16 * j] = p;
        }
    }
    __syncthreads();
    if (tid < 64) {
        float s = 0.f;
        #pragma unroll 8
        for (int i = 0; i < 64; i++) s += Qr[i * PW + tid];
        colsum[tid] = s;
    }
    __syncthreads();
    if (tid == 0) {
        float mx = colsum[0];
        for (int j = 1; j < 64; j++) mx = fmaxf(mx, colsum[j]);
        atomicMax(&g_gmax, __float_as_uint(mx));
    }
}

// ---------------- vectorized NN 64x64 matmul, pitch 64 ----------------
__device__ __forceinline__ void mm64v(const float* __restrict__ A,
                                      const float* __restrict__ Bm,
                                      float acc[4][4], int tx, int ty) {
    #pragma unroll
    for (int i = 0; i < 4; i++)
        #pragma unroll
        for (int j = 0; j < 4; j++) acc[i][j] = 0.f;
    #pragma unroll 2
    for (int k4 = 0; k4 < 16; k4++) {
        float4 a[4];
        #pragma unroll
        for (int i = 0; i < 4; i++) a[i] = *(const float4*)&A[(ty * 4 + i) * 64 + k4 * 4];
        #pragma unroll
        for (int kk = 0; kk < 4; kk++) {
            float4 bv = *(const float4*)&Bm[(k4 * 4 + kk) * 64 + tx * 4];
            float av[4];
            av[0] = (kk == 0) ? a[0].x : (kk == 1) ? a[0].y : (kk == 2) ? a[0].z : a[0].w;
            av[1] = (kk == 0) ? a[1].x : (kk == 1) ? a[1].y : (kk == 2) ? a[1].z : a[1].w;
            av[2] = (kk == 0) ? a[2].x : (kk == 1) ? a[2].y : (kk == 2) ? a[2].z : a[2].w;
            av[3] = (kk == 0) ? a[3].x : (kk == 1) ? a[3].y : (kk == 2) ? a[3].z : a[3].w;
            #pragma unroll
            for (int i = 0; i < 4; i++) {
                acc[i][0] = fmaf(av[i], bv.x, acc[i][0]);
                acc[i][1] = fmaf(av[i], bv.y, acc[i][1]);
                acc[i][2] = fmaf(av[i], bv.z, acc[i][2]);
                acc[i][3] = fmaf(av[i], bv.w, acc[i][3]);
            }
        }
    }
}

// ---------------- Newton-Schulz inverse -> g_Vinv ----------------
__global__ __launch_bounds__(256) void inv_kernel() {
    __shared__ float Vv[4096];
    __shared__ float A[4096];
    __shared__ float T[4096];

    int bh = blockIdx.x, tid = threadIdx.x;
    int tx = tid & 15, ty = tid >> 4;
    const float* Ug = g_u + (size_t)bh * 4096;
    float ginv = 1.f / __uint_as_float(g_gmax);

    for (int i = tid; i < 4096; i += 256) {
        int r = i >> 6, c = i & 63;
        Vv[r * 64 + c] = Ug[c * 64 + r] * ginv;
    }
    __syncthreads();

    float acc[4][4], t1[4][4];
    for (int it = 0; it < 6; ++it) {
        // A = U @ V  (U from global, float4, tx-broadcast)
        #pragma unroll
        for (int i = 0; i < 4; i++)
            #pragma unroll
            for (int j = 0; j < 4; j++) acc[i][j] = 0.f;
        #pragma unroll 2
        for (int k4 = 0; k4 < 16; k4++) {
            float4 a[4];
            #pragma unroll
            for (int i = 0; i < 4; i++)
                a[i] = *(const float4*)(Ug + (ty * 4 + i) * 64 + k4 * 4);
            #pragma unroll
            for (int kk = 0; kk < 4; kk++) {
                float4 bv = *(const float4*)&Vv[(k4 * 4 + kk) * 64 + tx * 4];
                float av[4];
                av[0] = (kk == 0) ? a[0].x : (kk == 1) ? a[0].y : (kk == 2) ? a[0].z : a[0].w;
                av[1] = (kk == 0) ? a[1].x : (kk == 1) ? a[1].y : (kk == 2) ? a[1].z : a[1].w;
                av[2] = (kk == 0) ? a[2].x : (kk == 1) ? a[2].y : (kk == 2) ? a[2].z : a[2].w;
                av[3] = (kk == 0) ? a[3].x : (kk == 1) ? a[3].y : (kk == 2) ? a[3].z : a[3].w;
                #pragma unroll
                for (int i = 0; i < 4; i++) {
                    acc[i][0] = fmaf(av[i], bv.x, acc[i][0]);
                    acc[i][1] = fmaf(av[i], bv.y, acc[i][1]);
                    acc[i][2] = fmaf(av[i], bv.z, acc[i][2]);
                    acc[i][3] = fmaf(av[i], bv.w, acc[i][3]);
                }
            }
        }
        __syncthreads();
        #pragma unroll
        for (int i = 0; i < 4; i++)
            #pragma unroll
            for (int j = 0; j < 4; j++) A[(ty * 4 + i) * 64 + tx * 4 + j] = acc[i][j];
        __syncthreads();

        mm64v(A, A, acc, tx, ty);
        #pragma unroll
        for (int i = 0; i < 4; i++)
            #pragma unroll
            for (int j = 0; j < 4; j++)
                t1[i][j] = 7.f * A[(ty * 4 + i) * 64 + tx * 4 + j] - acc[i][j];
        #pragma unroll
        for (int i = 0; i < 4; i++)
            #pragma unroll
            for (int j = 0; j < 4; j++) T[(ty * 4 + i) * 64 + tx * 4 + j] = t1[i][j];
        __syncthreads();

        mm64v(A, T, acc, tx, ty);
        #pragma unroll
        for (int i = 0; i < 4; i++)
            #pragma unroll
            for (int j = 0; j < 4; j++)
                t1[i][j] = 15.f * A[(ty * 4 + i) * 64 + tx * 4 + j] - acc[i][j];
        __syncthreads();
        #pragma unroll
        for (int i = 0; i < 4; i++)
            #pragma unroll
            for (int j = 0; j < 4; j++) T[(ty * 4 + i) * 64 + tx * 4 + j] = t1[i][j];
        __syncthreads();

        mm64v(Vv, T, acc, tx, ty);
        #pragma unroll
        for (int i = 0; i < 4; i++)
            #pragma unroll
            for (int j = 0; j < 4; j++)
                t1[i][j] = 0.25f * (13.f * Vv[(ty * 4 + i) * 64 + tx * 4 + j] - acc[i][j]);
        __syncthreads();
        #pragma unroll
        for (int i = 0; i < 4; i++)
            #pragma unroll
            for (int j = 0; j < 4; j++) Vv[(ty * 4 + i) * 64 + tx * 4 + j] = t1[i][j];
        __syncthreads();
    }

    for (int i = tid; i < 4096; i += 256)
        g_Vinv[(size_t)bh * 4096 + i] = Vv[i];
}

// ---------------- flash pass: Y_partial = softmax_n(nr@K^T, mask) @ V ----------
extern __shared__ float fsmem[];
__global__ __launch_bounds__(256) void flash_kernel(const float* __restrict__ Q,
                                                    const float* __restrict__ K,
                                                    const float* __restrict__ V,
                                                    const int* __restrict__ mask) {
    float* nr = fsmem;                 // 64*PW
    float* KV = nr + 64 * PW;          // 64*PW (K pitch PW, V pitch 64)
    float* P  = KV + 64 * PW;          // 64*PW
    __shared__ float rowmax[64], rowsum[64], alpha_s[64];
    __shared__ int   msk[64];
    __shared__ int   ri_s[64];

    int bh = blockIdx.y, sp = blockIdx.x;
    int b = bh / Hv;
    const float* Qb = Q + (size_t)bh * Nv * Dv;
    const float* Kb = K + (size_t)bh * Nv * Dv;
    const float* Vb = V + (size_t)bh * Nv * Dv;

    int tid = threadIdx.x, tx = tid & 15, ty = tid >> 4;
    int wp = tid >> 5, lane = tid & 31;

    if (tid < 64) {
        ri_s[tid] = g_ridx[bh * Mv + tid];
        rowmax[tid] = NEG_INF; rowsum[tid] = 0.f;
    }
    __syncthreads();
    for (int idx = tid; idx < 64 * 16; idx += 256) {
        int r = idx >> 4, c4 = (idx & 15) * 4;
        float4 q4 = *(const float4*)(Qb + (size_t)ri_s[r] * Dv + c4);
        q4.x *= 0.125f; q4.y *= 0.125f; q4.z *= 0.125f; q4.w *= 0.125f;
        *(float4*)&nr[r * PW + c4] = q4;
    }

    float acc[4][4];
    #pragma unroll
    for (int i = 0; i < 4; i++)
        #pragma unroll
        for (int j = 0; j < 4; j++) acc[i][j] = 0.f;

    int base0 = sp * CHUNK;
    for (int t = 0; t < CHUNK / 64; t++) {
        int base = base0 + t * 64;
        __syncthreads();
        for (int idx = tid; idx < 64 * 16; idx += 256) {
            int r = idx >> 4, c4 = (idx & 15) * 4;
            *(float4*)&KV[r * PW + c4] = *(const float4*)(Kb + (size_t)(base + r) * Dv + c4);
        }
        if (tid < 64) msk[tid] = mask[b * Nv + base + tid];
        __syncthreads();

        // scores: 64m x 64n, thread tile 4m x 4n (n = tx+16j)
        float sc[4][4];
        #pragma unroll
        for (int i = 0; i < 4; i++)
            #pragma unroll
            for (int j = 0; j < 4; j++) sc[i][j] = 0.f;
        #pragma unroll 4
        for (int k4 = 0; k4 < 16; k4++) {
            float4 a[4], bb[4];
            #pragma unroll
            for (int i = 0; i < 4; i++) a[i] = *(const float4*)&nr[(ty * 4 + i) * PW + k4 * 4];
            #pragma unroll
            for (int j = 0; j < 4; j++) bb[j] = *(const float4*)&KV[(tx + 16 * j) * PW + k4 * 4];
            #pragma unroll
            for (int i = 0; i < 4; i++)
                #pragma unroll
                for (int j = 0; j < 4; j++) {
                    sc[i][j] = fmaf(a[i].x, bb[j].x, sc[i][j]);
                    sc[i][j] = fmaf(a[i].y, bb[j].y, sc[i][j]);
                    sc[i][j] = fmaf(a[i].z, bb[j].z, sc[i][j]);
                    sc[i][j] = fmaf(a[i].w, bb[j].w, sc[i][j]);
                }
        }
        #pragma unroll
        for (int j = 0; j < 4; j++) {
            int n = tx + 16 * j;
            bool ok = (msk[n] != 0);
            #pragma unroll
            for (int i = 0; i < 4; i++)
                P[(ty * 4 + i) * PW + n] = ok ? sc[i][j] : NEG_INF;
        }
        __syncthreads();

        // softmax update (warps) + V-tile load (all threads, pitch 64) — independent
        for (int idx = tid; idx < 64 * 16; idx += 256) {
            int r = idx >> 4, c4 = (idx & 15) * 4;
            *(float4*)&KV[r * 64 + c4] = *(const float4*)(Vb + (size_t)(base + r) * Dv + c4);
        }
        for (int r = wp; r < 64; r += 8) {
            float v0 = P[r * PW + lane], v1 = P[r * PW + lane + 32];
            float tmx = fmaxf(v0, v1);
            #pragma unroll
            for (int o = 16; o; o >>= 1) tmx = fmaxf(tmx, __shfl_xor_sync(0xffffffffu, tmx, o));
            float om = rowmax[r];
            float nm = fmaxf(om, tmx);
            float mc = fmaxf(nm, -1e30f);
            float p0 = __expf(v0 - mc), p1 = __expf(v1 - mc);
            float ts = p0 + p1;
            #pragma unroll
            for (int o = 16; o; o >>= 1) ts += __shfl_xor_sync(0xffffffffu, ts, o);
            if (lane == 0) {
                float al = __expf(om - mc);
                alpha_s[r] = al;
                rowsum[r] = rowsum[r] * al + ts;
                rowmax[r] = nm;
            }
            P[r * PW + lane] = p0;
            P[r * PW + lane + 32] = p1;
        }
        __syncthreads();

        // rescale + accumulate P @ V  (thread tile 4m x 4d)
        #pragma unroll
        for (int i = 0; i < 4; i++) {
            float al = alpha_s[ty * 4 + i];
            #pragma unroll
            for (int j = 0; j < 4; j++) acc[i][j] *= al;
        }
        #pragma unroll 2
        for (int k4 = 0; k4 < 16; k4++) {
            float4 a[4];
            #pragma unroll
            for (int i = 0; i < 4; i++) a[i] = *(const float4*)&P[(ty * 4 + i) * PW + k4 * 4];
            #pragma unroll
            for (int kk = 0; kk < 4; kk++) {
                float4 bv = *(const float4*)&KV[(k4 * 4 + kk) * 64 + tx * 4];
                float av[4];
                av[0] = (kk == 0) ? a[0].x : (kk == 1) ? a[0].y : (kk == 2) ? a[0].z : a[0].w;
                av[1] = (kk == 0) ? a[1].x : (kk == 1) ? a[1].y : (kk == 2) ? a[1].z : a[1].w;
                av[2] = (kk == 0) ? a[2].x : (kk == 1) ? a[2].y : (kk == 2) ? a[2].z : a[2].w;
                av[3] = (kk == 0) ? a[3].x : (kk == 1) ? a[3].y : (kk == 2) ? a[3].z : a[3].w;
                #pragma unroll
                for (int i = 0; i < 4; i++) {
                    acc[i][0] = fmaf(av[i], bv.x, acc[i][0]);
                    acc[i][1] = fmaf(av[i], bv.y, acc[i][1]);
                    acc[i][2] = fmaf(av[i], bv.z, acc[i][2]);
                    acc[i][3] = fmaf(av[i], bv.w, acc[i][3]);
                }
            }
        }
    }

    int idxbase = (bh * NSPLIT + sp) * 64;
    if (tid < 64) { g_mx[idxbase + tid] = rowmax[tid]; g_sm[idxbase + tid] = rowsum[tid]; }
    #pragma unroll
    for (int i = 0; i < 4; i++) {
        float4 w = make_float4(acc[i][0], acc[i][1], acc[i][2], acc[i][3]);
        *(float4*)&g_Yp[((size_t)idxbase + ty * 4 + i) * 64 + tx * 4] = w;
    }
}

// ---------------- combine split partials into Y ----------------
__global__ __launch_bounds__(256) void combine_kernel() {
    int bh = blockIdx.x, tid = threadIdx.x;
    __shared__ float smx[64], ssum[64];
    if (tid < 64) {
        float mx = NEG_INF;
        for (int s = 0; s < NSPLIT; s++)
            mx = fmaxf(mx, g_mx[(bh * NSPLIT + s) * 64 + tid]);
        float mc = fmaxf(mx, -1e30f);
        float tot = 0.f;
        for (int s = 0; s < NSPLIT; s++)
            tot += __expf(g_mx[(bh * NSPLIT + s) * 64 + tid] - mc) *
                   g_sm[(bh * NSPLIT + s) * 64 + tid];
        smx[tid] = mc; ssum[tid] = tot;
    }
    __syncthreads();
    int m = tid >> 2, db = (tid & 3) * 16;
    float inv = 1.f / ssum[m];
    float acc[16];
    #pragma unroll
    for (int d = 0; d < 16; d++) acc[d] = 0.f;
    for (int s = 0; s < NSPLIT; s++) {
        float w = __expf(g_mx[(bh * NSPLIT + s) * 64 + m] - smx[m]);
        const float* yp = g_Yp + (((size_t)(bh * NSPLIT + s) * 64) + m) * 64 + db;
        #pragma unroll
        for (int d = 0; d < 16; d++) acc[d] += w * yp[d];
    }
    float* y = g_Y + ((size_t)bh * 64 + m) * 64 + db;
    #pragma unroll
    for (int d = 0; d < 16; d++) y[d] = acc[d] * inv;
}

// ---------------- Z = Vinv @ Y ----------------
__global__ __launch_bounds__(256) void z_kernel() {
    __shared__ float Vv[4096];
    __shared__ float Ys[4096];
    int bh = blockIdx.x, tid = threadIdx.x;
    int tx = tid & 15, ty = tid >> 4;
    for (int i = tid; i < 4096; i += 256) {
        Vv[i] = g_Vinv[(size_t)bh * 4096 + i];
        Ys[i] = g_Y[(size_t)bh * 4096 + i];
    }
    __syncthreads();
    float acc[4][4];
    mm64v(Vv, Ys, acc, tx, ty);
    #pragma unroll
    for (int i = 0; i < 4; i++) {
        float4 w = make_float4(acc[i][0], acc[i][1], acc[i][2], acc[i][3]);
        *(float4*)&g_Z[((size_t)bh * 64 + ty * 4 + i) * 64 + tx * 4] = w;
    }
}

// ---------------- fused: X = softmax(Qs @ nc^T) @ Z ----------------
extern __shared__ float xsmem[];
__global__ __launch_bounds__(256) void fx_kernel(const float* __restrict__ Q,
                                                 const float* __restrict__ K,
                                                 float* __restrict__ out) {
    float* ncs = xsmem;                // 64*PW
    float* qs  = ncs + 64 * PW;        // 64*PW  (scores/P after matmul)
    float* Zs  = qs + 64 * PW;         // 64*64
    __shared__ int ci_s[64];

    int bh = blockIdx.y; int n0 = blockIdx.x * 64;
    const float* Kb = K + (size_t)bh * Nv * Dv;
    const float* Qb = Q + (size_t)bh * Nv * Dv;
    int tid = threadIdx.x;
    if (tid < 64) ci_s[tid] = g_cidx[bh * Mv + tid];
    __syncthreads();

    for (int idx = tid; idx < 64 * 16; idx += 256) {
        int r = idx >> 4, c4 = (idx & 15) * 4;
        float4 q4 = *(const float4*)(Qb + (size_t)(n0 + r) * Dv + c4);
        q4.x *= 0.125f; q4.y *= 0.125f; q4.z *= 0.125f; q4.w *= 0.125f;
        *(float4*)&qs[r * PW + c4] = q4;
        *(float4*)&ncs[r * PW + c4] = *(const float4*)(Kb + (size_t)ci_s[r] * Dv + c4);
        *(float4*)&Zs[r * 64 + c4] = *(const float4*)(g_Z + (size_t)bh * 4096 + r * 64 + c4);
    }
    __syncthreads();

    int tx = tid & 15, ty = tid >> 4;
    float acc[4][4];
    #pragma unroll
    for (int i = 0; i < 4; i++)
        #pragma unroll
        for (int j = 0; j < 4; j++) acc[i][j] = 0.f;

    #pragma unroll 4
    for (int k4 = 0; k4 < 16; k4++) {
        float4 a[4], bb[4];
        #pragma unroll
        for (int i = 0; i < 4; i++) a[i] = *(const float4*)&qs[(ty * 4 + i) * PW + k4 * 4];
        #pragma unroll
        for (int j = 0; j < 4; j++) bb[j] = *(const float4*)&ncs[(tx + 16 * j) * PW + k4 * 4];
        #pragma unroll
        for (int i = 0; i < 4; i++)
            #pragma unroll
            for (int j = 0; j < 4; j++) {
                acc[i][j] = fmaf(a[i].x, bb[j].x, acc[i][j]);
                acc[i][j] = fmaf(a[i].y, bb[j].y, acc[i][j]);
                acc[i][j] = fmaf(a[i].z, bb[j].z, acc[i][j]);
                acc[i][j] = fmaf(a[i].w, bb[j].w, acc[i][j]);
            }
    }
    __syncthreads();
    #pragma unroll
    for (int i = 0; i < 4; i++)
        #pragma unroll
        for (int j = 0; j < 4; j++)
            qs[(ty * 4 + i) * PW + tx + 16 * j] = acc[i][j];
    __syncthreads();

    // softmax rows in-place
    int warp = tid >> 5, lane = tid & 31;
    for (int r = warp; r < 64; r += 8) {
        float v0 = qs[r * PW + lane], v1 = qs[r * PW + lane + 32];
        float mx = fmaxf(v0, v1);
        #pragma unroll
        for (int o = 16; o; o >>= 1) mx = fmaxf(mx, __shfl_xor_sync(0xffffffffu, mx, o));
        float e0 = __expf(v0 - mx), e1 = __expf(v1 - mx);
        float sm = e0 + e1;
        #pragma unroll
        for (int o = 16; o; o >>= 1) sm += __shfl_xor_sync(0xffffffffu, sm, o);
        float inv = 1.f / sm;
        qs[r * PW + lane] = e0 * inv;
        qs[r * PW + lane + 32] = e1 * inv;
    }
    __syncthreads();

    // X = P @ Z
    #pragma unroll
    for (int i = 0; i < 4; i++)
        #pragma unroll
        for (int j = 0; j < 4; j++) acc[i][j] = 0.f;
    #pragma unroll 2
    for (int k4 = 0; k4 < 16; k4++) {
        float4 a[4];
        #pragma unroll
        for (int i = 0; i < 4; i++) a[i] = *(const float4*)&qs[(ty * 4 + i) * PW + k4 * 4];
        #pragma unroll
        for (int kk = 0; kk < 4; kk++) {
            float4 bv = *(const float4*)&Zs[(k4 * 4 + kk) * 64 + tx * 4];
            float av[4];
            av[0] = (kk == 0) ? a[0].x : (kk == 1) ? a[0].y : (kk == 2) ? a[0].z : a[0].w;
            av[1] = (kk == 0) ? a[1].x : (kk == 1) ? a[1].y : (kk == 2) ? a[1].z : a[1].w;
            av[2] = (kk == 0) ? a[2].x : (kk == 1) ? a[2].y : (kk == 2) ? a[2].z : a[2].w;
            av[3] = (kk == 0) ? a[3].x : (kk == 1) ? a[3].y : (kk == 2) ? a[3].z : a[3].w;
            #pragma unroll
            for (int i = 0; i < 4; i++) {
                acc[i][0] = fmaf(av[i], bv.x, acc[i][0]);
                acc[i][1] = fmaf(av[i], bv.y, acc[i][1]);
                acc[i][2] = fmaf(av[i], bv.z, acc[i][2]);
                acc[i][3] = fmaf(av[i], bv.w, acc[i][3]);
            }
        }
    }
    #pragma unroll
    for (int i = 0; i < 4; i++) {
        float4 w = make_float4(acc[i][0], acc[i][1], acc[i][2], acc[i][3]);
        *(float4*)(out + ((size_t)bh * Nv + n0 + ty * 4 + i) * Dv + tx * 4) = w;
    }
}

// ---------------- launch ----------------
extern "C" void kernel_launch(void* const* d_in, const int* in_sizes, int n_in,
                              void* d_out, int out_size) {
    (void)in_sizes; (void)n_in; (void)out_size;
    const float* Q    = (const float*)d_in[0];
    const float* K    = (const float*)d_in[1];
    const float* V    = (const float*)d_in[2];
    const int*   mask = (const int*)d_in[3];
    float* out = (float*)d_out;

    const int FLASH_SMEM = 3 * 64 * PW * (int)sizeof(float);   // 52224
    const int FX_SMEM = (2 * 64 * PW + 64 * 64) * (int)sizeof(float); // 51200
    cudaFuncSetAttribute(flash_kernel, cudaFuncAttributeMaxDynamicSharedMemorySize, FLASH_SMEM);
    cudaFuncSetAttribute(fx_kernel, cudaFuncAttributeMaxDynamicSharedMemorySize, FX_SMEM);

    cudaStream_t s2;
    cudaEvent_t evA, evB;
    cudaStreamCreateWithFlags(&s2, cudaStreamNonBlocking);
    cudaEventCreateWithFlags(&evA, cudaEventDisableTiming);
    cudaEventCreateWithFlags(&evB, cudaEventDisableTiming);

    init_kernel<<<1, 1>>>();
    select_kernel<<<dim3(BH, 2), 256>>>(K, Q, mask);
    cudaEventRecord(evA, 0);

    // side stream: u -> Newton inverse (overlaps flash)
    cudaStreamWaitEvent(s2, evA, 0);
    u_kernel<<<BH, 256, 0, s2>>>(Q, K);
    inv_kernel<<<BH, 256, 0, s2>>>();
    cudaEventRecord(evB, s2);

    // main stream: flash + combine
    flash_kernel<<<dim3(NSPLIT, BH), 256, FLASH_SMEM>>>(Q, K, V, mask);
    combine_kernel<<<BH, 256>>>();

    cudaStreamWaitEvent(0, evB, 0);
    z_kernel<<<BH, 256>>>();
    fx_kernel<<<dim3(Nv / 64, BH), 256, FX_SMEM>>>(Q, K, out);
}

// round 5
// speedup vs baseline: 1.5050x; 1.1537x over previous
#include <cuda_runtime.h>
#include <float.h>

#define Bv 4
#define Hv 8
#define BH 32
#define Nv 4096
#define Dv 64
#define Mv 64
#define NSPLIT 32
#define CHUNK 128
#define PW 68              // padded pitch (words); 16B-aligned rows, 2-way-max conflicts

#define NEG_INF __int_as_float(0xff800000)

typedef unsigned long long u64;

// ---- packed f32x2 helpers (SASS FFMA2 path; PTX-only per pattern notes) ----
__device__ __forceinline__ u64 ffma2(u64 a, u64 b, u64 c) {
    u64 d;
    asm("fma.rn.f32x2 %0, %1, %2, %3;" : "=l"(d) : "l"(a), "l"(b), "l"(c));
    return d;
}
__device__ __forceinline__ u64 fmul2(u64 a, u64 b) {
    u64 d;
    asm("mul.rn.f32x2 %0, %1, %2;" : "=l"(d) : "l"(a), "l"(b));
    return d;
}
__device__ __forceinline__ float pairsum(u64 v) {
    unsigned lo, hi;
    asm("mov.b64 {%0, %1}, %2;" : "=r"(lo), "=r"(hi) : "l"(v));
    return __uint_as_float(lo) + __uint_as_float(hi);
}
__device__ __forceinline__ u64 pack2(float x) {
    unsigned u = __float_as_uint(x);
    u64 d;
    asm("mov.b64 %0, {%1, %2};" : "=l"(d) : "r"(u), "r"(u));
    return d;
}

// ---------------- scratch ----------------
__device__ int   g_cidx[BH * Mv];
__device__ int   g_ridx[BH * Mv];
__device__ float g_u[BH * Mv * Mv];
__device__ float g_Vinv[BH * Mv * Mv];
__device__ float g_Yp[(size_t)BH * NSPLIT * Mv * Dv];
__device__ float g_mx[BH * NSPLIT * Mv];
__device__ float g_sm[BH * NSPLIT * Mv];
__device__ float g_Y[BH * Mv * Dv];
__device__ float g_Zt[BH * Mv * Dv];      // Z transposed: [bh][d][m]
__device__ unsigned int g_gmax;

__global__ void init_kernel() { g_gmax = 0u; }

// ---------------- top-k selection ----------------
__global__ __launch_bounds__(256) void select_kernel(const float* __restrict__ Kp,
                                                     const float* __restrict__ Qp,
                                                     const int* __restrict__ mask) {
    int bh = blockIdx.x;
    int b = bh / Hv;
    const float* T = (blockIdx.y == 0) ? Kp : Qp;
    int* outIdx = (blockIdx.y == 0) ? g_cidx : g_ridx;

    __shared__ float s[Nv];
    __shared__ float cmax[16];
    __shared__ int   cidx[16];
    __shared__ int   picked[Mv];

    int tid = threadIdx.x;
    int warp = tid >> 5, lane = tid & 31;
    const float* Tb = T + (size_t)bh * Nv * Dv;

    for (int n = warp; n < Nv; n += 8) {
        float v = Tb[(size_t)n * Dv + lane] + Tb[(size_t)n * Dv + lane + 32];
        #pragma unroll
        for (int o = 16; o; o >>= 1) v += __shfl_xor_sync(0xffffffffu, v, o);
        if (lane == 0) {
            bool bad = (n == 0) || (mask[b * Nv + n] != 0);
            s[n] = bad ? -FLT_MAX : v;
        }
    }
    __syncthreads();

    for (int c = warp; c < 16; c += 8) {
        float bv = -FLT_MAX; int bi = Nv;
        #pragma unroll
        for (int t = 0; t < 8; t++) {
            int idx = c * 256 + lane + 32 * t;
            float v = s[idx];
            if (v > bv || (v == bv && idx < bi)) { bv = v; bi = idx; }
        }
        #pragma unroll
        for (int o = 16; o; o >>= 1) {
            float ov = __shfl_xor_sync(0xffffffffu, bv, o);
            int   oi = __shfl_xor_sync(0xffffffffu, bi, o);
            if (ov > bv || (ov == bv && oi < bi)) { bv = ov; bi = oi; }
        }
        if (lane == 0) { cmax[c] = bv; cidx[c] = bi; }
    }
    __syncthreads();

    if (warp == 0) {
        for (int it = 0; it < Mv - 1; ++it) {
            float bv = (lane < 16) ? cmax[lane] : -FLT_MAX;
            int   bi = (lane < 16) ? cidx[lane] : Nv;
            #pragma unroll
            for (int o = 16; o; o >>= 1) {
                float ov = __shfl_xor_sync(0xffffffffu, bv, o);
                int   oi = __shfl_xor_sync(0xffffffffu, bi, o);
                if (ov > bv || (ov == bv && oi < bi)) { bv = ov; bi = oi; }
            }
            int gidx = __shfl_sync(0xffffffffu, bi, 0);
            if (lane == 0) { picked[it] = gidx; s[gidx] = -FLT_MAX; }
            __syncwarp();
            int c = gidx >> 8;
            float nv = -FLT_MAX; int ni = Nv;
            #pragma unroll
            for (int t = 0; t < 8; t++) {
                int idx = c * 256 + lane + 32 * t;
                float v = s[idx];
                if (v > nv || (v == nv && idx < ni)) { nv = v; ni = idx; }
            }
            #pragma unroll
            for (int o = 16; o; o >>= 1) {
                float ov = __shfl_xor_sync(0xffffffffu, nv, o);
                int   oi = __shfl_xor_sync(0xffffffffu, ni, o);
                if (ov > nv || (ov == nv && oi < ni)) { nv = ov; ni = oi; }
            }
            if (lane == 0) { cmax[c] = nv; cidx[c] = ni; }
            __syncwarp();
        }
        if (lane == 0) picked[Mv - 1] = 0;
    }
    __syncthreads();

    if (tid < Mv) {
        int key = picked[tid];
        int rank = 0;
        #pragma unroll 16
        for (int j = 0; j < Mv; j++) rank += (picked[j] < key);
        outIdx[bh * Mv + rank] = key;
    }
}

// ---------------- u = softmax(Qs[ridx] @ nc^T) + global colsum-max ----------
__global__ __launch_bounds__(256) void u_kernel(const float* __restrict__ Q,
                                                const float* __restrict__ K) {
    int bh = blockIdx.x;
    __shared__ float Kc[64 * PW];
    __shared__ float Qr[64 * PW];
    __shared__ float colsum[64];
    __shared__ int ci_s[64], ri_s[64];

    const float* Kb = K + (size_t)bh * Nv * Dv;
    const float* Qb = Q + (size_t)bh * Nv * Dv;
    int tid = threadIdx.x;
    if (tid < 64) { ci_s[tid] = g_cidx[bh * Mv + tid]; ri_s[tid] = g_ridx[bh * Mv + tid]; }
    __syncthreads();

    for (int idx = tid; idx < 64 * 16; idx += 256) {
        int r = idx >> 4, c4 = (idx & 15) * 4;
        float4 q4 = *(const float4*)(Qb + (size_t)ri_s[r] * Dv + c4);
        q4.x *= 0.125f; q4.y *= 0.125f; q4.z *= 0.125f; q4.w *= 0.125f;
        *(float4*)&Qr[r * PW + c4] = q4;
        *(float4*)&Kc[r * PW + c4] = *(const float4*)(Kb + (size_t)ci_s[r] * Dv + c4);
    }
    __syncthreads();

    int tx = tid & 15, ty = tid >> 4;
    u64 sc2[4][4];
    #pragma unroll
    for (int i = 0; i < 4; i++)
        #pragma unroll
        for (int j = 0; j < 4; j++) sc2[i][j] = 0ull;
    #pragma unroll 4
    for (int k4 = 0; k4 < 16; k4++) {
        ulonglong2 a2[4], b2[4];
        #pragma unroll
        for (int i = 0; i < 4; i++) a2[i] = *(const ulonglong2*)&Qr[(ty * 4 + i) * PW + k4 * 4];
        #pragma unroll
        for (int j = 0; j < 4; j++) b2[j] = *(const ulonglong2*)&Kc[(tx + 16 * j) * PW + k4 * 4];
        #pragma unroll
        for (int i = 0; i < 4; i++)
            #pragma unroll
            for (int j = 0; j < 4; j++) {
                sc2[i][j] = ffma2(a2[i].x, b2[j].x, sc2[i][j]);
                sc2[i][j] = ffma2(a2[i].y, b2[j].y, sc2[i][j]);
            }
    }
    __syncthreads();   // Qr reusable

    #pragma unroll
    for (int i = 0; i < 4; i++) {
        float sv[4];
        #pragma unroll
        for (int j = 0; j < 4; j++) sv[j] = pairsum(sc2[i][j]);
        float mx = fmaxf(fmaxf(sv[0], sv[1]), fmaxf(sv[2], sv[3]));
        #pragma unroll
        for (int o = 8; o; o >>= 1) mx = fmaxf(mx, __shfl_xor_sync(0xffffffffu, mx, o));
        float e[4], sm = 0.f;
        #pragma unroll
        for (int j = 0; j < 4; j++) { e[j] = __expf(sv[j] - mx); sm += e[j]; }
        #pragma unroll
        for (int o = 8; o; o >>= 1) sm += __shfl_xor_sync(0xffffffffu, sm, o);
        float inv = 1.f / sm;
        int row = ty * 4 + i;
        #pragma unroll
        for (int j = 0; j < 4; j++) {
            float p = e[j] * inv;
            Qr[row * PW + tx + 16 * j] = p;
            g_u[(bh * 64 + row) * 64 + tx + 16 * j] = p;
        }
    }
    __syncthreads();
    if (tid < 64) {
        float s = 0.f;
        #pragma unroll 8
        for (int i = 0; i < 64; i++) s += Qr[i * PW + tid];
        colsum[tid] = s;
    }
    __syncthreads();
    if (tid == 0) {
        float mx = colsum[0];
        for (int j = 1; j < 64; j++) mx = fmaxf(mx, colsum[j]);
        atomicMax(&g_gmax, __float_as_uint(mx));
    }
}

// ---------------- vectorized NN 64x64 matmul, pitch 64 ----------------
__device__ __forceinline__ void mm64v(const float* __restrict__ A,
                                      const float* __restrict__ Bm,
                                      float acc[4][4], int tx, int ty) {
    #pragma unroll
    for (int i = 0; i < 4; i++)
        #pragma unroll
        for (int j = 0; j < 4; j++) acc[i][j] = 0.f;
    #pragma unroll 2
    for (int k4 = 0; k4 < 16; k4++) {
        float4 a[4];
        #pragma unroll
        for (int i = 0; i < 4; i++) a[i] = *(const float4*)&A[(ty * 4 + i) * 64 + k4 * 4];
        #pragma unroll
        for (int kk = 0; kk < 4; kk++) {
            float4 bv = *(const float4*)&Bm[(k4 * 4 + kk) * 64 + tx * 4];
            float av[4];
            av[0] = (kk == 0) ? a[0].x : (kk == 1) ? a[0].y : (kk == 2) ? a[0].z : a[0].w;
            av[1] = (kk == 0) ? a[1].x : (kk == 1) ? a[1].y : (kk == 2) ? a[1].z : a[1].w;
            av[2] = (kk == 0) ? a[2].x : (kk == 1) ? a[2].y : (kk == 2) ? a[2].z : a[2].w;
            av[3] = (kk == 0) ? a[3].x : (kk == 1) ? a[3].y : (kk == 2) ? a[3].z : a[3].w;
            #pragma unroll
            for (int i = 0; i < 4; i++) {
                acc[i][0] = fmaf(av[i], bv.x, acc[i][0]);
                acc[i][1] = fmaf(av[i], bv.y, acc[i][1]);
                acc[i][2] = fmaf(av[i], bv.z, acc[i][2]);
                acc[i][3] = fmaf(av[i], bv.w, acc[i][3]);
            }
        }
    }
}

// ---------------- Newton-Schulz inverse -> g_Vinv ----------------
__global__ __launch_bounds__(256) void inv_kernel() {
    __shared__ float Vv[4096];
    __shared__ float A[4096];
    __shared__ float T[4096];

    int bh = blockIdx.x, tid = threadIdx.x;
    int tx = tid & 15, ty = tid >> 4;
    const float* Ug = g_u + (size_t)bh * 4096;
    float ginv = 1.f / __uint_as_float(g_gmax);

    for (int i = tid; i < 4096; i += 256) {
        int r = i >> 6, c = i & 63;
        Vv[r * 64 + c] = Ug[c * 64 + r] * ginv;
    }
    __syncthreads();

    float acc[4][4], t1[4][4];
    for (int it = 0; it < 6; ++it) {
        #pragma unroll
        for (int i = 0; i < 4; i++)
            #pragma unroll
            for (int j = 0; j < 4; j++) acc[i][j] = 0.f;
        #pragma unroll 2
        for (int k4 = 0; k4 < 16; k4++) {
            float4 a[4];
            #pragma unroll
            for (int i = 0; i < 4; i++)
                a[i] = *(const float4*)(Ug + (ty * 4 + i) * 64 + k4 * 4);
            #pragma unroll
            for (int kk = 0; kk < 4; kk++) {
                float4 bv = *(const float4*)&Vv[(k4 * 4 + kk) * 64 + tx * 4];
                float av[4];
                av[0] = (kk == 0) ? a[0].x : (kk == 1) ? a[0].y : (kk == 2) ? a[0].z : a[0].w;
                av[1] = (kk == 0) ? a[1].x : (kk == 1) ? a[1].y : (kk == 2) ? a[1].z : a[1].w;
                av[2] = (kk == 0) ? a[2].x : (kk == 1) ? a[2].y : (kk == 2) ? a[2].z : a[2].w;
                av[3] = (kk == 0) ? a[3].x : (kk == 1) ? a[3].y : (kk == 2) ? a[3].z : a[3].w;
                #pragma unroll
                for (int i = 0; i < 4; i++) {
                    acc[i][0] = fmaf(av[i], bv.x, acc[i][0]);
                    acc[i][1] = fmaf(av[i], bv.y, acc[i][1]);
                    acc[i][2] = fmaf(av[i], bv.z, acc[i][2]);
                    acc[i][3] = fmaf(av[i], bv.w, acc[i][3]);
                }
            }
        }
        __syncthreads();
        #pragma unroll
        for (int i = 0; i < 4; i++)
            #pragma unroll
            for (int j = 0; j < 4; j++) A[(ty * 4 + i) * 64 + tx * 4 + j] = acc[i][j];
        __syncthreads();

        mm64v(A, A, acc, tx, ty);
        #pragma unroll
        for (int i = 0; i < 4; i++)
            #pragma unroll
            for (int j = 0; j < 4; j++)
                t1[i][j] = 7.f * A[(ty * 4 + i) * 64 + tx * 4 + j] - acc[i][j];
        #pragma unroll
        for (int i = 0; i < 4; i++)
            #pragma unroll
            for (int j = 0; j < 4; j++) T[(ty * 4 + i) * 64 + tx * 4 + j] = t1[i][j];
        __syncthreads();

        mm64v(A, T, acc, tx, ty);
        #pragma unroll
        for (int i = 0; i < 4; i++)
            #pragma unroll
            for (int j = 0; j < 4; j++)
                t1[i][j] = 15.f * A[(ty * 4 + i) * 64 + tx * 4 + j] - acc[i][j];
        __syncthreads();
        #pragma unroll
        for (int i = 0; i < 4; i++)
            #pragma unroll
            for (int j = 0; j < 4; j++) T[(ty * 4 + i) * 64 + tx * 4 + j] = t1[i][j];
        __syncthreads();

        mm64v(Vv, T, acc, tx, ty);
        #pragma unroll
        for (int i = 0; i < 4; i++)
            #pragma unroll
            for (int j = 0; j < 4; j++)
                t1[i][j] = 0.25f * (13.f * Vv[(ty * 4 + i) * 64 + tx * 4 + j] - acc[i][j]);
        __syncthreads();
        #pragma unroll
        for (int i = 0; i < 4; i++)
            #pragma unroll
            for (int j = 0; j < 4; j++) Vv[(ty * 4 + i) * 64 + tx * 4 + j] = t1[i][j];
        __syncthreads();
    }

    for (int i = tid; i < 4096; i += 256)
        g_Vinv[(size_t)bh * 4096 + i] = Vv[i];
}

// ---------------- flash: Y_partial = softmax_n(nr@K^T, mask) @ V ----------
extern __shared__ float fsmem[];
__global__ __launch_bounds__(256) void flash_kernel(const float* __restrict__ Q,
                                                    const float* __restrict__ K,
                                                    const float* __restrict__ V,
                                                    const int* __restrict__ mask) {
    float* nr = fsmem;                 // [m][d]  64*PW
    float* Kt = nr + 64 * PW;          // [n][d]  64*PW
    float* VT = Kt + 64 * PW;          // [d][n]  64*PW (transposed V)
    float* P  = VT + 64 * PW;          // [m][n]  64*PW
    __shared__ int msk[64];
    __shared__ int ri_s[64];

    int bh = blockIdx.y, sp = blockIdx.x;
    int b = bh / Hv;
    const float* Qb = Q + (size_t)bh * Nv * Dv;
    const float* Kb = K + (size_t)bh * Nv * Dv;
    const float* Vb = V + (size_t)bh * Nv * Dv;

    int tid = threadIdx.x, tx = tid & 15, ty = tid >> 4;

    if (tid < 64) ri_s[tid] = g_ridx[bh * Mv + tid];
    __syncthreads();
    for (int idx = tid; idx < 64 * 16; idx += 256) {
        int r = idx >> 4, c4 = (idx & 15) * 4;
        float4 q4 = *(const float4*)(Qb + (size_t)ri_s[r] * Dv + c4);
        q4.x *= 0.125f; q4.y *= 0.125f; q4.z *= 0.125f; q4.w *= 0.125f;
        *(float4*)&nr[r * PW + c4] = q4;
    }

    u64 acc2[4][4];
    float m_i[4], l_i[4];
    #pragma unroll
    for (int i = 0; i < 4; i++) {
        m_i[i] = NEG_INF; l_i[i] = 0.f;
        #pragma unroll
        for (int j = 0; j < 4; j++) acc2[i][j] = 0ull;
    }

    int base0 = sp * CHUNK;
    for (int t = 0; t < CHUNK / 64; t++) {
        int base = base0 + t * 64;
        __syncthreads();                          // buffers free (and nr ready on t=0)
        for (int idx = tid; idx < 64 * 16; idx += 256) {
            int r = idx >> 4, c4 = (idx & 15) * 4;
            *(float4*)&Kt[r * PW + c4] = *(const float4*)(Kb + (size_t)(base + r) * Dv + c4);
        }
        for (int idx = tid; idx < 64 * 16; idx += 256) {
            int r = idx & 63, c4 = (idx >> 6) * 4;   // transpose store: conflict-free STS
            float4 v = *(const float4*)(Vb + (size_t)(base + r) * Dv + c4);
            VT[(c4 + 0) * PW + r] = v.x;
            VT[(c4 + 1) * PW + r] = v.y;
            VT[(c4 + 2) * PW + r] = v.z;
            VT[(c4 + 3) * PW + r] = v.w;
        }
        if (tid < 64) msk[tid] = mask[b * Nv + base + tid];
        __syncthreads();                          // K, VT, msk ready

        // scores in packed registers
        u64 sc2[4][4];
        #pragma unroll
        for (int i = 0; i < 4; i++)
            #pragma unroll
            for (int j = 0; j < 4; j++) sc2[i][j] = 0ull;
        #pragma unroll 4
        for (int k4 = 0; k4 < 16; k4++) {
            ulonglong2 a2[4], b2[4];
            #pragma unroll
            for (int i = 0; i < 4; i++) a2[i] = *(const ulonglong2*)&nr[(ty * 4 + i) * PW + k4 * 4];
            #pragma unroll
            for (int j = 0; j < 4; j++) b2[j] = *(const ulonglong2*)&Kt[(tx + 16 * j) * PW + k4 * 4];
            #pragma unroll
            for (int i = 0; i < 4; i++)
                #pragma unroll
                for (int j = 0; j < 4; j++) {
                    sc2[i][j] = ffma2(a2[i].x, b2[j].x, sc2[i][j]);
                    sc2[i][j] = ffma2(a2[i].y, b2[j].y, sc2[i][j]);
                }
        }

        int ok0 = msk[tx], ok1 = msk[tx + 16], ok2 = msk[tx + 32], ok3 = msk[tx + 48];

        // register online softmax (row groups = 16 tx-lanes)
        #pragma unroll
        for (int i = 0; i < 4; i++) {
            float s0 = ok0 ? pairsum(sc2[i][0]) : NEG_INF;
            float s1 = ok1 ? pairsum(sc2[i][1]) : NEG_INF;
            float s2 = ok2 ? pairsum(sc2[i][2]) : NEG_INF;
            float s3 = ok3 ? pairsum(sc2[i][3]) : NEG_INF;
            float tmx = fmaxf(fmaxf(s0, s1), fmaxf(s2, s3));
            #pragma unroll
            for (int o = 8; o; o >>= 1) tmx = fmaxf(tmx, __shfl_xor_sync(0xffffffffu, tmx, o));
            float nm = fmaxf(m_i[i], tmx);
            float mc = fmaxf(nm, -1e30f);                 // all-masked guard
            float al = __expf(m_i[i] - mc);               // m_i=-inf -> 0
            float p0 = __expf(s0 - mc), p1 = __expf(s1 - mc);
            float p2v = __expf(s2 - mc), p3 = __expf(s3 - mc);
            float ts = (p0 + p1) + (p2v + p3);
            #pragma unroll
            for (int o = 8; o; o >>= 1) ts += __shfl_xor_sync(0xffffffffu, ts, o);
            l_i[i] = l_i[i] * al + ts;
            m_i[i] = nm;
            u64 al2 = pack2(al);
            #pragma unroll
            for (int jj = 0; jj < 4; jj++) acc2[i][jj] = fmul2(acc2[i][jj], al2);
            int rw = (ty * 4 + i) * PW;
            P[rw + tx] = p0; P[rw + tx + 16] = p1; P[rw + tx + 32] = p2v; P[rw + tx + 48] = p3;
        }
        __syncwarp();                                    // P rows are half-warp-local

        // PV: acc[i][d], d = tx + 16*jj; pairs over n
        #pragma unroll 4
        for (int n4 = 0; n4 < 16; n4++) {
            ulonglong2 p2[4], v2[4];
            #pragma unroll
            for (int i = 0; i < 4; i++) p2[i] = *(const ulonglong2*)&P[(ty * 4 + i) * PW + n4 * 4];
            #pragma unroll
            for (int jj = 0; jj < 4; jj++) v2[jj] = *(const ulonglong2*)&VT[(tx + 16 * jj) * PW + n4 * 4];
            #pragma unroll
            for (int i = 0; i < 4; i++)
                #pragma unroll
                for (int jj = 0; jj < 4; jj++) {
                    acc2[i][jj] = ffma2(p2[i].x, v2[jj].x, acc2[i][jj]);
                    acc2[i][jj] = ffma2(p2[i].y, v2[jj].y, acc2[i][jj]);
                }
        }
    }

    int idxbase = (bh * NSPLIT + sp) * 64;
    if (tx == 0) {
        #pragma unroll
        for (int i = 0; i < 4; i++) {
            g_mx[idxbase + ty * 4 + i] = m_i[i];
            g_sm[idxbase + ty * 4 + i] = l_i[i];
        }
    }
    #pragma unroll
    for (int i = 0; i < 4; i++)
        #pragma unroll
        for (int jj = 0; jj < 4; jj++)
            g_Yp[((size_t)idxbase + ty * 4 + i) * 64 + tx + 16 * jj] = pairsum(acc2[i][jj]);
}

// ---------------- combine split partials into Y ----------------
__global__ __launch_bounds__(256) void combine_kernel() {
    int bh = blockIdx.x, tid = threadIdx.x;
    __shared__ float smx[64], ssum[64];
    if (tid < 64) {
        float mx = NEG_INF;
        for (int s = 0; s < NSPLIT; s++)
            mx = fmaxf(mx, g_mx[(bh * NSPLIT + s) * 64 + tid]);
        float mc = fmaxf(mx, -1e30f);
        float tot = 0.f;
        for (int s = 0; s < NSPLIT; s++)
            tot += __expf(g_mx[(bh * NSPLIT + s) * 64 + tid] - mc) *
                   g_sm[(bh * NSPLIT + s) * 64 + tid];
        smx[tid] = mc; ssum[tid] = tot;
    }
    __syncthreads();
    int m = tid >> 2, db = (tid & 3) * 16;
    float inv = 1.f / ssum[m];
    float acc[16];
    #pragma unroll
    for (int d = 0; d < 16; d++) acc[d] = 0.f;
    for (int s = 0; s < NSPLIT; s++) {
        float w = __expf(g_mx[(bh * NSPLIT + s) * 64 + m] - smx[m]);
        const float* yp = g_Yp + (((size_t)(bh * NSPLIT + s) * 64) + m) * 64 + db;
        #pragma unroll
        for (int d = 0; d < 16; d++) acc[d] += w * yp[d];
    }
    float* y = g_Y + ((size_t)bh * 64 + m) * 64 + db;
    #pragma unroll
    for (int d = 0; d < 16; d++) y[d] = acc[d] * inv;
}

// ---------------- Zt = (Vinv @ Y)^T ----------------
__global__ __launch_bounds__(256) void z_kernel() {
    __shared__ float Vv[4096];
    __shared__ float Ys[4096];
    int bh = blockIdx.x, tid = threadIdx.x;
    int tx = tid & 15, ty = tid >> 4;
    for (int i = tid; i < 4096; i += 256) {
        Vv[i] = g_Vinv[(size_t)bh * 4096 + i];
        Ys[i] = g_Y[(size_t)bh * 4096 + i];
    }
    __syncthreads();
    float acc[4][4];
    mm64v(Vv, Ys, acc, tx, ty);
    #pragma unroll
    for (int i = 0; i < 4; i++)
        #pragma unroll
        for (int j = 0; j < 4; j++)
            g_Zt[(size_t)bh * 4096 + (tx * 4 + j) * 64 + ty * 4 + i] = acc[i][j];
}

// ---------------- fused: X = softmax(Qs @ nc^T) @ Z ----------------
extern __shared__ float xsmem[];
__global__ __launch_bounds__(256) void fx_kernel(const float* __restrict__ Q,
                                                 const float* __restrict__ K,
                                                 float* __restrict__ out) {
    float* ncs = xsmem;                // [m'][d] 64*PW
    float* qs  = ncs + 64 * PW;        // [n][d]  64*PW
    float* Zs  = qs + 64 * PW;         // [d][m'] 64*PW (Z transposed)
    float* P   = Zs + 64 * PW;         // [n][m'] 64*PW
    __shared__ int ci_s[64];

    int bh = blockIdx.y; int n0 = blockIdx.x * 64;
    const float* Kb = K + (size_t)bh * Nv * Dv;
    const float* Qb = Q + (size_t)bh * Nv * Dv;
    int tid = threadIdx.x;
    if (tid < 64) ci_s[tid] = g_cidx[bh * Mv + tid];
    __syncthreads();

    for (int idx = tid; idx < 64 * 16; idx += 256) {
        int r = idx >> 4, c4 = (idx & 15) * 4;
        float4 q4 = *(const float4*)(Qb + (size_t)(n0 + r) * Dv + c4);
        q4.x *= 0.125f; q4.y *= 0.125f; q4.z *= 0.125f; q4.w *= 0.125f;
        *(float4*)&qs[r * PW + c4] = q4;
        *(float4*)&ncs[r * PW + c4] = *(const float4*)(Kb + (size_t)ci_s[r] * Dv + c4);
        *(float4*)&Zs[r * PW + c4] = *(const float4*)(g_Zt + (size_t)bh * 4096 + r * 64 + c4);
    }
    __syncthreads();

    int tx = tid & 15, ty = tid >> 4;
    u64 sc2[4][4];
    #pragma unroll
    for (int i = 0; i < 4; i++)
        #pragma unroll
        for (int j = 0; j < 4; j++) sc2[i][j] = 0ull;
    #pragma unroll 4
    for (int k4 = 0; k4 < 16; k4++) {
        ulonglong2 a2[4], b2[4];
        #pragma unroll
        for (int i = 0; i < 4; i++) a2[i] = *(const ulonglong2*)&qs[(ty * 4 + i) * PW + k4 * 4];
        #pragma unroll
        for (int j = 0; j < 4; j++) b2[j] = *(const ulonglong2*)&ncs[(tx + 16 * j) * PW + k4 * 4];
        #pragma unroll
        for (int i = 0; i < 4; i++)
            #pragma unroll
            for (int j = 0; j < 4; j++) {
                sc2[i][j] = ffma2(a2[i].x, b2[j].x, sc2[i][j]);
                sc2[i][j] = ffma2(a2[i].y, b2[j].y, sc2[i][j]);
            }
    }

    // register softmax + P write
    #pragma unroll
    for (int i = 0; i < 4; i++) {
        float sv[4];
        #pragma unroll
        for (int j = 0; j < 4; j++) sv[j] = pairsum(sc2[i][j]);
        float mx = fmaxf(fmaxf(sv[0], sv[1]), fmaxf(sv[2], sv[3]));
        #pragma unroll
        for (int o = 8; o; o >>= 1) mx = fmaxf(mx, __shfl_xor_sync(0xffffffffu, mx, o));
        float e[4], sm = 0.f;
        #pragma unroll
        for (int j = 0; j < 4; j++) { e[j] = __expf(sv[j] - mx); sm += e[j]; }
        #pragma unroll
        for (int o = 8; o; o >>= 1) sm += __shfl_xor_sync(0xffffffffu, sm, o);
        float inv = 1.f / sm;
        int rw = (ty * 4 + i) * PW;
        #pragma unroll
        for (int j = 0; j < 4; j++) P[rw + tx + 16 * j] = e[j] * inv;
    }
    __syncwarp();

    // X = P @ Z : acc[i][d], d = tx + 16*jj; pairs over m'
    u64 acc2[4][4];
    #pragma unroll
    for (int i = 0; i < 4; i++)
        #pragma unroll
        for (int jj = 0; jj < 4; jj++) acc2[i][jj] = 0ull;
    #pragma unroll 4
    for (int m4 = 0; m4 < 16; m4++) {
        ulonglong2 p2[4], z2[4];
        #pragma unroll
        for (int i = 0; i < 4; i++) p2[i] = *(const ulonglong2*)&P[(ty * 4 + i) * PW + m4 * 4];
        #pragma unroll
        for (int jj = 0; jj < 4; jj++) z2[jj] = *(const ulonglong2*)&Zs[(tx + 16 * jj) * PW + m4 * 4];
        #pragma unroll
        for (int i = 0; i < 4; i++)
            #pragma unroll
            for (int jj = 0; jj < 4; jj++) {
                acc2[i][jj] = ffma2(p2[i].x, z2[jj].x, acc2[i][jj]);
                acc2[i][jj] = ffma2(p2[i].y, z2[jj].y, acc2[i][jj]);
            }
    }
    #pragma unroll
    for (int i = 0; i < 4; i++)
        #pragma unroll
        for (int jj = 0; jj < 4; jj++)
            out[((size_t)bh * Nv + n0 + ty * 4 + i) * Dv + tx + 16 * jj] = pairsum(acc2[i][jj]);
}

// ---------------- launch ----------------
extern "C" void kernel_launch(void* const* d_in, const int* in_sizes, int n_in,
                              void* d_out, int out_size) {
    (void)in_sizes; (void)n_in; (void)out_size;
    const float* Q    = (const float*)d_in[0];
    const float* K    = (const float*)d_in[1];
    const float* V    = (const float*)d_in[2];
    const int*   mask = (const int*)d_in[3];
    float* out = (float*)d_out;

    const int FLASH_SMEM = 4 * 64 * PW * (int)sizeof(float);   // 69632
    const int FX_SMEM    = 4 * 64 * PW * (int)sizeof(float);   // 69632
    cudaFuncSetAttribute(flash_kernel, cudaFuncAttributeMaxDynamicSharedMemorySize, FLASH_SMEM);
    cudaFuncSetAttribute(fx_kernel, cudaFuncAttributeMaxDynamicSharedMemorySize, FX_SMEM);

    cudaStream_t s2;
    cudaEvent_t evA, evB;
    cudaStreamCreateWithFlags(&s2, cudaStreamNonBlocking);
    cudaEventCreateWithFlags(&evA, cudaEventDisableTiming);
    cudaEventCreateWithFlags(&evB, cudaEventDisableTiming);

    init_kernel<<<1, 1>>>();
    select_kernel<<<dim3(BH, 2), 256>>>(K, Q, mask);
    cudaEventRecord(evA, 0);

    // side stream: u -> Newton inverse (overlaps flash)
    cudaStreamWaitEvent(s2, evA, 0);
    u_kernel<<<BH, 256, 0, s2>>>(Q, K);
    inv_kernel<<<BH, 256, 0, s2>>>();
    cudaEventRecord(evB, s2);

    // main stream: flash + combine
    flash_kernel<<<dim3(NSPLIT, BH), 256, FLASH_SMEM>>>(Q, K, V, mask);
    combine_kernel<<<BH, 256>>>();

    cudaStreamWaitEvent(0, evB, 0);
    z_kernel<<<BH, 256>>>();
    fx_kernel<<<dim3(Nv / 64, BH), 256, FX_SMEM>>>(Q, K, out);
}

// round 6
// speedup vs baseline: 1.5244x; 1.0129x over previous
#include <cuda_runtime.h>
#include <float.h>

#define Bv 4
#define Hv 8
#define BH 32
#define Nv 4096
#define Dv 64
#define Mv 64
#define NSPLIT 32
#define CHUNK 128
#define PW 68              // pitch (words): bank = (4*row + col) mod 32 -> conflict-free frags

#define NEG_INF __int_as_float(0xff800000)

typedef unsigned long long u64;

// ---- packed f32x2 helpers (used by u_kernel) ----
__device__ __forceinline__ u64 ffma2(u64 a, u64 b, u64 c) {
    u64 d;
    asm("fma.rn.f32x2 %0, %1, %2, %3;" : "=l"(d) : "l"(a), "l"(b), "l"(c));
    return d;
}
__device__ __forceinline__ float pairsum(u64 v) {
    unsigned lo, hi;
    asm("mov.b64 {%0, %1}, %2;" : "=r"(lo), "=r"(hi) : "l"(v));
    return __uint_as_float(lo) + __uint_as_float(hi);
}

// ---- tf32 mma helpers ----
__device__ __forceinline__ unsigned cvt_tf32(float x) {
    unsigned u;
    asm("cvt.rna.tf32.f32 %0, %1;" : "=r"(u) : "f"(x));
    return u;
}
__device__ __forceinline__ void split_tf32(float x, unsigned& hi, unsigned& lo) {
    hi = cvt_tf32(x);
    lo = cvt_tf32(x - __uint_as_float(hi));
}
__device__ __forceinline__ void mma8(float c[4], const unsigned a[4], unsigned b0, unsigned b1) {
    asm("mma.sync.aligned.m16n8k8.row.col.f32.tf32.tf32.f32 "
        "{%0,%1,%2,%3},{%4,%5,%6,%7},{%8,%9},{%0,%1,%2,%3};"
        : "+f"(c[0]), "+f"(c[1]), "+f"(c[2]), "+f"(c[3])
        : "r"(a[0]), "r"(a[1]), "r"(a[2]), "r"(a[3]), "r"(b0), "r"(b1));
}
// 3xTF32: full-ish fp32 accuracy
__device__ __forceinline__ void mma3(float c[4], const unsigned ah[4], const unsigned al[4],
                                     unsigned bh0, unsigned bh1, unsigned bl0, unsigned bl1) {
    mma8(c, ah, bh0, bh1);
    mma8(c, ah, bl0, bl1);
    mma8(c, al, bh0, bh1);
}

// ---------------- scratch ----------------
__device__ int   g_cidx[BH * Mv];
__device__ int   g_ridx[BH * Mv];
__device__ float g_u[BH * Mv * Mv];
__device__ float g_Vinv[BH * Mv * Mv];
__device__ float g_Yp[(size_t)BH * NSPLIT * Mv * Dv];
__device__ float g_mx[BH * NSPLIT * Mv];
__device__ float g_sm[BH * NSPLIT * Mv];
__device__ float g_Y[BH * Mv * Dv];
__device__ float g_Zt[BH * Mv * Dv];      // Z transposed: [bh][d][m]
__device__ unsigned int g_gmax;

__global__ void init_kernel() { g_gmax = 0u; }

// ---------------- top-k selection ----------------
__global__ __launch_bounds__(256) void select_kernel(const float* __restrict__ Kp,
                                                     const float* __restrict__ Qp,
                                                     const int* __restrict__ mask) {
    int bh = blockIdx.x;
    int b = bh / Hv;
    const float* T = (blockIdx.y == 0) ? Kp : Qp;
    int* outIdx = (blockIdx.y == 0) ? g_cidx : g_ridx;

    __shared__ float s[Nv];
    __shared__ float cmax[16];
    __shared__ int   cidx[16];
    __shared__ int   picked[Mv];

    int tid = threadIdx.x;
    int warp = tid >> 5, lane = tid & 31;
    const float* Tb = T + (size_t)bh * Nv * Dv;

    for (int n = warp; n < Nv; n += 8) {
        float v = Tb[(size_t)n * Dv + lane] + Tb[(size_t)n * Dv + lane + 32];
        #pragma unroll
        for (int o = 16; o; o >>= 1) v += __shfl_xor_sync(0xffffffffu, v, o);
        if (lane == 0) {
            bool bad = (n == 0) || (mask[b * Nv + n] != 0);
            s[n] = bad ? -FLT_MAX : v;
        }
    }
    __syncthreads();

    for (int c = warp; c < 16; c += 8) {
        float bv = -FLT_MAX; int bi = Nv;
        #pragma unroll
        for (int t = 0; t < 8; t++) {
            int idx = c * 256 + lane + 32 * t;
            float v = s[idx];
            if (v > bv || (v == bv && idx < bi)) { bv = v; bi = idx; }
        }
        #pragma unroll
        for (int o = 16; o; o >>= 1) {
            float ov = __shfl_xor_sync(0xffffffffu, bv, o);
            int   oi = __shfl_xor_sync(0xffffffffu, bi, o);
            if (ov > bv || (ov == bv && oi < bi)) { bv = ov; bi = oi; }
        }
        if (lane == 0) { cmax[c] = bv; cidx[c] = bi; }
    }
    __syncthreads();

    if (warp == 0) {
        for (int it = 0; it < Mv - 1; ++it) {
            float bv = (lane < 16) ? cmax[lane] : -FLT_MAX;
            int   bi = (lane < 16) ? cidx[lane] : Nv;
            #pragma unroll
            for (int o = 16; o; o >>= 1) {
                float ov = __shfl_xor_sync(0xffffffffu, bv, o);
                int   oi = __shfl_xor_sync(0xffffffffu, bi, o);
                if (ov > bv || (ov == bv && oi < bi)) { bv = ov; bi = oi; }
            }
            int gidx = __shfl_sync(0xffffffffu, bi, 0);
            if (lane == 0) { picked[it] = gidx; s[gidx] = -FLT_MAX; }
            __syncwarp();
            int c = gidx >> 8;
            float nv = -FLT_MAX; int ni = Nv;
            #pragma unroll
            for (int t = 0; t < 8; t++) {
                int idx = c * 256 + lane + 32 * t;
                float v = s[idx];
                if (v > nv || (v == nv && idx < ni)) { nv = v; ni = idx; }
            }
            #pragma unroll
            for (int o = 16; o; o >>= 1) {
                float ov = __shfl_xor_sync(0xffffffffu, nv, o);
                int   oi = __shfl_xor_sync(0xffffffffu, ni, o);
                if (ov > nv || (ov == nv && oi < ni)) { nv = ov; ni = oi; }
            }
            if (lane == 0) { cmax[c] = nv; cidx[c] = ni; }
            __syncwarp();
        }
        if (lane == 0) picked[Mv - 1] = 0;
    }
    __syncthreads();

    if (tid < Mv) {
        int key = picked[tid];
        int rank = 0;
        #pragma unroll 16
        for (int j = 0; j < Mv; j++) rank += (picked[j] < key);
        outIdx[bh * Mv + rank] = key;
    }
}

// ---------------- u = softmax(Qs[ridx] @ nc^T) + global colsum-max ----------
__global__ __launch_bounds__(256) void u_kernel(const float* __restrict__ Q,
                                                const float* __restrict__ K) {
    int bh = blockIdx.x;
    __shared__ float Kc[64 * PW];
    __shared__ float Qr[64 * PW];
    __shared__ float colsum[64];
    __shared__ int ci_s[64], ri_s[64];

    const float* Kb = K + (size_t)bh * Nv * Dv;
    const float* Qb = Q + (size_t)bh * Nv * Dv;
    int tid = threadIdx.x;
    if (tid < 64) { ci_s[tid] = g_cidx[bh * Mv + tid]; ri_s[tid] = g_ridx[bh * Mv + tid]; }
    __syncthreads();

    for (int idx = tid; idx < 64 * 16; idx += 256) {
        int r = idx >> 4, c4 = (idx & 15) * 4;
        float4 q4 = *(const float4*)(Qb + (size_t)ri_s[r] * Dv + c4);
        q4.x *= 0.125f; q4.y *= 0.125f; q4.z *= 0.125f; q4.w *= 0.125f;
        *(float4*)&Qr[r * PW + c4] = q4;
        *(float4*)&Kc[r * PW + c4] = *(const float4*)(Kb + (size_t)ci_s[r] * Dv + c4);
    }
    __syncthreads();

    int tx = tid & 15, ty = tid >> 4;
    u64 sc2[4][4];
    #pragma unroll
    for (int i = 0; i < 4; i++)
        #pragma unroll
        for (int j = 0; j < 4; j++) sc2[i][j] = 0ull;
    #pragma unroll 4
    for (int k4 = 0; k4 < 16; k4++) {
        ulonglong2 a2[4], b2[4];
        #pragma unroll
        for (int i = 0; i < 4; i++) a2[i] = *(const ulonglong2*)&Qr[(ty * 4 + i) * PW + k4 * 4];
        #pragma unroll
        for (int j = 0; j < 4; j++) b2[j] = *(const ulonglong2*)&Kc[(tx + 16 * j) * PW + k4 * 4];
        #pragma unroll
        for (int i = 0; i < 4; i++)
            #pragma unroll
            for (int j = 0; j < 4; j++) {
                sc2[i][j] = ffma2(a2[i].x, b2[j].x, sc2[i][j]);
                sc2[i][j] = ffma2(a2[i].y, b2[j].y, sc2[i][j]);
            }
    }
    __syncthreads();

    #pragma unroll
    for (int i = 0; i < 4; i++) {
        float sv[4];
        #pragma unroll
        for (int j = 0; j < 4; j++) sv[j] = pairsum(sc2[i][j]);
        float mx = fmaxf(fmaxf(sv[0], sv[1]), fmaxf(sv[2], sv[3]));
        #pragma unroll
        for (int o = 8; o; o >>= 1) mx = fmaxf(mx, __shfl_xor_sync(0xffffffffu, mx, o));
        float e[4], sm = 0.f;
        #pragma unroll
        for (int j = 0; j < 4; j++) { e[j] = __expf(sv[j] - mx); sm += e[j]; }
        #pragma unroll
        for (int o = 8; o; o >>= 1) sm += __shfl_xor_sync(0xffffffffu, sm, o);
        float inv = 1.f / sm;
        int row = ty * 4 + i;
        #pragma unroll
        for (int j = 0; j < 4; j++) {
            float p = e[j] * inv;
            Qr[row * PW + tx + 16 * j] = p;
            g_u[(bh * 64 + row) * 64 + tx + 16 * j] = p;
        }
    }
    __syncthreads();
    if (tid < 64) {
        float s = 0.f;
        #pragma unroll 8
        for (int i = 0; i < 64; i++) s += Qr[i * PW + tid];
        colsum[tid] = s;
    }
    __syncthreads();
    if (tid == 0) {
        float mx = colsum[0];
        for (int j = 1; j < 64; j++) mx = fmaxf(mx, colsum[j]);
        atomicMax(&g_gmax, __float_as_uint(mx));
    }
}

// ---------------- vectorized NN 64x64 matmul, pitch 64 ----------------
__device__ __forceinline__ void mm64v(const float* __restrict__ A,
                                      const float* __restrict__ Bm,
                                      float acc[4][4], int tx, int ty) {
    #pragma unroll
    for (int i = 0; i < 4; i++)
        #pragma unroll
        for (int j = 0; j < 4; j++) acc[i][j] = 0.f;
    #pragma unroll 2
    for (int k4 = 0; k4 < 16; k4++) {
        float4 a[4];
        #pragma unroll
        for (int i = 0; i < 4; i++) a[i] = *(const float4*)&A[(ty * 4 + i) * 64 + k4 * 4];
        #pragma unroll
        for (int kk = 0; kk < 4; kk++) {
            float4 bv = *(const float4*)&Bm[(k4 * 4 + kk) * 64 + tx * 4];
            float av[4];
            av[0] = (kk == 0) ? a[0].x : (kk == 1) ? a[0].y : (kk == 2) ? a[0].z : a[0].w;
            av[1] = (kk == 0) ? a[1].x : (kk == 1) ? a[1].y : (kk == 2) ? a[1].z : a[1].w;
            av[2] = (kk == 0) ? a[2].x : (kk == 1) ? a[2].y : (kk == 2) ? a[2].z : a[2].w;
            av[3] = (kk == 0) ? a[3].x : (kk == 1) ? a[3].y : (kk == 2) ? a[3].z : a[3].w;
            #pragma unroll
            for (int i = 0; i < 4; i++) {
                acc[i][0] = fmaf(av[i], bv.x, acc[i][0]);
                acc[i][1] = fmaf(av[i], bv.y, acc[i][1]);
                acc[i][2] = fmaf(av[i], bv.z, acc[i][2]);
                acc[i][3] = fmaf(av[i], bv.w, acc[i][3]);
            }
        }
    }
}

// ---------------- Newton-Schulz inverse -> g_Vinv ----------------
__global__ __launch_bounds__(256) void inv_kernel() {
    __shared__ float Vv[4096];
    __shared__ float A[4096];
    __shared__ float T[4096];

    int bh = blockIdx.x, tid = threadIdx.x;
    int tx = tid & 15, ty = tid >> 4;
    const float* Ug = g_u + (size_t)bh * 4096;
    float ginv = 1.f / __uint_as_float(g_gmax);

    for (int i = tid; i < 4096; i += 256) {
        int r = i >> 6, c = i & 63;
        Vv[r * 64 + c] = Ug[c * 64 + r] * ginv;
    }
    __syncthreads();

    float acc[4][4], t1[4][4];
    for (int it = 0; it < 6; ++it) {
        #pragma unroll
        for (int i = 0; i < 4; i++)
            #pragma unroll
            for (int j = 0; j < 4; j++) acc[i][j] = 0.f;
        #pragma unroll 2
        for (int k4 = 0; k4 < 16; k4++) {
            float4 a[4];
            #pragma unroll
            for (int i = 0; i < 4; i++)
                a[i] = *(const float4*)(Ug + (ty * 4 + i) * 64 + k4 * 4);
            #pragma unroll
            for (int kk = 0; kk < 4; kk++) {
                float4 bv = *(const float4*)&Vv[(k4 * 4 + kk) * 64 + tx * 4];
                float av[4];
                av[0] = (kk == 0) ? a[0].x : (kk == 1) ? a[0].y : (kk == 2) ? a[0].z : a[0].w;
                av[1] = (kk == 0) ? a[1].x : (kk == 1) ? a[1].y : (kk == 2) ? a[1].z : a[1].w;
                av[2] = (kk == 0) ? a[2].x : (kk == 1) ? a[2].y : (kk == 2) ? a[2].z : a[2].w;
                av[3] = (kk == 0) ? a[3].x : (kk == 1) ? a[3].y : (kk == 2) ? a[3].z : a[3].w;
                #pragma unroll
                for (int i = 0; i < 4; i++) {
                    acc[i][0] = fmaf(av[i], bv.x, acc[i][0]);
                    acc[i][1] = fmaf(av[i], bv.y, acc[i][1]);
                    acc[i][2] = fmaf(av[i], bv.z, acc[i][2]);
                    acc[i][3] = fmaf(av[i], bv.w, acc[i][3]);
                }
            }
        }
        __syncthreads();
        #pragma unroll
        for (int i = 0; i < 4; i++)
            #pragma unroll
            for (int j = 0; j < 4; j++) A[(ty * 4 + i) * 64 + tx * 4 + j] = acc[i][j];
        __syncthreads();

        mm64v(A, A, acc, tx, ty);
        #pragma unroll
        for (int i = 0; i < 4; i++)
            #pragma unroll
            for (int j = 0; j < 4; j++)
                t1[i][j] = 7.f * A[(ty * 4 + i) * 64 + tx * 4 + j] - acc[i][j];
        #pragma unroll
        for (int i = 0; i < 4; i++)
            #pragma unroll
            for (int j = 0; j < 4; j++) T[(ty * 4 + i) * 64 + tx * 4 + j] = t1[i][j];
        __syncthreads();

        mm64v(A, T, acc, tx, ty);
        #pragma unroll
        for (int i = 0; i < 4; i++)
            #pragma unroll
            for (int j = 0; j < 4; j++)
                t1[i][j] = 15.f * A[(ty * 4 + i) * 64 + tx * 4 + j] - acc[i][j];
        __syncthreads();
        #pragma unroll
        for (int i = 0; i < 4; i++)
            #pragma unroll
            for (int j = 0; j < 4; j++) T[(ty * 4 + i) * 64 + tx * 4 + j] = t1[i][j];
        __syncthreads();

        mm64v(Vv, T, acc, tx, ty);
        #pragma unroll
        for (int i = 0; i < 4; i++)
            #pragma unroll
            for (int j = 0; j < 4; j++)
                t1[i][j] = 0.25f * (13.f * Vv[(ty * 4 + i) * 64 + tx * 4 + j] - acc[i][j]);
        __syncthreads();
        #pragma unroll
        for (int i = 0; i < 4; i++)
            #pragma unroll
            for (int j = 0; j < 4; j++) Vv[(ty * 4 + i) * 64 + tx * 4 + j] = t1[i][j];
        __syncthreads();
    }

    for (int i = tid; i < 4096; i += 256)
        g_Vinv[(size_t)bh * 4096 + i] = Vv[i];
}

// ---------------- flash (tf32 mma): Y_partial = softmax_n(nr@K^T, mask) @ V ----
extern __shared__ float fsmem[];
__global__ __launch_bounds__(256) void flash_kernel(const float* __restrict__ Q,
                                                    const float* __restrict__ K,
                                                    const float* __restrict__ V,
                                                    const int* __restrict__ mask) {
    float* nr = fsmem;                 // [m][d]   64*PW
    float* Kt = nr + 64 * PW;          // [n][d]   64*PW
    float* VT = Kt + 64 * PW;          // [d][n]   64*PW (V transposed)
    float* P  = VT + 64 * PW;          // [m][n]   64*PW
    __shared__ float rmaxp[2][64];
    __shared__ float rsump[2][64];
    __shared__ int msk[64];
    __shared__ int ri_s[64];

    int bh = blockIdx.y, sp = blockIdx.x;
    int b = bh / Hv;
    const float* Qb = Q + (size_t)bh * Nv * Dv;
    const float* Kb = K + (size_t)bh * Nv * Dv;
    const float* Vb = V + (size_t)bh * Nv * Dv;

    int tid = threadIdx.x;
    int wid = tid >> 5, lane = tid & 31;
    int wm = wid & 3, wn = wid >> 2;
    int qr = lane >> 2, qc = lane & 3;
    int r0 = wm * 16 + qr, r1 = r0 + 8;

    if (tid < 64) ri_s[tid] = g_ridx[bh * Mv + tid];
    __syncthreads();
    for (int idx = tid; idx < 64 * 16; idx += 256) {
        int r = idx >> 4, c4 = (idx & 15) * 4;
        float4 q4 = *(const float4*)(Qb + (size_t)ri_s[r] * Dv + c4);
        q4.x *= 0.125f; q4.y *= 0.125f; q4.z *= 0.125f; q4.w *= 0.125f;
        *(float4*)&nr[r * PW + c4] = q4;
    }

    float o[4][4];
    #pragma unroll
    for (int nt = 0; nt < 4; nt++)
        #pragma unroll
        for (int j = 0; j < 4; j++) o[nt][j] = 0.f;
    float m0 = NEG_INF, m1 = NEG_INF, l0 = 0.f, l1 = 0.f;

    int base0 = sp * CHUNK;
    for (int t = 0; t < CHUNK / 64; t++) {
        int base = base0 + t * 64;
        __syncthreads();                               // Kt/VT/P free, nr ready (t=0)
        for (int idx = tid; idx < 64 * 16; idx += 256) {
            int r = idx >> 4, c4 = (idx & 15) * 4;
            *(float4*)&Kt[r * PW + c4] = *(const float4*)(Kb + (size_t)(base + r) * Dv + c4);
        }
        for (int idx = tid; idx < 64 * 16; idx += 256) {
            int r = idx & 63, c4 = (idx >> 6) * 4;
            float4 v = *(const float4*)(Vb + (size_t)(base + r) * Dv + c4);
            VT[(c4 + 0) * PW + r] = v.x;
            VT[(c4 + 1) * PW + r] = v.y;
            VT[(c4 + 2) * PW + r] = v.z;
            VT[(c4 + 3) * PW + r] = v.w;
        }
        if (tid < 64) msk[tid] = mask[b * Nv + base + tid];
        __syncthreads();

        // ---- S = nr @ Kt^T  (3xTF32) ----
        float s[4][4];
        #pragma unroll
        for (int nt = 0; nt < 4; nt++)
            #pragma unroll
            for (int j = 0; j < 4; j++) s[nt][j] = 0.f;
        #pragma unroll
        for (int k8 = 0; k8 < 8; k8++) {
            int kb = k8 * 8;
            unsigned ah[4], al[4];
            split_tf32(nr[r0 * PW + kb + qc],     ah[0], al[0]);
            split_tf32(nr[r1 * PW + kb + qc],     ah[1], al[1]);
            split_tf32(nr[r0 * PW + kb + 4 + qc], ah[2], al[2]);
            split_tf32(nr[r1 * PW + kb + 4 + qc], ah[3], al[3]);
            #pragma unroll
            for (int nt = 0; nt < 4; nt++) {
                int bn = wn * 32 + nt * 8 + qr;
                unsigned bh0, bl0, bh1, bl1;
                split_tf32(Kt[bn * PW + kb + qc],     bh0, bl0);
                split_tf32(Kt[bn * PW + kb + 4 + qc], bh1, bl1);
                mma3(s[nt], ah, al, bh0, bh1, bl0, bl1);
            }
        }

        // ---- mask + row max (quad + cross-warp) ----
        float rmA = NEG_INF, rmB = NEG_INF;
        #pragma unroll
        for (int nt = 0; nt < 4; nt++) {
            int c0 = wn * 32 + nt * 8 + 2 * qc, c1 = c0 + 1;
            if (!msk[c0]) { s[nt][0] = NEG_INF; s[nt][2] = NEG_INF; }
            if (!msk[c1]) { s[nt][1] = NEG_INF; s[nt][3] = NEG_INF; }
            rmA = fmaxf(rmA, fmaxf(s[nt][0], s[nt][1]));
            rmB = fmaxf(rmB, fmaxf(s[nt][2], s[nt][3]));
        }
        #pragma unroll
        for (int o2 = 1; o2 <= 2; o2 <<= 1) {
            rmA = fmaxf(rmA, __shfl_xor_sync(0xffffffffu, rmA, o2));
            rmB = fmaxf(rmB, __shfl_xor_sync(0xffffffffu, rmB, o2));
        }
        if (qc == 0) { rmaxp[wn][r0] = rmA; rmaxp[wn][r1] = rmB; }
        __syncthreads();

        // ---- online update, exp, P store, l update, o rescale ----
        float tmxA = fmaxf(rmaxp[0][r0], rmaxp[1][r0]);
        float tmxB = fmaxf(rmaxp[0][r1], rmaxp[1][r1]);
        float nmA = fmaxf(m0, tmxA), mcA = fmaxf(nmA, -1e30f);
        float nmB = fmaxf(m1, tmxB), mcB = fmaxf(nmB, -1e30f);
        float alA = __expf(m0 - mcA), alB = __expf(m1 - mcB);
        m0 = nmA; m1 = nmB;
        float tsA = 0.f, tsB = 0.f;
        #pragma unroll
        for (int nt = 0; nt < 4; nt++) {
            int c0 = wn * 32 + nt * 8 + 2 * qc;
            float p00 = __expf(s[nt][0] - mcA), p01 = __expf(s[nt][1] - mcA);
            float p10 = __expf(s[nt][2] - mcB), p11 = __expf(s[nt][3] - mcB);
            tsA += p00 + p01; tsB += p10 + p11;
            *(float2*)&P[r0 * PW + c0] = make_float2(p00, p01);
            *(float2*)&P[r1 * PW + c0] = make_float2(p10, p11);
        }
        #pragma unroll
        for (int o2 = 1; o2 <= 2; o2 <<= 1) {
            tsA += __shfl_xor_sync(0xffffffffu, tsA, o2);
            tsB += __shfl_xor_sync(0xffffffffu, tsB, o2);
        }
        l0 = l0 * alA + tsA;     // per-half l (this wn's 32 cols)
        l1 = l1 * alB + tsB;
        #pragma unroll
        for (int nt = 0; nt < 4; nt++) {
            o[nt][0] *= alA; o[nt][1] *= alA;
            o[nt][2] *= alB; o[nt][3] *= alB;
        }
        __syncthreads();                               // P complete

        // ---- O += P @ V  (3xTF32; B from transposed V) ----
        #pragma unroll
        for (int k8 = 0; k8 < 8; k8++) {
            int kb = k8 * 8;
            unsigned ah[4], al[4];
            split_tf32(P[r0 * PW + kb + qc],     ah[0], al[0]);
            split_tf32(P[r1 * PW + kb + qc],     ah[1], al[1]);
            split_tf32(P[r0 * PW + kb + 4 + qc], ah[2], al[2]);
            split_tf32(P[r1 * PW + kb + 4 + qc], ah[3], al[3]);
            #pragma unroll
            for (int nt = 0; nt < 4; nt++) {
                int dn = wn * 32 + nt * 8 + qr;
                unsigned bh0, bl0, bh1, bl1;
                split_tf32(VT[dn * PW + kb + qc],     bh0, bl0);
                split_tf32(VT[dn * PW + kb + 4 + qc], bh1, bl1);
                mma3(o[nt], ah, al, bh0, bh1, bl0, bl1);
            }
        }
    }

    // ---- epilogue: combine l halves, write m/l/Yp ----
    if (qc == 0) { rsump[wn][r0] = l0; rsump[wn][r1] = l1; }
    int idxbase = (bh * NSPLIT + sp) * 64;
    if (wn == 0 && qc == 0) {
        g_mx[idxbase + r0] = m0;
        g_mx[idxbase + r1] = m1;
    }
    __syncthreads();
    if (tid < 64) g_sm[idxbase + tid] = rsump[0][tid] + rsump[1][tid];
    #pragma unroll
    for (int nt = 0; nt < 4; nt++) {
        int c0 = wn * 32 + nt * 8 + 2 * qc;
        *(float2*)&g_Yp[((size_t)idxbase + r0) * 64 + c0] = make_float2(o[nt][0], o[nt][1]);
        *(float2*)&g_Yp[((size_t)idxbase + r1) * 64 + c0] = make_float2(o[nt][2], o[nt][3]);
    }
}

// ---------------- combine split partials into Y ----------------
__global__ __launch_bounds__(256) void combine_kernel() {
    int bh = blockIdx.x, tid = threadIdx.x;
    __shared__ float smx[64], ssum[64];
    if (tid < 64) {
        float mx = NEG_INF;
        for (int s = 0; s < NSPLIT; s++)
            mx = fmaxf(mx, g_mx[(bh * NSPLIT + s) * 64 + tid]);
        float mc = fmaxf(mx, -1e30f);
        float tot = 0.f;
        for (int s = 0; s < NSPLIT; s++)
            tot += __expf(g_mx[(bh * NSPLIT + s) * 64 + tid] - mc) *
                   g_sm[(bh * NSPLIT + s) * 64 + tid];
        smx[tid] = mc; ssum[tid] = tot;
    }
    __syncthreads();
    int m = tid >> 2, db = (tid & 3) * 16;
    float inv = 1.f / ssum[m];
    float acc[16];
    #pragma unroll
    for (int d = 0; d < 16; d++) acc[d] = 0.f;
    for (int s = 0; s < NSPLIT; s++) {
        float w = __expf(g_mx[(bh * NSPLIT + s) * 64 + m] - smx[m]);
        const float* yp = g_Yp + (((size_t)(bh * NSPLIT + s) * 64) + m) * 64 + db;
        #pragma unroll
        for (int d = 0; d < 16; d++) acc[d] += w * yp[d];
    }
    float* y = g_Y + ((size_t)bh * 64 + m) * 64 + db;
    #pragma unroll
    for (int d = 0; d < 16; d++) y[d] = acc[d] * inv;
}

// ---------------- Zt = (Vinv @ Y)^T ----------------
__global__ __launch_bounds__(256) void z_kernel() {
    __shared__ float Vv[4096];
    __shared__ float Ys[4096];
    int bh = blockIdx.x, tid = threadIdx.x;
    int tx = tid & 15, ty = tid >> 4;
    for (int i = tid; i < 4096; i += 256) {
        Vv[i] = g_Vinv[(size_t)bh * 4096 + i];
        Ys[i] = g_Y[(size_t)bh * 4096 + i];
    }
    __syncthreads();
    float acc[4][4];
    mm64v(Vv, Ys, acc, tx, ty);
    #pragma unroll
    for (int i = 0; i < 4; i++)
        #pragma unroll
        for (int j = 0; j < 4; j++)
            g_Zt[(size_t)bh * 4096 + (tx * 4 + j) * 64 + ty * 4 + i] = acc[i][j];
}

// ---------------- fused (tf32 mma): X = softmax(Qs @ nc^T) @ Z ----------------
extern __shared__ float xsmem[];
__global__ __launch_bounds__(256) void fx_kernel(const float* __restrict__ Q,
                                                 const float* __restrict__ K,
                                                 float* __restrict__ out) {
    float* ncs = xsmem;                // [m'][d] 64*PW
    float* qs  = ncs + 64 * PW;        // [n][d]  64*PW
    float* Zs  = qs + 64 * PW;         // [d][m'] 64*PW (Z transposed)
    float* P   = Zs + 64 * PW;         // [n][m'] 64*PW
    __shared__ float rmaxp[2][64];
    __shared__ float rsump[2][64];
    __shared__ int ci_s[64];

    int bh = blockIdx.y; int n0 = blockIdx.x * 64;
    const float* Kb = K + (size_t)bh * Nv * Dv;
    const float* Qb = Q + (size_t)bh * Nv * Dv;
    int tid = threadIdx.x;
    int wid = tid >> 5, lane = tid & 31;
    int wm = wid & 3, wn = wid >> 2;
    int qr = lane >> 2, qc = lane & 3;
    int r0 = wm * 16 + qr, r1 = r0 + 8;

    if (tid < 64) ci_s[tid] = g_cidx[bh * Mv + tid];
    __syncthreads();

    for (int idx = tid; idx < 64 * 16; idx += 256) {
        int r = idx >> 4, c4 = (idx & 15) * 4;
        float4 q4 = *(const float4*)(Qb + (size_t)(n0 + r) * Dv + c4);
        q4.x *= 0.125f; q4.y *= 0.125f; q4.z *= 0.125f; q4.w *= 0.125f;
        *(float4*)&qs[r * PW + c4] = q4;
        *(float4*)&ncs[r * PW + c4] = *(const float4*)(Kb + (size_t)ci_s[r] * Dv + c4);
        *(float4*)&Zs[r * PW + c4] = *(const float4*)(g_Zt + (size_t)bh * 4096 + r * 64 + c4);
    }
    __syncthreads();

    // ---- S = qs @ ncs^T (3xTF32) ----
    float s[4][4];
    #pragma unroll
    for (int nt = 0; nt < 4; nt++)
        #pragma unroll
        for (int j = 0; j < 4; j++) s[nt][j] = 0.f;
    #pragma unroll
    for (int k8 = 0; k8 < 8; k8++) {
        int kb = k8 * 8;
        unsigned ah[4], al[4];
        split_tf32(qs[r0 * PW + kb + qc],     ah[0], al[0]);
        split_tf32(qs[r1 * PW + kb + qc],     ah[1], al[1]);
        split_tf32(qs[r0 * PW + kb + 4 + qc], ah[2], al[2]);
        split_tf32(qs[r1 * PW + kb + 4 + qc], ah[3], al[3]);
        #pragma unroll
        for (int nt = 0; nt < 4; nt++) {
            int bn = wn * 32 + nt * 8 + qr;
            unsigned bh0, bl0, bh1, bl1;
            split_tf32(ncs[bn * PW + kb + qc],     bh0, bl0);
            split_tf32(ncs[bn * PW + kb + 4 + qc], bh1, bl1);
            mma3(s[nt], ah, al, bh0, bh1, bl0, bl1);
        }
    }

    // ---- row max ----
    float rmA = NEG_INF, rmB = NEG_INF;
    #pragma unroll
    for (int nt = 0; nt < 4; nt++) {
        rmA = fmaxf(rmA, fmaxf(s[nt][0], s[nt][1]));
        rmB = fmaxf(rmB, fmaxf(s[nt][2], s[nt][3]));
    }
    #pragma unroll
    for (int o2 = 1; o2 <= 2; o2 <<= 1) {
        rmA = fmaxf(rmA, __shfl_xor_sync(0xffffffffu, rmA, o2));
        rmB = fmaxf(rmB, __shfl_xor_sync(0xffffffffu, rmB, o2));
    }
    if (qc == 0) { rmaxp[wn][r0] = rmA; rmaxp[wn][r1] = rmB; }
    __syncthreads();

    // ---- exp (unnormalized), P store, row sums ----
    float mcA = fmaxf(rmaxp[0][r0], rmaxp[1][r0]);
    float mcB = fmaxf(rmaxp[0][r1], rmaxp[1][r1]);
    float tsA = 0.f, tsB = 0.f;
    #pragma unroll
    for (int nt = 0; nt < 4; nt++) {
        int c0 = wn * 32 + nt * 8 + 2 * qc;
        float p00 = __expf(s[nt][0] - mcA), p01 = __expf(s[nt][1] - mcA);
        float p10 = __expf(s[nt][2] - mcB), p11 = __expf(s[nt][3] - mcB);
        tsA += p00 + p01; tsB += p10 + p11;
        *(float2*)&P[r0 * PW + c0] = make_float2(p00, p01);
        *(float2*)&P[r1 * PW + c0] = make_float2(p10, p11);
    }
    #pragma unroll
    for (int o2 = 1; o2 <= 2; o2 <<= 1) {
        tsA += __shfl_xor_sync(0xffffffffu, tsA, o2);
        tsB += __shfl_xor_sync(0xffffffffu, tsB, o2);
    }
    if (qc == 0) { rsump[wn][r0] = tsA; rsump[wn][r1] = tsB; }
    __syncthreads();                                   // P + sums complete

    // ---- X = P @ Z (3xTF32), normalize at store ----
    float o[4][4];
    #pragma unroll
    for (int nt = 0; nt < 4; nt++)
        #pragma unroll
        for (int j = 0; j < 4; j++) o[nt][j] = 0.f;
    #pragma unroll
    for (int k8 = 0; k8 < 8; k8++) {
        int kb = k8 * 8;
        unsigned ah[4], al[4];
        split_tf32(P[r0 * PW + kb + qc],     ah[0], al[0]);
        split_tf32(P[r1 * PW + kb + qc],     ah[1], al[1]);
        split_tf32(P[r0 * PW + kb + 4 + qc], ah[2], al[2]);
        split_tf32(P[r1 * PW + kb + 4 + qc], ah[3], al[3]);
        #pragma unroll
        for (int nt = 0; nt < 4; nt++) {
            int dn = wn * 32 + nt * 8 + qr;
            unsigned bh0, bl0, bh1, bl1;
            split_tf32(Zs[dn * PW + kb + qc],     bh0, bl0);
            split_tf32(Zs[dn * PW + kb + 4 + qc], bh1, bl1);
            mma3(o[nt], ah, al, bh0, bh1, bl0, bl1);
        }
    }
    float invA = 1.f / (rsump[0][r0] + rsump[1][r0]);
    float invB = 1.f / (rsump[0][r1] + rsump[1][r1]);
    #pragma unroll
    for (int nt = 0; nt < 4; nt++) {
        int c0 = wn * 32 + nt * 8 + 2 * qc;
        *(float2*)(out + ((size_t)bh * Nv + n0 + r0) * Dv + c0) =
            make_float2(o[nt][0] * invA, o[nt][1] * invA);
        *(float2*)(out + ((size_t)bh * Nv + n0 + r1) * Dv + c0) =
            make_float2(o[nt][2] * invB, o[nt][3] * invB);
    }
}

// ---------------- launch ----------------
extern "C" void kernel_launch(void* const* d_in, const int* in_sizes, int n_in,
                              void* d_out, int out_size) {
    (void)in_sizes; (void)n_in; (void)out_size;
    const float* Q    = (const float*)d_in[0];
    const float* K    = (const float*)d_in[1];
    const float* V    = (const float*)d_in[2];
    const int*   mask = (const int*)d_in[3];
    float* out = (float*)d_out;

    const int FLASH_SMEM = 4 * 64 * PW * (int)sizeof(float);   // 69632
    const int FX_SMEM    = 4 * 64 * PW * (int)sizeof(float);   // 69632
    cudaFuncSetAttribute(flash_kernel, cudaFuncAttributeMaxDynamicSharedMemorySize, FLASH_SMEM);
    cudaFuncSetAttribute(fx_kernel, cudaFuncAttributeMaxDynamicSharedMemorySize, FX_SMEM);

    cudaStream_t s2;
    cudaEvent_t evA, evB;
    cudaStreamCreateWithFlags(&s2, cudaStreamNonBlocking);
    cudaEventCreateWithFlags(&evA, cudaEventDisableTiming);
    cudaEventCreateWithFlags(&evB, cudaEventDisableTiming);

    init_kernel<<<1, 1>>>();
    select_kernel<<<dim3(BH, 2), 256>>>(K, Q, mask);
    cudaEventRecord(evA, 0);

    // side stream: u -> Newton inverse (overlaps flash)
    cudaStreamWaitEvent(s2, evA, 0);
    u_kernel<<<BH, 256, 0, s2>>>(Q, K);
    inv_kernel<<<BH, 256, 0, s2>>>();
    cudaEventRecord(evB, s2);

    // main stream: flash + combine
    flash_kernel<<<dim3(NSPLIT, BH), 256, FLASH_SMEM>>>(Q, K, V, mask);
    combine_kernel<<<BH, 256>>>();

    cudaStreamWaitEvent(0, evB, 0);
    z_kernel<<<BH, 256>>>();
    fx_kernel<<<dim3(Nv / 64, BH), 256, FX_SMEM>>>(Q, K, out);
}

// round 7
// speedup vs baseline: 1.7207x; 1.1288x over previous
#include <cuda_runtime.h>
#include <float.h>

#define Bv 4
#define Hv 8
#define BH 32
#define Nv 4096
#define Dv 64
#define Mv 64
#define NSPLIT 32
#define CHUNK 128
#define PW 68              // pitch (words): bank = (4*row + col) mod 32 -> conflict-free frags

#define NEG_INF __int_as_float(0xff800000)

typedef unsigned long long u64;

// ---- packed f32x2 helpers (used by u_kernel) ----
__device__ __forceinline__ u64 ffma2(u64 a, u64 b, u64 c) {
    u64 d;
    asm("fma.rn.f32x2 %0, %1, %2, %3;" : "=l"(d) : "l"(a), "l"(b), "l"(c));
    return d;
}
__device__ __forceinline__ float pairsum(u64 v) {
    unsigned lo, hi;
    asm("mov.b64 {%0, %1}, %2;" : "=r"(lo), "=r"(hi) : "l"(v));
    return __uint_as_float(lo) + __uint_as_float(hi);
}

// ---- tf32 mma helpers ----
__device__ __forceinline__ unsigned cvt_tf32(float x) {
    unsigned u;
    asm("cvt.rna.tf32.f32 %0, %1;" : "=r"(u) : "f"(x));
    return u;
}
__device__ __forceinline__ void split_tf32(float x, unsigned& hi, unsigned& lo) {
    hi = cvt_tf32(x);
    lo = cvt_tf32(x - __uint_as_float(hi));
}
__device__ __forceinline__ void mma8(float c[4], const unsigned a[4], unsigned b0, unsigned b1) {
    asm("mma.sync.aligned.m16n8k8.row.col.f32.tf32.tf32.f32 "
        "{%0,%1,%2,%3},{%4,%5,%6,%7},{%8,%9},{%0,%1,%2,%3};"
        : "+f"(c[0]), "+f"(c[1]), "+f"(c[2]), "+f"(c[3])
        : "r"(a[0]), "r"(a[1]), "r"(a[2]), "r"(a[3]), "r"(b0), "r"(b1));
}
__device__ __forceinline__ void mma3(float c[4], const unsigned ah[4], const unsigned al[4],
                                     unsigned bh0, unsigned bh1, unsigned bl0, unsigned bl1) {
    mma8(c, ah, bh0, bh1);
    mma8(c, ah, bl0, bl1);
    mma8(c, al, bh0, bh1);
}

// 64x64x64 3xTF32 GEMM: C = Arow @ Bt^T, Arow [m][k] pitch PW, Bt [n][k] pitch PW
__device__ __forceinline__ void gemm3(const float* __restrict__ Arow, const float* __restrict__ Bt,
                                      float c[4][4], int wn, int r0, int r1, int qr, int qc) {
    #pragma unroll
    for (int nt = 0; nt < 4; nt++) { c[nt][0] = c[nt][1] = c[nt][2] = c[nt][3] = 0.f; }
    #pragma unroll
    for (int k8 = 0; k8 < 8; k8++) {
        int kb = k8 * 8;
        unsigned ah[4], al[4];
        split_tf32(Arow[r0 * PW + kb + qc],     ah[0], al[0]);
        split_tf32(Arow[r1 * PW + kb + qc],     ah[1], al[1]);
        split_tf32(Arow[r0 * PW + kb + 4 + qc], ah[2], al[2]);
        split_tf32(Arow[r1 * PW + kb + 4 + qc], ah[3], al[3]);
        #pragma unroll
        for (int nt = 0; nt < 4; nt++) {
            int bn = wn * 32 + nt * 8 + qr;
            unsigned bh0, bl0, bh1, bl1;
            split_tf32(Bt[bn * PW + kb + qc],     bh0, bl0);
            split_tf32(Bt[bn * PW + kb + 4 + qc], bh1, bl1);
            mma3(c[nt], ah, al, bh0, bh1, bl0, bl1);
        }
    }
}

// ---------------- scratch ----------------
__device__ int   g_cidx[BH * Mv];
__device__ int   g_ridx[BH * Mv];
__device__ float g_u[BH * Mv * Mv];
__device__ float g_Vinv[BH * Mv * Mv];
__device__ float g_Yp[(size_t)BH * NSPLIT * Mv * Dv];
__device__ float g_mx[BH * NSPLIT * Mv];
__device__ float g_sm[BH * NSPLIT * Mv];
__device__ float g_Zt[BH * Mv * Dv];      // Z transposed: [bh][d][m]
__device__ unsigned int g_gmax;

__global__ void init_kernel() { g_gmax = 0u; }

// ---------------- top-k selection ----------------
__global__ __launch_bounds__(256) void select_kernel(const float* __restrict__ Kp,
                                                     const float* __restrict__ Qp,
                                                     const int* __restrict__ mask) {
    int bh = blockIdx.x;
    int b = bh / Hv;
    const float* T = (blockIdx.y == 0) ? Kp : Qp;
    int* outIdx = (blockIdx.y == 0) ? g_cidx : g_ridx;

    __shared__ float s[Nv];
    __shared__ float cmax[16];
    __shared__ int   cidx[16];
    __shared__ int   picked[Mv];

    int tid = threadIdx.x;
    int warp = tid >> 5, lane = tid & 31;
    const float* Tb = T + (size_t)bh * Nv * Dv;

    // row sums: half-warp per row (float4 + 4-deep shfl)
    for (int i = warp; i < 2048; i += 8) {
        int r = i * 2 + (lane >> 4);
        int l16 = lane & 15;
        float4 v4 = *(const float4*)(Tb + (size_t)r * Dv + l16 * 4);
        float v = (v4.x + v4.y) + (v4.z + v4.w);
        #pragma unroll
        for (int o = 1; o <= 8; o <<= 1) v += __shfl_xor_sync(0xffffffffu, v, o);
        if (l16 == 0) {
            bool bad = (r == 0) || (mask[b * Nv + r] != 0);
            s[r] = bad ? -FLT_MAX : v;
        }
    }
    __syncthreads();

    for (int c = warp; c < 16; c += 8) {
        float bv = -FLT_MAX; int bi = Nv;
        #pragma unroll
        for (int t = 0; t < 8; t++) {
            int idx = c * 256 + lane + 32 * t;
            float v = s[idx];
            if (v > bv || (v == bv && idx < bi)) { bv = v; bi = idx; }
        }
        #pragma unroll
        for (int o = 16; o; o >>= 1) {
            float ov = __shfl_xor_sync(0xffffffffu, bv, o);
            int   oi = __shfl_xor_sync(0xffffffffu, bi, o);
            if (ov > bv || (ov == bv && oi < bi)) { bv = ov; bi = oi; }
        }
        if (lane == 0) { cmax[c] = bv; cidx[c] = bi; }
    }
    __syncthreads();

    if (warp == 0) {
        for (int it = 0; it < Mv - 1; ++it) {
            float bv = (lane < 16) ? cmax[lane] : -FLT_MAX;
            int   bi = (lane < 16) ? cidx[lane] : Nv;
            #pragma unroll
            for (int o = 16; o; o >>= 1) {
                float ov = __shfl_xor_sync(0xffffffffu, bv, o);
                int   oi = __shfl_xor_sync(0xffffffffu, bi, o);
                if (ov > bv || (ov == bv && oi < bi)) { bv = ov; bi = oi; }
            }
            int gidx = __shfl_sync(0xffffffffu, bi, 0);
            if (lane == 0) { picked[it] = gidx; s[gidx] = -FLT_MAX; }
            __syncwarp();
            int c = gidx >> 8;
            float nv = -FLT_MAX; int ni = Nv;
            #pragma unroll
            for (int t = 0; t < 8; t++) {
                int idx = c * 256 + lane + 32 * t;
                float v = s[idx];
                if (v > nv || (v == nv && idx < ni)) { nv = v; ni = idx; }
            }
            #pragma unroll
            for (int o = 16; o; o >>= 1) {
                float ov = __shfl_xor_sync(0xffffffffu, nv, o);
                int   oi = __shfl_xor_sync(0xffffffffu, ni, o);
                if (ov > nv || (ov == nv && oi < ni)) { nv = ov; ni = oi; }
            }
            if (lane == 0) { cmax[c] = nv; cidx[c] = ni; }
            __syncwarp();
        }
        if (lane == 0) picked[Mv - 1] = 0;
    }
    __syncthreads();

    if (tid < Mv) {
        int key = picked[tid];
        int rank = 0;
        #pragma unroll 16
        for (int j = 0; j < Mv; j++) rank += (picked[j] < key);
        outIdx[bh * Mv + rank] = key;
    }
}

// ---------------- u = softmax(Qs[ridx] @ nc^T) + global colsum-max ----------
__global__ __launch_bounds__(256) void u_kernel(const float* __restrict__ Q,
                                                const float* __restrict__ K) {
    int bh = blockIdx.x;
    __shared__ float Kc[64 * PW];
    __shared__ float Qr[64 * PW];
    __shared__ float colsum[64];
    __shared__ int ci_s[64], ri_s[64];

    const float* Kb = K + (size_t)bh * Nv * Dv;
    const float* Qb = Q + (size_t)bh * Nv * Dv;
    int tid = threadIdx.x;
    if (tid < 64) { ci_s[tid] = g_cidx[bh * Mv + tid]; ri_s[tid] = g_ridx[bh * Mv + tid]; }
    __syncthreads();

    for (int idx = tid; idx < 64 * 16; idx += 256) {
        int r = idx >> 4, c4 = (idx & 15) * 4;
        float4 q4 = *(const float4*)(Qb + (size_t)ri_s[r] * Dv + c4);
        q4.x *= 0.125f; q4.y *= 0.125f; q4.z *= 0.125f; q4.w *= 0.125f;
        *(float4*)&Qr[r * PW + c4] = q4;
        *(float4*)&Kc[r * PW + c4] = *(const float4*)(Kb + (size_t)ci_s[r] * Dv + c4);
    }
    __syncthreads();

    int tx = tid & 15, ty = tid >> 4;
    u64 sc2[4][4];
    #pragma unroll
    for (int i = 0; i < 4; i++)
        #pragma unroll
        for (int j = 0; j < 4; j++) sc2[i][j] = 0ull;
    #pragma unroll 4
    for (int k4 = 0; k4 < 16; k4++) {
        ulonglong2 a2[4], b2[4];
        #pragma unroll
        for (int i = 0; i < 4; i++) a2[i] = *(const ulonglong2*)&Qr[(ty * 4 + i) * PW + k4 * 4];
        #pragma unroll
        for (int j = 0; j < 4; j++) b2[j] = *(const ulonglong2*)&Kc[(tx + 16 * j) * PW + k4 * 4];
        #pragma unroll
        for (int i = 0; i < 4; i++)
            #pragma unroll
            for (int j = 0; j < 4; j++) {
                sc2[i][j] = ffma2(a2[i].x, b2[j].x, sc2[i][j]);
                sc2[i][j] = ffma2(a2[i].y, b2[j].y, sc2[i][j]);
            }
    }
    __syncthreads();

    #pragma unroll
    for (int i = 0; i < 4; i++) {
        float sv[4];
        #pragma unroll
        for (int j = 0; j < 4; j++) sv[j] = pairsum(sc2[i][j]);
        float mx = fmaxf(fmaxf(sv[0], sv[1]), fmaxf(sv[2], sv[3]));
        #pragma unroll
        for (int o = 8; o; o >>= 1) mx = fmaxf(mx, __shfl_xor_sync(0xffffffffu, mx, o));
        float e[4], sm = 0.f;
        #pragma unroll
        for (int j = 0; j < 4; j++) { e[j] = __expf(sv[j] - mx); sm += e[j]; }
        #pragma unroll
        for (int o = 8; o; o >>= 1) sm += __shfl_xor_sync(0xffffffffu, sm, o);
        float inv = 1.f / sm;
        int row = ty * 4 + i;
        #pragma unroll
        for (int j = 0; j < 4; j++) {
            float p = e[j] * inv;
            Qr[row * PW + tx + 16 * j] = p;
            g_u[(bh * 64 + row) * 64 + tx + 16 * j] = p;
        }
    }
    __syncthreads();
    if (tid < 64) {
        float s = 0.f;
        #pragma unroll 8
        for (int i = 0; i < 64; i++) s += Qr[i * PW + tid];
        colsum[tid] = s;
    }
    __syncthreads();
    if (tid == 0) {
        float mx = colsum[0];
        for (int j = 1; j < 64; j++) mx = fmaxf(mx, colsum[j]);
        atomicMax(&g_gmax, __float_as_uint(mx));
    }
}

// ---------------- vectorized NN 64x64 matmul, pitch 64 (combine_z epilogue) ----
__device__ __forceinline__ void mm64v(const float* __restrict__ A,
                                      const float* __restrict__ Bm,
                                      float acc[4][4], int tx, int ty) {
    #pragma unroll
    for (int i = 0; i < 4; i++)
        #pragma unroll
        for (int j = 0; j < 4; j++) acc[i][j] = 0.f;
    #pragma unroll 2
    for (int k4 = 0; k4 < 16; k4++) {
        float4 a[4];
        #pragma unroll
        for (int i = 0; i < 4; i++) a[i] = *(const float4*)&A[(ty * 4 + i) * 64 + k4 * 4];
        #pragma unroll
        for (int kk = 0; kk < 4; kk++) {
            float4 bv = *(const float4*)&Bm[(k4 * 4 + kk) * 64 + tx * 4];
            float av[4];
            av[0] = (kk == 0) ? a[0].x : (kk == 1) ? a[0].y : (kk == 2) ? a[0].z : a[0].w;
            av[1] = (kk == 0) ? a[1].x : (kk == 1) ? a[1].y : (kk == 2) ? a[1].z : a[1].w;
            av[2] = (kk == 0) ? a[2].x : (kk == 1) ? a[2].y : (kk == 2) ? a[2].z : a[2].w;
            av[3] = (kk == 0) ? a[3].x : (kk == 1) ? a[3].y : (kk == 2) ? a[3].z : a[3].w;
            #pragma unroll
            for (int i = 0; i < 4; i++) {
                acc[i][0] = fmaf(av[i], bv.x, acc[i][0]);
                acc[i][1] = fmaf(av[i], bv.y, acc[i][1]);
                acc[i][2] = fmaf(av[i], bv.z, acc[i][2]);
                acc[i][3] = fmaf(av[i], bv.w, acc[i][3]);
            }
        }
    }
}

// ---------------- Newton-Schulz inverse (3xTF32 mma) -> g_Vinv ----------------
extern __shared__ float invsm[];
__global__ __launch_bounds__(256) void inv_kernel() {
    float* Us  = invsm;               // [m][k]
    float* Vr  = Us  + 64 * PW;       // V row form [m][k]
    float* Vt  = Vr  + 64 * PW;       // V transposed [n][k]
    float* Ar  = Vt  + 64 * PW;       // A row
    float* At  = Ar  + 64 * PW;       // A transposed
    float* Tt  = At  + 64 * PW;       // T transposed
    float* T2t = Tt  + 64 * PW;       // T2 transposed

    int bh = blockIdx.x, tid = threadIdx.x;
    int wid = tid >> 5, lane = tid & 31;
    int wm = wid & 3, wn = wid >> 2;
    int qr = lane >> 2, qc = lane & 3;
    int r0 = wm * 16 + qr, r1 = r0 + 8;

    const float* Ug = g_u + (size_t)bh * 4096;
    float ginv = 1.f / __uint_as_float(g_gmax);

    // Us = U; Vt = U*ginv (V^T row form == U); Vr = transpose(Vt)
    for (int idx = tid; idx < 1024; idx += 256) {
        int r = idx >> 4, c4 = (idx & 15) * 4;
        float4 u4 = *(const float4*)(Ug + r * 64 + c4);
        *(float4*)&Us[r * PW + c4] = u4;
        float4 s4 = make_float4(u4.x * ginv, u4.y * ginv, u4.z * ginv, u4.w * ginv);
        *(float4*)&Vt[r * PW + c4] = s4;
        Vr[(c4 + 0) * PW + r] = s4.x;
        Vr[(c4 + 1) * PW + r] = s4.y;
        Vr[(c4 + 2) * PW + r] = s4.z;
        Vr[(c4 + 3) * PW + r] = s4.w;
    }
    __syncthreads();

    float c1[4][4], cw[4][4];
    for (int it = 0; it < 6; it++) {
        // A = U @ V
        gemm3(Us, Vt, c1, wn, r0, r1, qr, qc);
        #pragma unroll
        for (int nt = 0; nt < 4; nt++) {
            int c0 = wn * 32 + nt * 8 + 2 * qc;
            Ar[r0 * PW + c0] = c1[nt][0]; Ar[r0 * PW + c0 + 1] = c1[nt][1];
            Ar[r1 * PW + c0] = c1[nt][2]; Ar[r1 * PW + c0 + 1] = c1[nt][3];
            At[c0 * PW + r0] = c1[nt][0]; At[(c0 + 1) * PW + r0] = c1[nt][1];
            At[c0 * PW + r1] = c1[nt][2]; At[(c0 + 1) * PW + r1] = c1[nt][3];
        }
        __syncthreads();

        // T = 7A - A@A
        gemm3(Ar, At, cw, wn, r0, r1, qr, qc);
        #pragma unroll
        for (int nt = 0; nt < 4; nt++) {
            int c0 = wn * 32 + nt * 8 + 2 * qc;
            Tt[c0 * PW + r0]       = 7.f * c1[nt][0] - cw[nt][0];
            Tt[(c0 + 1) * PW + r0] = 7.f * c1[nt][1] - cw[nt][1];
            Tt[c0 * PW + r1]       = 7.f * c1[nt][2] - cw[nt][2];
            Tt[(c0 + 1) * PW + r1] = 7.f * c1[nt][3] - cw[nt][3];
        }
        __syncthreads();

        // T2 = 15A - A@T
        gemm3(Ar, Tt, cw, wn, r0, r1, qr, qc);
        #pragma unroll
        for (int nt = 0; nt < 4; nt++) {
            int c0 = wn * 32 + nt * 8 + 2 * qc;
            T2t[c0 * PW + r0]       = 15.f * c1[nt][0] - cw[nt][0];
            T2t[(c0 + 1) * PW + r0] = 15.f * c1[nt][1] - cw[nt][1];
            T2t[c0 * PW + r1]       = 15.f * c1[nt][2] - cw[nt][2];
            T2t[(c0 + 1) * PW + r1] = 15.f * c1[nt][3] - cw[nt][3];
        }
        __syncthreads();

        // V = 0.25*(13V - V@T2)
        gemm3(Vr, T2t, cw, wn, r0, r1, qr, qc);
        __syncthreads();                                  // all Vr reads done
        #pragma unroll
        for (int nt = 0; nt < 4; nt++) {
            int c0 = wn * 32 + nt * 8 + 2 * qc;
            float v00 = Vr[r0 * PW + c0], v01 = Vr[r0 * PW + c0 + 1];
            float v10 = Vr[r1 * PW + c0], v11 = Vr[r1 * PW + c0 + 1];
            float n00 = 0.25f * (13.f * v00 - cw[nt][0]);
            float n01 = 0.25f * (13.f * v01 - cw[nt][1]);
            float n10 = 0.25f * (13.f * v10 - cw[nt][2]);
            float n11 = 0.25f * (13.f * v11 - cw[nt][3]);
            Vr[r0 * PW + c0] = n00; Vr[r0 * PW + c0 + 1] = n01;
            Vr[r1 * PW + c0] = n10; Vr[r1 * PW + c0 + 1] = n11;
            Vt[c0 * PW + r0] = n00; Vt[(c0 + 1) * PW + r0] = n01;
            Vt[c0 * PW + r1] = n10; Vt[(c0 + 1) * PW + r1] = n11;
        }
        __syncthreads();
    }

    for (int idx = tid; idx < 1024; idx += 256) {
        int r = idx >> 4, c4 = (idx & 15) * 4;
        *(float4*)(g_Vinv + (size_t)bh * 4096 + r * 64 + c4) = *(float4*)&Vr[r * PW + c4];
    }
}

// ---------------- flash (tf32 mma): Y_partial = softmax_n(nr@K^T, mask) @ V ----
extern __shared__ float fsmem[];
__global__ __launch_bounds__(256) void flash_kernel(const float* __restrict__ Q,
                                                    const float* __restrict__ K,
                                                    const float* __restrict__ V,
                                                    const int* __restrict__ mask) {
    float* nr = fsmem;                 // [m][d]   64*PW
    float* Kt = nr + 64 * PW;          // [n][d]   64*PW
    float* VT = Kt + 64 * PW;          // [d][n]   64*PW (V transposed)
    float* P  = VT + 64 * PW;          // [m][n]   64*PW
    __shared__ float rmaxp[2][64];
    __shared__ float rsump[2][64];
    __shared__ int msk[64];
    __shared__ int ri_s[64];

    int bh = blockIdx.y, sp = blockIdx.x;
    int b = bh / Hv;
    const float* Qb = Q + (size_t)bh * Nv * Dv;
    const float* Kb = K + (size_t)bh * Nv * Dv;
    const float* Vb = V + (size_t)bh * Nv * Dv;

    int tid = threadIdx.x;
    int wid = tid >> 5, lane = tid & 31;
    int wm = wid & 3, wn = wid >> 2;
    int qr = lane >> 2, qc = lane & 3;
    int r0 = wm * 16 + qr, r1 = r0 + 8;

    if (tid < 64) ri_s[tid] = g_ridx[bh * Mv + tid];
    __syncthreads();
    for (int idx = tid; idx < 64 * 16; idx += 256) {
        int r = idx >> 4, c4 = (idx & 15) * 4;
        float4 q4 = *(const float4*)(Qb + (size_t)ri_s[r] * Dv + c4);
        q4.x *= 0.125f; q4.y *= 0.125f; q4.z *= 0.125f; q4.w *= 0.125f;
        *(float4*)&nr[r * PW + c4] = q4;
    }

    float o[4][4];
    #pragma unroll
    for (int nt = 0; nt < 4; nt++)
        #pragma unroll
        for (int j = 0; j < 4; j++) o[nt][j] = 0.f;
    float m0 = NEG_INF, m1 = NEG_INF, l0 = 0.f, l1 = 0.f;

    int base0 = sp * CHUNK;
    for (int t = 0; t < CHUNK / 64; t++) {
        int base = base0 + t * 64;
        __syncthreads();
        for (int idx = tid; idx < 64 * 16; idx += 256) {
            int r = idx >> 4, c4 = (idx & 15) * 4;
            *(float4*)&Kt[r * PW + c4] = *(const float4*)(Kb + (size_t)(base + r) * Dv + c4);
        }
        for (int idx = tid; idx < 64 * 16; idx += 256) {
            int r = idx & 63, c4 = (idx >> 6) * 4;
            float4 v = *(const float4*)(Vb + (size_t)(base + r) * Dv + c4);
            VT[(c4 + 0) * PW + r] = v.x;
            VT[(c4 + 1) * PW + r] = v.y;
            VT[(c4 + 2) * PW + r] = v.z;
            VT[(c4 + 3) * PW + r] = v.w;
        }
        if (tid < 64) msk[tid] = mask[b * Nv + base + tid];
        __syncthreads();

        // ---- S = nr @ Kt^T  (3xTF32) ----
        float s[4][4];
        #pragma unroll
        for (int nt = 0; nt < 4; nt++)
            #pragma unroll
            for (int j = 0; j < 4; j++) s[nt][j] = 0.f;
        #pragma unroll
        for (int k8 = 0; k8 < 8; k8++) {
            int kb = k8 * 8;
            unsigned ah[4], al[4];
            split_tf32(nr[r0 * PW + kb + qc],     ah[0], al[0]);
            split_tf32(nr[r1 * PW + kb + qc],     ah[1], al[1]);
            split_tf32(nr[r0 * PW + kb + 4 + qc], ah[2], al[2]);
            split_tf32(nr[r1 * PW + kb + 4 + qc], ah[3], al[3]);
            #pragma unroll
            for (int nt = 0; nt < 4; nt++) {
                int bn = wn * 32 + nt * 8 + qr;
                unsigned bh0, bl0, bh1, bl1;
                split_tf32(Kt[bn * PW + kb + qc],     bh0, bl0);
                split_tf32(Kt[bn * PW + kb + 4 + qc], bh1, bl1);
                mma3(s[nt], ah, al, bh0, bh1, bl0, bl1);
            }
        }

        // ---- mask + row max ----
        float rmA = NEG_INF, rmB = NEG_INF;
        #pragma unroll
        for (int nt = 0; nt < 4; nt++) {
            int c0 = wn * 32 + nt * 8 + 2 * qc, c1c = c0 + 1;
            if (!msk[c0])  { s[nt][0] = NEG_INF; s[nt][2] = NEG_INF; }
            if (!msk[c1c]) { s[nt][1] = NEG_INF; s[nt][3] = NEG_INF; }
            rmA = fmaxf(rmA, fmaxf(s[nt][0], s[nt][1]));
            rmB = fmaxf(rmB, fmaxf(s[nt][2], s[nt][3]));
        }
        #pragma unroll
        for (int o2 = 1; o2 <= 2; o2 <<= 1) {
            rmA = fmaxf(rmA, __shfl_xor_sync(0xffffffffu, rmA, o2));
            rmB = fmaxf(rmB, __shfl_xor_sync(0xffffffffu, rmB, o2));
        }
        if (qc == 0) { rmaxp[wn][r0] = rmA; rmaxp[wn][r1] = rmB; }
        __syncthreads();

        // ---- online update, exp, P store, l update, o rescale ----
        float tmxA = fmaxf(rmaxp[0][r0], rmaxp[1][r0]);
        float tmxB = fmaxf(rmaxp[0][r1], rmaxp[1][r1]);
        float nmA = fmaxf(m0, tmxA), mcA = fmaxf(nmA, -1e30f);
        float nmB = fmaxf(m1, tmxB), mcB = fmaxf(nmB, -1e30f);
        float alA = __expf(m0 - mcA), alB = __expf(m1 - mcB);
        m0 = nmA; m1 = nmB;
        float tsA = 0.f, tsB = 0.f;
        #pragma unroll
        for (int nt = 0; nt < 4; nt++) {
            int c0 = wn * 32 + nt * 8 + 2 * qc;
            float p00 = __expf(s[nt][0] - mcA), p01 = __expf(s[nt][1] - mcA);
            float p10 = __expf(s[nt][2] - mcB), p11 = __expf(s[nt][3] - mcB);
            tsA += p00 + p01; tsB += p10 + p11;
            *(float2*)&P[r0 * PW + c0] = make_float2(p00, p01);
            *(float2*)&P[r1 * PW + c0] = make_float2(p10, p11);
        }
        #pragma unroll
        for (int o2 = 1; o2 <= 2; o2 <<= 1) {
            tsA += __shfl_xor_sync(0xffffffffu, tsA, o2);
            tsB += __shfl_xor_sync(0xffffffffu, tsB, o2);
        }
        l0 = l0 * alA + tsA;
        l1 = l1 * alB + tsB;
        #pragma unroll
        for (int nt = 0; nt < 4; nt++) {
            o[nt][0] *= alA; o[nt][1] *= alA;
            o[nt][2] *= alB; o[nt][3] *= alB;
        }
        __syncthreads();

        // ---- O += P @ V  (3xTF32) ----
        #pragma unroll
        for (int k8 = 0; k8 < 8; k8++) {
            int kb = k8 * 8;
            unsigned ah[4], al[4];
            split_tf32(P[r0 * PW + kb + qc],     ah[0], al[0]);
            split_tf32(P[r1 * PW + kb + qc],     ah[1], al[1]);
            split_tf32(P[r0 * PW + kb + 4 + qc], ah[2], al[2]);
            split_tf32(P[r1 * PW + kb + 4 + qc], ah[3], al[3]);
            #pragma unroll
            for (int nt = 0; nt < 4; nt++) {
                int dn = wn * 32 + nt * 8 + qr;
                unsigned bh0, bl0, bh1, bl1;
                split_tf32(VT[dn * PW + kb + qc],     bh0, bl0);
                split_tf32(VT[dn * PW + kb + 4 + qc], bh1, bl1);
                mma3(o[nt], ah, al, bh0, bh1, bl0, bl1);
            }
        }
    }

    if (qc == 0) { rsump[wn][r0] = l0; rsump[wn][r1] = l1; }
    int idxbase = (bh * NSPLIT + sp) * 64;
    if (wn == 0 && qc == 0) {
        g_mx[idxbase + r0] = m0;
        g_mx[idxbase + r1] = m1;
    }
    __syncthreads();
    if (tid < 64) g_sm[idxbase + tid] = rsump[0][tid] + rsump[1][tid];
    #pragma unroll
    for (int nt = 0; nt < 4; nt++) {
        int c0 = wn * 32 + nt * 8 + 2 * qc;
        *(float2*)&g_Yp[((size_t)idxbase + r0) * 64 + c0] = make_float2(o[nt][0], o[nt][1]);
        *(float2*)&g_Yp[((size_t)idxbase + r1) * 64 + c0] = make_float2(o[nt][2], o[nt][3]);
    }
}

// ---------------- combine split partials into Y, then Zt = (Vinv @ Y)^T -------
__global__ __launch_bounds__(256) void combine_z_kernel() {
    __shared__ float smx[64], ssum[64];
    __shared__ float Ys[4096];
    __shared__ float Vv[4096];
    int bh = blockIdx.x, tid = threadIdx.x;

    for (int i = tid; i < 4096; i += 256) Vv[i] = g_Vinv[(size_t)bh * 4096 + i];

    if (tid < 64) {
        float mx = NEG_INF;
        for (int s = 0; s < NSPLIT; s++)
            mx = fmaxf(mx, g_mx[(bh * NSPLIT + s) * 64 + tid]);
        float mc = fmaxf(mx, -1e30f);
        float tot = 0.f;
        for (int s = 0; s < NSPLIT; s++)
            tot += __expf(g_mx[(bh * NSPLIT + s) * 64 + tid] - mc) *
                   g_sm[(bh * NSPLIT + s) * 64 + tid];
        smx[tid] = mc; ssum[tid] = tot;
    }
    __syncthreads();
    int m = tid >> 2, db = (tid & 3) * 16;
    float inv = 1.f / ssum[m];
    float acc[16];
    #pragma unroll
    for (int d = 0; d < 16; d++) acc[d] = 0.f;
    for (int s = 0; s < NSPLIT; s++) {
        float w = __expf(g_mx[(bh * NSPLIT + s) * 64 + m] - smx[m]);
        const float* yp = g_Yp + (((size_t)(bh * NSPLIT + s) * 64) + m) * 64 + db;
        #pragma unroll
        for (int d = 0; d < 16; d++) acc[d] += w * yp[d];
    }
    #pragma unroll
    for (int d = 0; d < 16; d++) Ys[m * 64 + db + d] = acc[d] * inv;
    __syncthreads();

    int tx = tid & 15, ty = tid >> 4;
    float a2[4][4];
    mm64v(Vv, Ys, a2, tx, ty);
    #pragma unroll
    for (int i = 0; i < 4; i++)
        #pragma unroll
        for (int j = 0; j < 4; j++)
            g_Zt[(size_t)bh * 4096 + (tx * 4 + j) * 64 + ty * 4 + i] = a2[i][j];
}

// ---------------- fused (tf32 mma): X = softmax(Qs @ nc^T) @ Z ----------------
extern __shared__ float xsmem[];
__global__ __launch_bounds__(256) void fx_kernel(const float* __restrict__ Q,
                                                 const float* __restrict__ K,
                                                 float* __restrict__ out) {
    float* ncs = xsmem;                // [m'][d] 64*PW
    float* qs  = ncs + 64 * PW;        // [n][d]  64*PW
    float* Zs  = qs + 64 * PW;         // [d][m'] 64*PW (Z transposed)
    float* P   = Zs + 64 * PW;         // [n][m'] 64*PW
    __shared__ float rmaxp[2][64];
    __shared__ float rsump[2][64];
    __shared__ int ci_s[64];

    int bh = blockIdx.y; int n0 = blockIdx.x * 64;
    const float* Kb = K + (size_t)bh * Nv * Dv;
    const float* Qb = Q + (size_t)bh * Nv * Dv;
    int tid = threadIdx.x;
    int wid = tid >> 5, lane = tid & 31;
    int wm = wid & 3, wn = wid >> 2;
    int qr = lane >> 2, qc = lane & 3;
    int r0 = wm * 16 + qr, r1 = r0 + 8;

    if (tid < 64) ci_s[tid] = g_cidx[bh * Mv + tid];
    __syncthreads();

    for (int idx = tid; idx < 64 * 16; idx += 256) {
        int r = idx >> 4, c4 = (idx & 15) * 4;
        float4 q4 = *(const float4*)(Qb + (size_t)(n0 + r) * Dv + c4);
        q4.x *= 0.125f; q4.y *= 0.125f; q4.z *= 0.125f; q4.w *= 0.125f;
        *(float4*)&qs[r * PW + c4] = q4;
        *(float4*)&ncs[r * PW + c4] = *(const float4*)(Kb + (size_t)ci_s[r] * Dv + c4);
        *(float4*)&Zs[r * PW + c4] = *(const float4*)(g_Zt + (size_t)bh * 4096 + r * 64 + c4);
    }
    __syncthreads();

    float s[4][4];
    #pragma unroll
    for (int nt = 0; nt < 4; nt++)
        #pragma unroll
        for (int j = 0; j < 4; j++) s[nt][j] = 0.f;
    #pragma unroll
    for (int k8 = 0; k8 < 8; k8++) {
        int kb = k8 * 8;
        unsigned ah[4], al[4];
        split_tf32(qs[r0 * PW + kb + qc],     ah[0], al[0]);
        split_tf32(qs[r1 * PW + kb + qc],     ah[1], al[1]);
        split_tf32(qs[r0 * PW + kb + 4 + qc], ah[2], al[2]);
        split_tf32(qs[r1 * PW + kb + 4 + qc], ah[3], al[3]);
        #pragma unroll
        for (int nt = 0; nt < 4; nt++) {
            int bn = wn * 32 + nt * 8 + qr;
            unsigned bh0, bl0, bh1, bl1;
            split_tf32(ncs[bn * PW + kb + qc],     bh0, bl0);
            split_tf32(ncs[bn * PW + kb + 4 + qc], bh1, bl1);
            mma3(s[nt], ah, al, bh0, bh1, bl0, bl1);
        }
    }

    float rmA = NEG_INF, rmB = NEG_INF;
    #pragma unroll
    for (int nt = 0; nt < 4; nt++) {
        rmA = fmaxf(rmA, fmaxf(s[nt][0], s[nt][1]));
        rmB = fmaxf(rmB, fmaxf(s[nt][2], s[nt][3]));
    }
    #pragma unroll
    for (int o2 = 1; o2 <= 2; o2 <<= 1) {
        rmA = fmaxf(rmA, __shfl_xor_sync(0xffffffffu, rmA, o2));
        rmB = fmaxf(rmB, __shfl_xor_sync(0xffffffffu, rmB, o2));
    }
    if (qc == 0) { rmaxp[wn][r0] = rmA; rmaxp[wn][r1] = rmB; }
    __syncthreads();

    float mcA = fmaxf(rmaxp[0][r0], rmaxp[1][r0]);
    float mcB = fmaxf(rmaxp[0][r1], rmaxp[1][r1]);
    float tsA = 0.f, tsB = 0.f;
    #pragma unroll
    for (int nt = 0; nt < 4; nt++) {
        int c0 = wn * 32 + nt * 8 + 2 * qc;
        float p00 = __expf(s[nt][0] - mcA), p01 = __expf(s[nt][1] - mcA);
        float p10 = __expf(s[nt][2] - mcB), p11 = __expf(s[nt][3] - mcB);
        tsA += p00 + p01; tsB += p10 + p11;
        *(float2*)&P[r0 * PW + c0] = make_float2(p00, p01);
        *(float2*)&P[r1 * PW + c0] = make_float2(p10, p11);
    }
    #pragma unroll
    for (int o2 = 1; o2 <= 2; o2 <<= 1) {
        tsA += __shfl_xor_sync(0xffffffffu, tsA, o2);
        tsB += __shfl_xor_sync(0xffffffffu, tsB, o2);
    }
    if (qc == 0) { rsump[wn][r0] = tsA; rsump[wn][r1] = tsB; }
    __syncthreads();

    float o[4][4];
    #pragma unroll
    for (int nt = 0; nt < 4; nt++)
        #pragma unroll
        for (int j = 0; j < 4; j++) o[nt][j] = 0.f;
    #pragma unroll
    for (int k8 = 0; k8 < 8; k8++) {
        int kb = k8 * 8;
        unsigned ah[4], al[4];
        split_tf32(P[r0 * PW + kb + qc],     ah[0], al[0]);
        split_tf32(P[r1 * PW + kb + qc],     ah[1], al[1]);
        split_tf32(P[r0 * PW + kb + 4 + qc], ah[2], al[2]);
        split_tf32(P[r1 * PW + kb + 4 + qc], ah[3], al[3]);
        #pragma unroll
        for (int nt = 0; nt < 4; nt++) {
            int dn = wn * 32 + nt * 8 + qr;
            unsigned bh0, bl0, bh1, bl1;
            split_tf32(Zs[dn * PW + kb + qc],     bh0, bl0);
            split_tf32(Zs[dn * PW + kb + 4 + qc], bh1, bl1);
            mma3(o[nt], ah, al, bh0, bh1, bl0, bl1);
        }
    }
    float invA = 1.f / (rsump[0][r0] + rsump[1][r0]);
    float invB = 1.f / (rsump[0][r1] + rsump[1][r1]);
    #pragma unroll
    for (int nt = 0; nt < 4; nt++) {
        int c0 = wn * 32 + nt * 8 + 2 * qc;
        *(float2*)(out + ((size_t)bh * Nv + n0 + r0) * Dv + c0) =
            make_float2(o[nt][0] * invA, o[nt][1] * invA);
        *(float2*)(out + ((size_t)bh * Nv + n0 + r1) * Dv + c0) =
            make_float2(o[nt][2] * invB, o[nt][3] * invB);
    }
}

// ---------------- launch ----------------
extern "C" void kernel_launch(void* const* d_in, const int* in_sizes, int n_in,
                              void* d_out, int out_size) {
    (void)in_sizes; (void)n_in; (void)out_size;
    const float* Q    = (const float*)d_in[0];
    const float* K    = (const float*)d_in[1];
    const float* V    = (const float*)d_in[2];
    const int*   mask = (const int*)d_in[3];
    float* out = (float*)d_out;

    const int FLASH_SMEM = 4 * 64 * PW * (int)sizeof(float);   // 69632
    const int FX_SMEM    = 4 * 64 * PW * (int)sizeof(float);   // 69632
    const int INV_SMEM   = 7 * 64 * PW * (int)sizeof(float);   // 121856
    cudaFuncSetAttribute(flash_kernel, cudaFuncAttributeMaxDynamicSharedMemorySize, FLASH_SMEM);
    cudaFuncSetAttribute(fx_kernel, cudaFuncAttributeMaxDynamicSharedMemorySize, FX_SMEM);
    cudaFuncSetAttribute(inv_kernel, cudaFuncAttributeMaxDynamicSharedMemorySize, INV_SMEM);

    cudaStream_t s2;
    cudaEvent_t evU, evB;
    cudaStreamCreateWithFlags(&s2, cudaStreamNonBlocking);
    cudaEventCreateWithFlags(&evU, cudaEventDisableTiming);
    cudaEventCreateWithFlags(&evB, cudaEventDisableTiming);

    init_kernel<<<1, 1>>>();                              // launch 1
    select_kernel<<<dim3(BH, 2), 256>>>(K, Q, mask);      // launch 2
    u_kernel<<<BH, 256>>>(Q, K);                          // launch 3
    cudaEventRecord(evU, 0);

    flash_kernel<<<dim3(NSPLIT, BH), 256, FLASH_SMEM>>>(Q, K, V, mask);  // launch 4 (profiled)

    cudaStreamWaitEvent(s2, evU, 0);
    inv_kernel<<<BH, 256, INV_SMEM, s2>>>();              // launch 5 (side, overlaps flash)
    cudaEventRecord(evB, s2);

    cudaStreamWaitEvent(0, evB, 0);
    combine_z_kernel<<<BH, 256>>>();                      // launch 6
    fx_kernel<<<dim3(Nv / 64, BH), 256, FX_SMEM>>>(Q, K, out);  // launch 7
}

// round 8
// speedup vs baseline: 2.8515x; 1.6571x over previous
#include <cuda_runtime.h>
#include <float.h>

#define Bv 4
#define Hv 8
#define BH 32
#define Nv 4096
#define Dv 64
#define Mv 64
#define NSPLIT 32
#define CHUNK 128
#define PW 68              // pitch (words): bank = (4*row + col) mod 32 -> conflict-free frags

#define NEG_INF __int_as_float(0xff800000)

typedef unsigned long long u64;

// ---- packed f32x2 helpers (used by u_kernel) ----
__device__ __forceinline__ u64 ffma2(u64 a, u64 b, u64 c) {
    u64 d;
    asm("fma.rn.f32x2 %0, %1, %2, %3;" : "=l"(d) : "l"(a), "l"(b), "l"(c));
    return d;
}
__device__ __forceinline__ float pairsum(u64 v) {
    unsigned lo, hi;
    asm("mov.b64 {%0, %1}, %2;" : "=r"(lo), "=r"(hi) : "l"(v));
    return __uint_as_float(lo) + __uint_as_float(hi);
}

// ---- tf32 mma helpers ----
__device__ __forceinline__ unsigned cvt_tf32(float x) {
    unsigned u;
    asm("cvt.rna.tf32.f32 %0, %1;" : "=r"(u) : "f"(x));
    return u;
}
__device__ __forceinline__ void split_tf32(float x, unsigned& hi, unsigned& lo) {
    hi = cvt_tf32(x);
    lo = cvt_tf32(x - __uint_as_float(hi));
}
__device__ __forceinline__ void mma8(float c[4], const unsigned a[4], unsigned b0, unsigned b1) {
    asm("mma.sync.aligned.m16n8k8.row.col.f32.tf32.tf32.f32 "
        "{%0,%1,%2,%3},{%4,%5,%6,%7},{%8,%9},{%0,%1,%2,%3};"
        : "+f"(c[0]), "+f"(c[1]), "+f"(c[2]), "+f"(c[3])
        : "r"(a[0]), "r"(a[1]), "r"(a[2]), "r"(a[3]), "r"(b0), "r"(b1));
}
__device__ __forceinline__ void mma3(float c[4], const unsigned ah[4], const unsigned al[4],
                                     unsigned bh0, unsigned bh1, unsigned bl0, unsigned bl1) {
    mma8(c, ah, bh0, bh1);
    mma8(c, ah, bl0, bl1);
    mma8(c, al, bh0, bh1);
}

// split-and-store to hi/lo planes (bit-cast stored as float)
__device__ __forceinline__ void split_store4(float4 v, float* hi_p, float* lo_p) {
    unsigned h0, l0, h1, l1, h2, l2, h3, l3;
    split_tf32(v.x, h0, l0); split_tf32(v.y, h1, l1);
    split_tf32(v.z, h2, l2); split_tf32(v.w, h3, l3);
    *(float4*)hi_p = make_float4(__uint_as_float(h0), __uint_as_float(h1),
                                 __uint_as_float(h2), __uint_as_float(h3));
    *(float4*)lo_p = make_float4(__uint_as_float(l0), __uint_as_float(l1),
                                 __uint_as_float(l2), __uint_as_float(l3));
}

// 64x64x64 GEMM, A float plane (split inline 2x), B pre-split hi/lo planes
__device__ __forceinline__ void gemm3b(const float* __restrict__ Arow,
                                       const float* __restrict__ Bhi,
                                       const float* __restrict__ Blo,
                                       float c[4][4], int wn, int r0, int r1, int qr, int qc) {
    #pragma unroll
    for (int k8 = 0; k8 < 8; k8++) {
        int kb = k8 * 8;
        unsigned ah[4], al[4];
        split_tf32(Arow[r0 * PW + kb + qc],     ah[0], al[0]);
        split_tf32(Arow[r1 * PW + kb + qc],     ah[1], al[1]);
        split_tf32(Arow[r0 * PW + kb + 4 + qc], ah[2], al[2]);
        split_tf32(Arow[r1 * PW + kb + 4 + qc], ah[3], al[3]);
        #pragma unroll
        for (int nt = 0; nt < 4; nt++) {
            int bn = wn * 32 + nt * 8 + qr;
            unsigned bh0 = __float_as_uint(Bhi[bn * PW + kb + qc]);
            unsigned bl0 = __float_as_uint(Blo[bn * PW + kb + qc]);
            unsigned bh1 = __float_as_uint(Bhi[bn * PW + kb + 4 + qc]);
            unsigned bl1 = __float_as_uint(Blo[bn * PW + kb + 4 + qc]);
            mma3(c[nt], ah, al, bh0, bh1, bl0, bl1);
        }
    }
}

// ---------------- scratch ----------------
__device__ float g_rs[2 * BH * Nv];
__device__ int   g_cidx[BH * Mv];
__device__ int   g_ridx[BH * Mv];
__device__ float g_u[BH * Mv * Mv];
__device__ float g_Vinv[BH * Mv * Mv];
__device__ float g_Yp[(size_t)BH * NSPLIT * Mv * Dv];
__device__ float g_mx[BH * NSPLIT * Mv];
__device__ float g_sm[BH * NSPLIT * Mv];
__device__ float g_Y[BH * Mv * Dv];
__device__ float g_Zt[BH * Mv * Dv];
__device__ unsigned int g_gmax;

// ---------------- row sums (wide) + gmax reset ----------------
__global__ __launch_bounds__(256) void rowsum_kernel(const float* __restrict__ Kp,
                                                     const float* __restrict__ Qp,
                                                     const int* __restrict__ mask) {
    int bh = blockIdx.x, y = blockIdx.y;
    int b = bh / Hv;
    const float* T = (y == 0) ? Kp : Qp;
    const float* Tb = T + (size_t)bh * Nv * Dv;
    float* outs = g_rs + (y * BH + bh) * Nv;
    int base = blockIdx.z * 1024;

    if (bh == 0 && y == 0 && blockIdx.z == 0 && threadIdx.x == 0) g_gmax = 0u;

    int hw = threadIdx.x >> 4, l16 = threadIdx.x & 15;
    for (int i = hw; i < 1024; i += 16) {
        int r = base + i;
        float4 v4 = *(const float4*)(Tb + (size_t)r * Dv + l16 * 4);
        float v = (v4.x + v4.y) + (v4.z + v4.w);
        #pragma unroll
        for (int o = 1; o <= 8; o <<= 1) v += __shfl_xor_sync(0xffffffffu, v, o);
        if (l16 == 0) {
            bool bad = (r == 0) || (mask[b * Nv + r] != 0);
            outs[r] = bad ? -FLT_MAX : v;
        }
    }
}

// ---------------- top-k pick (incremental chunk-argmax) ----------------
__global__ __launch_bounds__(256) void pick_kernel() {
    int bh = blockIdx.x;
    int* outIdx = (blockIdx.y == 0) ? g_cidx : g_ridx;
    const float* ins = g_rs + (blockIdx.y * BH + bh) * Nv;

    __shared__ float s[Nv];
    __shared__ float cmax[16];
    __shared__ int   cidx[16];
    __shared__ int   picked[Mv];

    int tid = threadIdx.x;
    int warp = tid >> 5, lane = tid & 31;

    for (int i = tid; i < Nv / 4; i += 256)
        *(float4*)&s[i * 4] = *(const float4*)(ins + i * 4);
    __syncthreads();

    for (int c = warp; c < 16; c += 8) {
        float bv = -FLT_MAX; int bi = Nv;
        #pragma unroll
        for (int t = 0; t < 8; t++) {
            int idx = c * 256 + lane + 32 * t;
            float v = s[idx];
            if (v > bv || (v == bv && idx < bi)) { bv = v; bi = idx; }
        }
        #pragma unroll
        for (int o = 16; o; o >>= 1) {
            float ov = __shfl_xor_sync(0xffffffffu, bv, o);
            int   oi = __shfl_xor_sync(0xffffffffu, bi, o);
            if (ov > bv || (ov == bv && oi < bi)) { bv = ov; bi = oi; }
        }
        if (lane == 0) { cmax[c] = bv; cidx[c] = bi; }
    }
    __syncthreads();

    if (warp == 0) {
        for (int it = 0; it < Mv - 1; ++it) {
            float bv = (lane < 16) ? cmax[lane] : -FLT_MAX;
            int   bi = (lane < 16) ? cidx[lane] : Nv;
            #pragma unroll
            for (int o = 16; o; o >>= 1) {
                float ov = __shfl_xor_sync(0xffffffffu, bv, o);
                int   oi = __shfl_xor_sync(0xffffffffu, bi, o);
                if (ov > bv || (ov == bv && oi < bi)) { bv = ov; bi = oi; }
            }
            int gidx = __shfl_sync(0xffffffffu, bi, 0);
            if (lane == 0) { picked[it] = gidx; s[gidx] = -FLT_MAX; }
            __syncwarp();
            int c = gidx >> 8;
            float nv = -FLT_MAX; int ni = Nv;
            #pragma unroll
            for (int t = 0; t < 8; t++) {
                int idx = c * 256 + lane + 32 * t;
                float v = s[idx];
                if (v > nv || (v == nv && idx < ni)) { nv = v; ni = idx; }
            }
            #pragma unroll
            for (int o = 16; o; o >>= 1) {
                float ov = __shfl_xor_sync(0xffffffffu, nv, o);
                int   oi = __shfl_xor_sync(0xffffffffu, ni, o);
                if (ov > nv || (ov == nv && oi < ni)) { nv = ov; ni = oi; }
            }
            if (lane == 0) { cmax[c] = nv; cidx[c] = ni; }
            __syncwarp();
        }
        if (lane == 0) picked[Mv - 1] = 0;
    }
    __syncthreads();

    if (tid < Mv) {
        int key = picked[tid];
        int rank = 0;
        #pragma unroll 16
        for (int j = 0; j < Mv; j++) rank += (picked[j] < key);
        outIdx[bh * Mv + rank] = key;
    }
}

// ---------------- u = softmax(Qs[ridx] @ nc^T) + global colsum-max ----------
__global__ __launch_bounds__(256) void u_kernel(const float* __restrict__ Q,
                                                const float* __restrict__ K) {
    int bh = blockIdx.x;
    __shared__ float Kc[64 * PW];
    __shared__ float Qr[64 * PW];
    __shared__ float colsum[64];
    __shared__ int ci_s[64], ri_s[64];

    const float* Kb = K + (size_t)bh * Nv * Dv;
    const float* Qb = Q + (size_t)bh * Nv * Dv;
    int tid = threadIdx.x;
    if (tid < 64) { ci_s[tid] = g_cidx[bh * Mv + tid]; ri_s[tid] = g_ridx[bh * Mv + tid]; }
    __syncthreads();

    for (int idx = tid; idx < 64 * 16; idx += 256) {
        int r = idx >> 4, c4 = (idx & 15) * 4;
        float4 q4 = *(const float4*)(Qb + (size_t)ri_s[r] * Dv + c4);
        q4.x *= 0.125f; q4.y *= 0.125f; q4.z *= 0.125f; q4.w *= 0.125f;
        *(float4*)&Qr[r * PW + c4] = q4;
        *(float4*)&Kc[r * PW + c4] = *(const float4*)(Kb + (size_t)ci_s[r] * Dv + c4);
    }
    __syncthreads();

    int tx = tid & 15, ty = tid >> 4;
    u64 sc2[4][4];
    #pragma unroll
    for (int i = 0; i < 4; i++)
        #pragma unroll
        for (int j = 0; j < 4; j++) sc2[i][j] = 0ull;
    #pragma unroll 4
    for (int k4 = 0; k4 < 16; k4++) {
        ulonglong2 a2[4], b2[4];
        #pragma unroll
        for (int i = 0; i < 4; i++) a2[i] = *(const ulonglong2*)&Qr[(ty * 4 + i) * PW + k4 * 4];
        #pragma unroll
        for (int j = 0; j < 4; j++) b2[j] = *(const ulonglong2*)&Kc[(tx + 16 * j) * PW + k4 * 4];
        #pragma unroll
        for (int i = 0; i < 4; i++)
            #pragma unroll
            for (int j = 0; j < 4; j++) {
                sc2[i][j] = ffma2(a2[i].x, b2[j].x, sc2[i][j]);
                sc2[i][j] = ffma2(a2[i].y, b2[j].y, sc2[i][j]);
            }
    }
    __syncthreads();

    #pragma unroll
    for (int i = 0; i < 4; i++) {
        float sv[4];
        #pragma unroll
        for (int j = 0; j < 4; j++) sv[j] = pairsum(sc2[i][j]);
        float mx = fmaxf(fmaxf(sv[0], sv[1]), fmaxf(sv[2], sv[3]));
        #pragma unroll
        for (int o = 8; o; o >>= 1) mx = fmaxf(mx, __shfl_xor_sync(0xffffffffu, mx, o));
        float e[4], sm = 0.f;
        #pragma unroll
        for (int j = 0; j < 4; j++) { e[j] = __expf(sv[j] - mx); sm += e[j]; }
        #pragma unroll
        for (int o = 8; o; o >>= 1) sm += __shfl_xor_sync(0xffffffffu, sm, o);
        float inv = 1.f / sm;
        int row = ty * 4 + i;
        #pragma unroll
        for (int j = 0; j < 4; j++) {
            float p = e[j] * inv;
            Qr[row * PW + tx + 16 * j] = p;
            g_u[(bh * 64 + row) * 64 + tx + 16 * j] = p;
        }
    }
    __syncthreads();
    if (tid < 64) {
        float s = 0.f;
        #pragma unroll 8
        for (int i = 0; i < 64; i++) s += Qr[i * PW + tid];
        colsum[tid] = s;
    }
    __syncthreads();
    if (tid == 0) {
        float mx = colsum[0];
        for (int j = 1; j < 64; j++) mx = fmaxf(mx, colsum[j]);
        atomicMax(&g_gmax, __float_as_uint(mx));
    }
}

// ---------------- vectorized NN 64x64 matmul, pitch 64 ----------------
__device__ __forceinline__ void mm64v(const float* __restrict__ A,
                                      const float* __restrict__ Bm,
                                      float acc[4][4], int tx, int ty) {
    #pragma unroll
    for (int i = 0; i < 4; i++)
        #pragma unroll
        for (int j = 0; j < 4; j++) acc[i][j] = 0.f;
    #pragma unroll 2
    for (int k4 = 0; k4 < 16; k4++) {
        float4 a[4];
        #pragma unroll
        for (int i = 0; i < 4; i++) a[i] = *(const float4*)&A[(ty * 4 + i) * 64 + k4 * 4];
        #pragma unroll
        for (int kk = 0; kk < 4; kk++) {
            float4 bv = *(const float4*)&Bm[(k4 * 4 + kk) * 64 + tx * 4];
            float av[4];
            av[0] = (kk == 0) ? a[0].x : (kk == 1) ? a[0].y : (kk == 2) ? a[0].z : a[0].w;
            av[1] = (kk == 0) ? a[1].x : (kk == 1) ? a[1].y : (kk == 2) ? a[1].z : a[1].w;
            av[2] = (kk == 0) ? a[2].x : (kk == 1) ? a[2].y : (kk == 2) ? a[2].z : a[2].w;
            av[3] = (kk == 0) ? a[3].x : (kk == 1) ? a[3].y : (kk == 2) ? a[3].z : a[3].w;
            #pragma unroll
            for (int i = 0; i < 4; i++) {
                acc[i][0] = fmaf(av[i], bv.x, acc[i][0]);
                acc[i][1] = fmaf(av[i], bv.y, acc[i][1]);
                acc[i][2] = fmaf(av[i], bv.z, acc[i][2]);
                acc[i][3] = fmaf(av[i], bv.w, acc[i][3]);
            }
        }
    }
}

// ---------------- Newton-Schulz inverse (3xTF32 mma) -> g_Vinv ----------------
__device__ __forceinline__ void gemm3(const float* __restrict__ Arow, const float* __restrict__ Bt,
                                      float c[4][4], int wn, int r0, int r1, int qr, int qc) {
    #pragma unroll
    for (int nt = 0; nt < 4; nt++) { c[nt][0] = c[nt][1] = c[nt][2] = c[nt][3] = 0.f; }
    #pragma unroll
    for (int k8 = 0; k8 < 8; k8++) {
        int kb = k8 * 8;
        unsigned ah[4], al[4];
        split_tf32(Arow[r0 * PW + kb + qc],     ah[0], al[0]);
        split_tf32(Arow[r1 * PW + kb + qc],     ah[1], al[1]);
        split_tf32(Arow[r0 * PW + kb + 4 + qc], ah[2], al[2]);
        split_tf32(Arow[r1 * PW + kb + 4 + qc], ah[3], al[3]);
        #pragma unroll
        for (int nt = 0; nt < 4; nt++) {
            int bn = wn * 32 + nt * 8 + qr;
            unsigned bh0, bl0, bh1, bl1;
            split_tf32(Bt[bn * PW + kb + qc],     bh0, bl0);
            split_tf32(Bt[bn * PW + kb + 4 + qc], bh1, bl1);
            mma3(c[nt], ah, al, bh0, bh1, bl0, bl1);
        }
    }
}

extern __shared__ float invsm[];
__global__ __launch_bounds__(256) void inv_kernel() {
    float* Us  = invsm;
    float* Vr  = Us  + 64 * PW;
    float* Vt  = Vr  + 64 * PW;
    float* Ar  = Vt  + 64 * PW;
    float* At  = Ar  + 64 * PW;
    float* Tt  = At  + 64 * PW;
    float* T2t = Tt  + 64 * PW;

    int bh = blockIdx.x, tid = threadIdx.x;
    int wid = tid >> 5, lane = tid & 31;
    int wm = wid & 3, wn = wid >> 2;
    int qr = lane >> 2, qc = lane & 3;
    int r0 = wm * 16 + qr, r1 = r0 + 8;

    const float* Ug = g_u + (size_t)bh * 4096;
    float ginv = 1.f / __uint_as_float(g_gmax);

    for (int idx = tid; idx < 1024; idx += 256) {
        int r = idx >> 4, c4 = (idx & 15) * 4;
        float4 u4 = *(const float4*)(Ug + r * 64 + c4);
        *(float4*)&Us[r * PW + c4] = u4;
        float4 s4 = make_float4(u4.x * ginv, u4.y * ginv, u4.z * ginv, u4.w * ginv);
        *(float4*)&Vt[r * PW + c4] = s4;
        Vr[(c4 + 0) * PW + r] = s4.x;
        Vr[(c4 + 1) * PW + r] = s4.y;
        Vr[(c4 + 2) * PW + r] = s4.z;
        Vr[(c4 + 3) * PW + r] = s4.w;
    }
    __syncthreads();

    float c1[4][4], cw[4][4];
    for (int it = 0; it < 6; it++) {
        gemm3(Us, Vt, c1, wn, r0, r1, qr, qc);
        #pragma unroll
        for (int nt = 0; nt < 4; nt++) {
            int c0 = wn * 32 + nt * 8 + 2 * qc;
            Ar[r0 * PW + c0] = c1[nt][0]; Ar[r0 * PW + c0 + 1] = c1[nt][1];
            Ar[r1 * PW + c0] = c1[nt][2]; Ar[r1 * PW + c0 + 1] = c1[nt][3];
            At[c0 * PW + r0] = c1[nt][0]; At[(c0 + 1) * PW + r0] = c1[nt][1];
            At[c0 * PW + r1] = c1[nt][2]; At[(c0 + 1) * PW + r1] = c1[nt][3];
        }
        __syncthreads();

        gemm3(Ar, At, cw, wn, r0, r1, qr, qc);
        #pragma unroll
        for (int nt = 0; nt < 4; nt++) {
            int c0 = wn * 32 + nt * 8 + 2 * qc;
            Tt[c0 * PW + r0]       = 7.f * c1[nt][0] - cw[nt][0];
            Tt[(c0 + 1) * PW + r0] = 7.f * c1[nt][1] - cw[nt][1];
            Tt[c0 * PW + r1]       = 7.f * c1[nt][2] - cw[nt][2];
            Tt[(c0 + 1) * PW + r1] = 7.f * c1[nt][3] - cw[nt][3];
        }
        __syncthreads();

        gemm3(Ar, Tt, cw, wn, r0, r1, qr, qc);
        #pragma unroll
        for (int nt = 0; nt < 4; nt++) {
            int c0 = wn * 32 + nt * 8 + 2 * qc;
            T2t[c0 * PW + r0]       = 15.f * c1[nt][0] - cw[nt][0];
            T2t[(c0 + 1) * PW + r0] = 15.f * c1[nt][1] - cw[nt][1];
            T2t[c0 * PW + r1]       = 15.f * c1[nt][2] - cw[nt][2];
            T2t[(c0 + 1) * PW + r1] = 15.f * c1[nt][3] - cw[nt][3];
        }
        __syncthreads();

        gemm3(Vr, T2t, cw, wn, r0, r1, qr, qc);
        __syncthreads();
        #pragma unroll
        for (int nt = 0; nt < 4; nt++) {
            int c0 = wn * 32 + nt * 8 + 2 * qc;
            float v00 = Vr[r0 * PW + c0], v01 = Vr[r0 * PW + c0 + 1];
            float v10 = Vr[r1 * PW + c0], v11 = Vr[r1 * PW + c0 + 1];
            float n00 = 0.25f * (13.f * v00 - cw[nt][0]);
            float n01 = 0.25f * (13.f * v01 - cw[nt][1]);
            float n10 = 0.25f * (13.f * v10 - cw[nt][2]);
            float n11 = 0.25f * (13.f * v11 - cw[nt][3]);
            Vr[r0 * PW + c0] = n00; Vr[r0 * PW + c0 + 1] = n01;
            Vr[r1 * PW + c0] = n10; Vr[r1 * PW + c0 + 1] = n11;
            Vt[c0 * PW + r0] = n00; Vt[(c0 + 1) * PW + r0] = n01;
            Vt[c0 * PW + r1] = n10; Vt[(c0 + 1) * PW + r1] = n11;
        }
        __syncthreads();
    }

    for (int idx = tid; idx < 1024; idx += 256) {
        int r = idx >> 4, c4 = (idx & 15) * 4;
        *(float4*)(g_Vinv + (size_t)bh * 4096 + r * 64 + c4) = *(float4*)&Vr[r * PW + c4];
    }
}

// ---------------- flash: Y_partial = softmax_n(nr@K^T, mask) @ V ----------
extern __shared__ float fsmem[];
__global__ __launch_bounds__(256) void flash_kernel(const float* __restrict__ Q,
                                                    const float* __restrict__ K,
                                                    const float* __restrict__ V,
                                                    const int* __restrict__ mask) {
    float* nr  = fsmem;                 // [m][d] float
    float* P   = nr + 64 * PW;          // [m][n] float
    float* Bhi = P + 64 * PW;           // K then V^T, tf32-hi plane
    float* Blo = Bhi + 64 * PW;         // tf32-lo plane
    __shared__ float rmaxp[2][64];
    __shared__ float rsump[2][64];
    __shared__ int msk[64];
    __shared__ int ri_s[64];

    int bh = blockIdx.y, sp = blockIdx.x;
    int b = bh / Hv;
    const float* Qb = Q + (size_t)bh * Nv * Dv;
    const float* Kb = K + (size_t)bh * Nv * Dv;
    const float* Vb = V + (size_t)bh * Nv * Dv;

    int tid = threadIdx.x;
    int wid = tid >> 5, lane = tid & 31;
    int wm = wid & 3, wn = wid >> 2;
    int qr = lane >> 2, qc = lane & 3;
    int r0 = wm * 16 + qr, r1 = r0 + 8;

    if (tid < 64) ri_s[tid] = g_ridx[bh * Mv + tid];
    __syncthreads();
    for (int idx = tid; idx < 64 * 16; idx += 256) {
        int r = idx >> 4, c4 = (idx & 15) * 4;
        float4 q4 = *(const float4*)(Qb + (size_t)ri_s[r] * Dv + c4);
        q4.x *= 0.125f; q4.y *= 0.125f; q4.z *= 0.125f; q4.w *= 0.125f;
        *(float4*)&nr[r * PW + c4] = q4;
    }

    float o[4][4];
    #pragma unroll
    for (int nt = 0; nt < 4; nt++)
        #pragma unroll
        for (int j = 0; j < 4; j++) o[nt][j] = 0.f;
    float m0 = NEG_INF, m1 = NEG_INF, l0 = 0.f, l1 = 0.f;

    int base0 = sp * CHUNK;
    for (int t = 0; t < CHUNK / 64; t++) {
        int base = base0 + t * 64;
        __syncthreads();                               // B planes + P free; nr ready on t=0
        // K tile -> pre-split B planes
        for (int idx = tid; idx < 64 * 16; idx += 256) {
            int r = idx >> 4, c4 = (idx & 15) * 4;
            float4 k4 = *(const float4*)(Kb + (size_t)(base + r) * Dv + c4);
            split_store4(k4, &Bhi[r * PW + c4], &Blo[r * PW + c4]);
        }
        if (tid < 64) msk[tid] = mask[b * Nv + base + tid];
        __syncthreads();

        // ---- S = nr @ K^T ----
        float s[4][4];
        #pragma unroll
        for (int nt = 0; nt < 4; nt++)
            #pragma unroll
            for (int j = 0; j < 4; j++) s[nt][j] = 0.f;
        gemm3b(nr, Bhi, Blo, s, wn, r0, r1, qr, qc);

        // ---- mask + row max ----
        float rmA = NEG_INF, rmB = NEG_INF;
        #pragma unroll
        for (int nt = 0; nt < 4; nt++) {
            int c0 = wn * 32 + nt * 8 + 2 * qc, c1c = c0 + 1;
            if (!msk[c0])  { s[nt][0] = NEG_INF; s[nt][2] = NEG_INF; }
            if (!msk[c1c]) { s[nt][1] = NEG_INF; s[nt][3] = NEG_INF; }
            rmA = fmaxf(rmA, fmaxf(s[nt][0], s[nt][1]));
            rmB = fmaxf(rmB, fmaxf(s[nt][2], s[nt][3]));
        }
        #pragma unroll
        for (int o2 = 1; o2 <= 2; o2 <<= 1) {
            rmA = fmaxf(rmA, __shfl_xor_sync(0xffffffffu, rmA, o2));
            rmB = fmaxf(rmB, __shfl_xor_sync(0xffffffffu, rmB, o2));
        }
        if (qc == 0) { rmaxp[wn][r0] = rmA; rmaxp[wn][r1] = rmB; }
        __syncthreads();                               // all S reads of B planes done

        // ---- V tile -> B planes (transposed, pre-split) + online softmax ----
        for (int idx = tid; idx < 64 * 16; idx += 256) {
            int r = idx & 63, c4 = (idx >> 6) * 4;
            float4 v = *(const float4*)(Vb + (size_t)(base + r) * Dv + c4);
            unsigned h, l;
            split_tf32(v.x, h, l); Bhi[(c4 + 0) * PW + r] = __uint_as_float(h); Blo[(c4 + 0) * PW + r] = __uint_as_float(l);
            split_tf32(v.y, h, l); Bhi[(c4 + 1) * PW + r] = __uint_as_float(h); Blo[(c4 + 1) * PW + r] = __uint_as_float(l);
            split_tf32(v.z, h, l); Bhi[(c4 + 2) * PW + r] = __uint_as_float(h); Blo[(c4 + 2) * PW + r] = __uint_as_float(l);
            split_tf32(v.w, h, l); Bhi[(c4 + 3) * PW + r] = __uint_as_float(h); Blo[(c4 + 3) * PW + r] = __uint_as_float(l);
        }
        float tmxA = fmaxf(rmaxp[0][r0], rmaxp[1][r0]);
        float tmxB = fmaxf(rmaxp[0][r1], rmaxp[1][r1]);
        float nmA = fmaxf(m0, tmxA), mcA = fmaxf(nmA, -1e30f);
        float nmB = fmaxf(m1, tmxB), mcB = fmaxf(nmB, -1e30f);
        float alA = __expf(m0 - mcA), alB = __expf(m1 - mcB);
        m0 = nmA; m1 = nmB;
        float tsA = 0.f, tsB = 0.f;
        #pragma unroll
        for (int nt = 0; nt < 4; nt++) {
            int c0 = wn * 32 + nt * 8 + 2 * qc;
            float p00 = __expf(s[nt][0] - mcA), p01 = __expf(s[nt][1] - mcA);
            float p10 = __expf(s[nt][2] - mcB), p11 = __expf(s[nt][3] - mcB);
            tsA += p00 + p01; tsB += p10 + p11;
            *(float2*)&P[r0 * PW + c0] = make_float2(p00, p01);
            *(float2*)&P[r1 * PW + c0] = make_float2(p10, p11);
        }
        #pragma unroll
        for (int o2 = 1; o2 <= 2; o2 <<= 1) {
            tsA += __shfl_xor_sync(0xffffffffu, tsA, o2);
            tsB += __shfl_xor_sync(0xffffffffu, tsB, o2);
        }
        l0 = l0 * alA + tsA;
        l1 = l1 * alB + tsB;
        #pragma unroll
        for (int nt = 0; nt < 4; nt++) {
            o[nt][0] *= alA; o[nt][1] *= alA;
            o[nt][2] *= alB; o[nt][3] *= alB;
        }
        __syncthreads();                               // P + V planes ready

        // ---- O += P @ V ----
        gemm3b(P, Bhi, Blo, o, wn, r0, r1, qr, qc);
    }

    if (qc == 0) { rsump[wn][r0] = l0; rsump[wn][r1] = l1; }
    int idxbase = (bh * NSPLIT + sp) * 64;
    if (wn == 0 && qc == 0) {
        g_mx[idxbase + r0] = m0;
        g_mx[idxbase + r1] = m1;
    }
    __syncthreads();
    if (tid < 64) g_sm[idxbase + tid] = rsump[0][tid] + rsump[1][tid];
    #pragma unroll
    for (int nt = 0; nt < 4; nt++) {
        int c0 = wn * 32 + nt * 8 + 2 * qc;
        *(float2*)&g_Yp[((size_t)idxbase + r0) * 64 + c0] = make_float2(o[nt][0], o[nt][1]);
        *(float2*)&g_Yp[((size_t)idxbase + r1) * 64 + c0] = make_float2(o[nt][2], o[nt][3]);
    }
}

// ---------------- combine split partials into Y (wide) ----------------
__global__ __launch_bounds__(256) void combine_kernel() {
    int bh = blockIdx.x, tid = threadIdx.x;
    int m = blockIdx.y * 16 + (tid >> 4);
    int dq = (tid & 15) * 4;

    float mx = NEG_INF;
    #pragma unroll 8
    for (int s = 0; s < NSPLIT; s++)
        mx = fmaxf(mx, g_mx[(bh * NSPLIT + s) * 64 + m]);
    float mc = fmaxf(mx, -1e30f);
    float tot = 0.f;
    float4 acc = make_float4(0.f, 0.f, 0.f, 0.f);
    #pragma unroll 4
    for (int s = 0; s < NSPLIT; s++) {
        float w = __expf(g_mx[(bh * NSPLIT + s) * 64 + m] - mc);
        tot += w * g_sm[(bh * NSPLIT + s) * 64 + m];
        float4 yp = *(const float4*)(g_Yp + (((size_t)(bh * NSPLIT + s) * 64) + m) * 64 + dq);
        acc.x += w * yp.x; acc.y += w * yp.y; acc.z += w * yp.z; acc.w += w * yp.w;
    }
    float inv = 1.f / tot;
    *(float4*)(g_Y + ((size_t)bh * 64 + m) * 64 + dq) =
        make_float4(acc.x * inv, acc.y * inv, acc.z * inv, acc.w * inv);
}

// ---------------- Zt = (Vinv @ Y)^T ----------------
__global__ __launch_bounds__(256) void z_kernel() {
    __shared__ float Vv[4096];
    __shared__ float Ys[4096];
    int bh = blockIdx.x, tid = threadIdx.x;
    int tx = tid & 15, ty = tid >> 4;
    for (int i = tid; i < 4096; i += 256) {
        Vv[i] = g_Vinv[(size_t)bh * 4096 + i];
        Ys[i] = g_Y[(size_t)bh * 4096 + i];
    }
    __syncthreads();
    float acc[4][4];
    mm64v(Vv, Ys, acc, tx, ty);
    #pragma unroll
    for (int i = 0; i < 4; i++)
        #pragma unroll
        for (int j = 0; j < 4; j++)
            g_Zt[(size_t)bh * 4096 + (tx * 4 + j) * 64 + ty * 4 + i] = acc[i][j];
}

// ---------------- fused: X = softmax(Qs @ nc^T) @ Z ----------------
extern __shared__ float xsmem[];
__global__ __launch_bounds__(256) void fx_kernel(const float* __restrict__ Q,
                                                 const float* __restrict__ K,
                                                 float* __restrict__ out) {
    float* qs  = xsmem;                // [n][d] float
    float* P   = qs + 64 * PW;         // [n][m'] float
    float* Bhi = P + 64 * PW;          // nc then Z^T, tf32-hi
    float* Blo = Bhi + 64 * PW;        // tf32-lo
    __shared__ float rmaxp[2][64];
    __shared__ float rsump[2][64];
    __shared__ int ci_s[64];

    int bh = blockIdx.y; int n0 = blockIdx.x * 64;
    const float* Kb = K + (size_t)bh * Nv * Dv;
    const float* Qb = Q + (size_t)bh * Nv * Dv;
    int tid = threadIdx.x;
    int wid = tid >> 5, lane = tid & 31;
    int wm = wid & 3, wn = wid >> 2;
    int qr = lane >> 2, qc = lane & 3;
    int r0 = wm * 16 + qr, r1 = r0 + 8;

    if (tid < 64) ci_s[tid] = g_cidx[bh * Mv + tid];
    __syncthreads();

    for (int idx = tid; idx < 64 * 16; idx += 256) {
        int r = idx >> 4, c4 = (idx & 15) * 4;
        float4 q4 = *(const float4*)(Qb + (size_t)(n0 + r) * Dv + c4);
        q4.x *= 0.125f; q4.y *= 0.125f; q4.z *= 0.125f; q4.w *= 0.125f;
        *(float4*)&qs[r * PW + c4] = q4;
        float4 n4 = *(const float4*)(Kb + (size_t)ci_s[r] * Dv + c4);
        split_store4(n4, &Bhi[r * PW + c4], &Blo[r * PW + c4]);
    }
    __syncthreads();

    // ---- S = qs @ nc^T ----
    float s[4][4];
    #pragma unroll
    for (int nt = 0; nt < 4; nt++)
        #pragma unroll
        for (int j = 0; j < 4; j++) s[nt][j] = 0.f;
    gemm3b(qs, Bhi, Blo, s, wn, r0, r1, qr, qc);

    float rmA = NEG_INF, rmB = NEG_INF;
    #pragma unroll
    for (int nt = 0; nt < 4; nt++) {
        rmA = fmaxf(rmA, fmaxf(s[nt][0], s[nt][1]));
        rmB = fmaxf(rmB, fmaxf(s[nt][2], s[nt][3]));
    }
    #pragma unroll
    for (int o2 = 1; o2 <= 2; o2 <<= 1) {
        rmA = fmaxf(rmA, __shfl_xor_sync(0xffffffffu, rmA, o2));
        rmB = fmaxf(rmB, __shfl_xor_sync(0xffffffffu, rmB, o2));
    }
    if (qc == 0) { rmaxp[wn][r0] = rmA; rmaxp[wn][r1] = rmB; }
    __syncthreads();                                   // S reads done

    // ---- Z^T -> B planes (pre-split) + softmax/P ----
    for (int idx = tid; idx < 64 * 16; idx += 256) {
        int r = idx >> 4, c4 = (idx & 15) * 4;
        float4 z4 = *(const float4*)(g_Zt + (size_t)bh * 4096 + r * 64 + c4);
        split_store4(z4, &Bhi[r * PW + c4], &Blo[r * PW + c4]);
    }
    float mcA = fmaxf(rmaxp[0][r0], rmaxp[1][r0]);
    float mcB = fmaxf(rmaxp[0][r1], rmaxp[1][r1]);
    float tsA = 0.f, tsB = 0.f;
    #pragma unroll
    for (int nt = 0; nt < 4; nt++) {
        int c0 = wn * 32 + nt * 8 + 2 * qc;
        float p00 = __expf(s[nt][0] - mcA), p01 = __expf(s[nt][1] - mcA);
        float p10 = __expf(s[nt][2] - mcB), p11 = __expf(s[nt][3] - mcB);
        tsA += p00 + p01; tsB += p10 + p11;
        *(float2*)&P[r0 * PW + c0] = make_float2(p00, p01);
        *(float2*)&P[r1 * PW + c0] = make_float2(p10, p11);
    }
    #pragma unroll
    for (int o2 = 1; o2 <= 2; o2 <<= 1) {
        tsA += __shfl_xor_sync(0xffffffffu, tsA, o2);
        tsB += __shfl_xor_sync(0xffffffffu, tsB, o2);
    }
    if (qc == 0) { rsump[wn][r0] = tsA; rsump[wn][r1] = tsB; }
    __syncthreads();                                   // P + Z planes ready

    // ---- X = P @ Z ----
    float o[4][4];
    #pragma unroll
    for (int nt = 0; nt < 4; nt++)
        #pragma unroll
        for (int j = 0; j < 4; j++) o[nt][j] = 0.f;
    gemm3b(P, Bhi, Blo, o, wn, r0, r1, qr, qc);

    float invA = 1.f / (rsump[0][r0] + rsump[1][r0]);
    float invB = 1.f / (rsump[0][r1] + rsump[1][r1]);
    #pragma unroll
    for (int nt = 0; nt < 4; nt++) {
        int c0 = wn * 32 + nt * 8 + 2 * qc;
        *(float2*)(out + ((size_t)bh * Nv + n0 + r0) * Dv + c0) =
            make_float2(o[nt][0] * invA, o[nt][1] * invA);
        *(float2*)(out + ((size_t)bh * Nv + n0 + r1) * Dv + c0) =
            make_float2(o[nt][2] * invB, o[nt][3] * invB);
    }
}

// ---------------- launch ----------------
extern "C" void kernel_launch(void* const* d_in, const int* in_sizes, int n_in,
                              void* d_out, int out_size) {
    (void)in_sizes; (void)n_in; (void)out_size;
    const float* Q    = (const float*)d_in[0];
    const float* K    = (const float*)d_in[1];
    const float* V    = (const float*)d_in[2];
    const int*   mask = (const int*)d_in[3];
    float* out = (float*)d_out;

    const int FLASH_SMEM = 4 * 64 * PW * (int)sizeof(float);   // 69632
    const int FX_SMEM    = 4 * 64 * PW * (int)sizeof(float);   // 69632
    const int INV_SMEM   = 7 * 64 * PW * (int)sizeof(float);   // 121856
    cudaFuncSetAttribute(flash_kernel, cudaFuncAttributeMaxDynamicSharedMemorySize, FLASH_SMEM);
    cudaFuncSetAttribute(fx_kernel, cudaFuncAttributeMaxDynamicSharedMemorySize, FX_SMEM);
    cudaFuncSetAttribute(inv_kernel, cudaFuncAttributeMaxDynamicSharedMemorySize, INV_SMEM);

    cudaStream_t s2;
    cudaEvent_t evU, evB;
    cudaStreamCreateWithFlags(&s2, cudaStreamNonBlocking);
    cudaEventCreateWithFlags(&evU, cudaEventDisableTiming);
    cudaEventCreateWithFlags(&evB, cudaEventDisableTiming);

    rowsum_kernel<<<dim3(BH, 2, 4), 256>>>(K, Q, mask);   // launch 1 (wide, + gmax reset)
    pick_kernel<<<dim3(BH, 2), 256>>>();                  // launch 2
    u_kernel<<<BH, 256>>>(Q, K);                          // launch 3
    cudaEventRecord(evU, 0);

    flash_kernel<<<dim3(NSPLIT, BH), 256, FLASH_SMEM>>>(Q, K, V, mask);  // launch 4 (profiled)

    cudaStreamWaitEvent(s2, evU, 0);
    inv_kernel<<<BH, 256, INV_SMEM, s2>>>();              // side stream, overlaps flash
    cudaEventRecord(evB, s2);

    combine_kernel<<<dim3(BH, 4), 256>>>();               // main; overlaps inv tail
    cudaStreamWaitEvent(0, evB, 0);
    z_kernel<<<BH, 256>>>();
    fx_kernel<<<dim3(Nv / 64, BH), 256, FX_SMEM>>>(Q, K, out);
}